// round 10
// baseline (speedup 1.0000x reference)
#include <cuda_runtime.h>
#include <math.h>
#include <stdint.h>

// Problem dims (fixed by the dataset)
#define NB 32      // batch
#define NS 128     // src seq len
#define NT 19      // decoder steps (T-1)
#define ND 512     // embed dim
#define NH 1024    // hidden
#define NG 4096    // 4*H
#define NK 100     // attn key dim
#define NV 32000   // vocab
#define NBLK 128

typedef unsigned long long ull_t;

// ------------------------- scratch (device globals; no allocs) ---------------
__device__ float g_src_embed[NS*NB*ND];
__device__ float g_ans_embed[NT*NB*ND];
__device__ float g_xproj[NS*NG*NB];         // [s][n][b]
__device__ float g_dxe[NT*NG*NB];           // [t][n][b]
__device__ float g_h[NB*NH];
__device__ float g_c[NB*NH];
__device__ float g_hbuf[2*NB*NH];           // enc: tf32 bits; dec: fp32
__device__ float g_enc_out[NS*NB*NH];
__device__ float g_qkey[NS*NB*NK];
__device__ float g_qval[NS*NB*NH];
__device__ float g_tmp[NB*2048];
__device__ float g_ctx[NB*NH];
__device__ float g_attw[NB*NS];
__device__ float g_feat[NT*NB*ND];

// two-level grid barrier state (monotonic counters, no resets)
__device__ unsigned g_bgrp[8*32];           // 8 group counters, 128B apart
__device__ unsigned g_btop = 0;
__device__ unsigned g_bgen = 0;

__device__ __forceinline__ float sigmf_(float x) { return 1.0f/(1.0f+expf(-x)); }

// ---- packed f32x2 helpers (decoder FFMA2 path) ----
__device__ __forceinline__ void ffma2(ull_t& d, ull_t a, ull_t b)
{
    asm("fma.rn.f32x2 %0, %1, %2, %3;" : "=l"(d) : "l"(a), "l"(b), "l"(d));
}
__device__ __forceinline__ ull_t dup2(float x)
{
    ull_t r;
    asm("mov.b64 %0, {%1, %1};" : "=l"(r) : "f"(x));
    return r;
}
__device__ __forceinline__ float2 unpk(ull_t v)
{
    float2 r;
    asm("mov.b64 {%0, %1}, %2;" : "=f"(r.x), "=f"(r.y) : "l"(v));
    return r;
}

// ---- tf32 tensor-core helpers ----
__device__ __forceinline__ uint32_t f2tf(float x)
{
    uint32_t r;
    asm("cvt.rna.tf32.f32 %0, %1;" : "=r"(r) : "f"(x));
    return r;
}
__device__ __forceinline__ uint32_t cvta_s(const void* p)
{
    uint32_t a;
    asm("{ .reg .u64 t; cvta.to.shared.u64 t, %1; cvt.u32.u64 %0, t; }"
        : "=r"(a) : "l"(p));
    return a;
}
__device__ __forceinline__ void ldsm_x4(uint32_t& r0, uint32_t& r1,
                                        uint32_t& r2, uint32_t& r3, uint32_t addr)
{
    asm volatile("ldmatrix.sync.aligned.m8n8.x4.b16 {%0,%1,%2,%3}, [%4];"
                 : "=r"(r0), "=r"(r1), "=r"(r2), "=r"(r3) : "r"(addr));
}
__device__ __forceinline__ void mma_tf32(float* d, uint32_t a0, uint32_t a1,
                                         uint32_t a2, uint32_t a3,
                                         uint32_t b0, uint32_t b1)
{
    asm volatile(
        "mma.sync.aligned.m16n8k8.row.col.f32.tf32.tf32.f32 "
        "{%0,%1,%2,%3}, {%4,%5,%6,%7}, {%8,%9}, {%0,%1,%2,%3};"
        : "+f"(d[0]), "+f"(d[1]), "+f"(d[2]), "+f"(d[3])
        : "r"(a0), "r"(a1), "r"(a2), "r"(a3), "r"(b0), "r"(b1));
}

// two-level barrier: 16 arrivals/group x 8 groups, then 8 on top counter.
// Monotonic counters (wrap compare) -> no reset, no reset race.
__device__ __forceinline__ void gridbar()
{
    __syncthreads();
    if (threadIdx.x == 0) {
        __threadfence();
        unsigned grp = blockIdx.x >> 4;
        volatile unsigned* vgen = &g_bgen;
        unsigned gen = *vgen;
        if ((atomicAdd(&g_bgrp[grp*32], 1u) & 15u) == 15u) {
            if ((atomicAdd(&g_btop, 1u) & 7u) == 7u) {
                __threadfence();
                atomicAdd(&g_bgen, 1u);
            }
        }
        while (*vgen == gen) { __nanosleep(8); }
        __threadfence();
    }
    __syncthreads();
}

// helper: scatter 4 prefetched float4s (rows kk=4*(lq+8p)) into tile[k][row]
__device__ __forceinline__ void stash4(float* buf, int lq, int row,
                                       float4 p0, float4 p1, float4 p2, float4 p3)
{
    buf[(4*lq+0)*36+row]=p0.x; buf[(4*lq+1)*36+row]=p0.y;
    buf[(4*lq+2)*36+row]=p0.z; buf[(4*lq+3)*36+row]=p0.w;
    buf[(4*(lq+8)+0)*36+row]=p1.x; buf[(4*(lq+8)+1)*36+row]=p1.y;
    buf[(4*(lq+8)+2)*36+row]=p1.z; buf[(4*(lq+8)+3)*36+row]=p1.w;
    buf[(4*(lq+16)+0)*36+row]=p2.x; buf[(4*(lq+16)+1)*36+row]=p2.y;
    buf[(4*(lq+16)+2)*36+row]=p2.z; buf[(4*(lq+16)+3)*36+row]=p2.w;
    buf[(4*(lq+24)+0)*36+row]=p3.x; buf[(4*(lq+24)+1)*36+row]=p3.y;
    buf[(4*(lq+24)+2)*36+row]=p3.z; buf[(4*(lq+24)+3)*36+row]=p3.w;
}

// ------------------------- embedding gather ---------------------------------
__global__ void k_gather(const int* __restrict__ seq, int seq_stride,
                         const float* __restrict__ embed, float* __restrict__ out)
{
    int row = blockIdx.x;
    int st  = row / NB;
    int b   = row % NB;
    int tok = seq[b*seq_stride + st];
    const float4* src = (const float4*)(embed + (size_t)tok*ND);
    float4*       dst = (float4*)(out + (size_t)row*ND);
    dst[threadIdx.x] = src[threadIdx.x];
}

// ------------------------- tf32 tensor-core GEMM (pipelined) -----------------
__global__ __launch_bounds__(256)
void k_sgemm(int M, int N, int K,
             const float* __restrict__ A, int lda,
             const float* __restrict__ W, int ldw,
             const float* __restrict__ bias1, const float* __restrict__ bias2,
             float* __restrict__ C, int ldc, int act, int out_map, int swap_grid)
{
    __shared__ __align__(16) uint32_t smem_u[8704];   // 34816 B
    float* Cs = (float*)smem_u;                       // [128][68] reuse at end

    int tid  = threadIdx.x;
    int lane = tid & 31;
    int warp = tid >> 5;
    int wm   = warp & 3;
    int wn   = warp >> 2;
    int m0, n0;
    if (swap_grid) { m0 = blockIdx.x*128; n0 = blockIdx.y*64; }
    else           { m0 = blockIdx.y*128; n0 = blockIdx.x*64; }

    int ra = tid >> 2;
    int kc = (tid & 3) * 4;

    uint32_t as_base0 = cvta_s(smem_u);
    uint32_t as_base1 = cvta_s(smem_u + 3840);
    uint32_t ws_row   = (uint32_t)(wn*32 + (lane >> 2))*20 + (lane & 3);

    float acc[2][4][4] = {};

    bool a0v = (m0 + ra < M);
    bool a1v = (m0 + ra + 64 < M);
    bool wv_ = (n0 + ra < N) && (ra < 64);
    const float* Arow0 = A + (size_t)(m0+ra)*lda + kc;
    const float* Arow1 = A + (size_t)(m0+ra+64)*lda + kc;
    const float* Wrow  = W + (size_t)(n0+ra)*ldw + kc;

    float4 a0 = make_float4(0.f,0.f,0.f,0.f);
    float4 a1 = make_float4(0.f,0.f,0.f,0.f);
    float4 w4 = make_float4(0.f,0.f,0.f,0.f);
    if (a0v) a0 = *(const float4*)Arow0;
    if (a1v) a1 = *(const float4*)Arow1;
    if (wv_) w4 = *(const float4*)Wrow;

    int nit = K >> 4;
    {
        uint32_t* As = smem_u;
        uint32_t* Ws = smem_u + 2560;
        *(uint4*)&As[ra*20 + kc]      = make_uint4(f2tf(a0.x), f2tf(a0.y), f2tf(a0.z), f2tf(a0.w));
        *(uint4*)&As[(ra+64)*20 + kc] = make_uint4(f2tf(a1.x), f2tf(a1.y), f2tf(a1.z), f2tf(a1.w));
        if (ra < 64)
            *(uint4*)&Ws[ra*20 + kc]  = make_uint4(f2tf(w4.x), f2tf(w4.y), f2tf(w4.z), f2tf(w4.w));
    }
    __syncthreads();

    for (int it = 0; it < nit; it++) {
        int cur = it & 1;
        if (it + 1 < nit) {
            int k0 = (it + 1) << 4;
            a0 = make_float4(0.f,0.f,0.f,0.f);
            a1 = make_float4(0.f,0.f,0.f,0.f);
            w4 = make_float4(0.f,0.f,0.f,0.f);
            if (a0v) a0 = *(const float4*)(Arow0 + k0);
            if (a1v) a1 = *(const float4*)(Arow1 + k0);
            if (wv_) w4 = *(const float4*)(Wrow  + k0);
        }

        uint32_t as_base = cur ? as_base1 : as_base0;
        uint32_t* Ws = smem_u + cur*3840 + 2560;
        #pragma unroll
        for (int ks = 0; ks < 16; ks += 8) {
            uint32_t afr[2][4];
            #pragma unroll
            for (int mi = 0; mi < 2; mi++) {
                uint32_t row = (uint32_t)(wm*32 + mi*16 + (lane & 15));
                uint32_t kof = (uint32_t)(ks + ((lane >> 4) << 2));
                uint32_t addr = as_base + (row*20 + kof)*4;
                ldsm_x4(afr[mi][0], afr[mi][1], afr[mi][2], afr[mi][3], addr);
            }
            uint32_t bfr[4][2];
            #pragma unroll
            for (int j = 0; j < 4; j++) {
                bfr[j][0] = Ws[ws_row + (uint32_t)(j*8)*20 + ks];
                bfr[j][1] = Ws[ws_row + (uint32_t)(j*8)*20 + ks + 4];
            }
            #pragma unroll
            for (int mi = 0; mi < 2; mi++)
                #pragma unroll
                for (int j = 0; j < 4; j++)
                    mma_tf32(acc[mi][j], afr[mi][0], afr[mi][1], afr[mi][2],
                             afr[mi][3], bfr[j][0], bfr[j][1]);
        }

        if (it + 1 < nit) {
            uint32_t* As2 = smem_u + (cur ^ 1)*3840;
            uint32_t* Ws2 = smem_u + (cur ^ 1)*3840 + 2560;
            *(uint4*)&As2[ra*20 + kc]      = make_uint4(f2tf(a0.x), f2tf(a0.y), f2tf(a0.z), f2tf(a0.w));
            *(uint4*)&As2[(ra+64)*20 + kc] = make_uint4(f2tf(a1.x), f2tf(a1.y), f2tf(a1.z), f2tf(a1.w));
            if (ra < 64)
                *(uint4*)&Ws2[ra*20 + kc]  = make_uint4(f2tf(w4.x), f2tf(w4.y), f2tf(w4.z), f2tf(w4.w));
        }
        __syncthreads();
    }

    #pragma unroll
    for (int mi = 0; mi < 2; mi++) {
        int ml0 = wm*32 + mi*16 + (lane >> 2);
        #pragma unroll
        for (int j = 0; j < 4; j++) {
            int nl = wn*32 + j*8 + (lane & 3)*2;
            float b0v = 0.f, b1v = 0.f;
            if (n0 + nl < N) {
                b0v = bias1[n0+nl];
                if (bias2) b0v += bias2[n0+nl];
            }
            if (n0 + nl + 1 < N) {
                b1v = bias1[n0+nl+1];
                if (bias2) b1v += bias2[n0+nl+1];
            }
            float v0 = acc[mi][j][0] + b0v;
            float v1 = acc[mi][j][1] + b1v;
            float v2 = acc[mi][j][2] + b0v;
            float v3 = acc[mi][j][3] + b1v;
            if (act == 1) { v0=tanhf(v0); v1=tanhf(v1); v2=tanhf(v2); v3=tanhf(v3); }
            else if (act == 2) { v0=fmaxf(v0,0.f); v1=fmaxf(v1,0.f);
                                 v2=fmaxf(v2,0.f); v3=fmaxf(v3,0.f); }
            Cs[ml0*68 + nl]       = v0;
            Cs[ml0*68 + nl + 1]   = v1;
            Cs[(ml0+8)*68 + nl]   = v2;
            Cs[(ml0+8)*68 + nl+1] = v3;
        }
    }
    __syncthreads();

    if (out_map == 2) {
        for (int c = tid; c < 2048; c += 256) {
            int qb = (c & 7) * 4;
            int nl = (c >> 3) & 63;
            int sh = c >> 9;
            int mgrp = m0 + sh*32;
            if (mgrp >= M) continue;
            float4 v4 = make_float4(Cs[(sh*32+qb+0)*68 + nl],
                                    Cs[(sh*32+qb+1)*68 + nl],
                                    Cs[(sh*32+qb+2)*68 + nl],
                                    Cs[(sh*32+qb+3)*68 + nl]);
            *(float4*)&C[((size_t)(mgrp >> 5)*NG + n0 + nl)*32 + qb] = v4;
        }
        return;
    }

    for (int c = tid; c < 2048; c += 256) {
        int ml = c >> 4;
        int nl = (c & 15) * 4;
        int m = m0 + ml;
        if (m >= M) continue;
        size_t row = (out_map == 1) ? (size_t)((m & 31)*NT + (m >> 5)) : (size_t)m;
        int n = n0 + nl;
        if (n + 3 < N) {
            *(float4*)&C[row*ldc + n] = *(const float4*)&Cs[ml*68 + nl];
        } else {
            for (int j = 0; j < 4; j++)
                if (n + j < N) C[row*ldc + n + j] = Cs[ml*68 + nl + j];
        }
    }
}

// ------------------------- tensor-core persistent encoder -------------------
// g_hbuf carries tf32 BITS during the encoder (producer-side convert):
// loader is a pure uint4 copy, cell does one cvt per (b,u).
#define HPITCH 1028
__global__ void __launch_bounds__(256, 1)
k_enc_persist(const float* __restrict__ Whh, const int* __restrict__ lengths)
{
    extern __shared__ float sm[];
    float* sH = sm;                          // [32][HPITCH] tf32 bits
    float* sZ = sm + 32*HPITCH;              // [8][32][33]

    int tid  = threadIdx.x;
    int lane = tid & 31;
    int warp = tid >> 5;
    int u0   = blockIdx.x * 8;

    // ---- load Whh slice as B fragments (once) ----
    uint32_t wf[4][16][2];
    {
        int nr  = lane >> 2;
        int kq  = lane & 3;
        #pragma unroll
        for (int nt = 0; nt < 4; nt++) {
            int n = nt*8 + nr;
            const float* wrow = Whh + (size_t)((n >> 3)*NH + u0 + (n & 7))*NH
                                + warp*128 + kq;
            #pragma unroll
            for (int kt = 0; kt < 16; kt++) {
                wf[nt][kt][0] = f2tf(__ldg(&wrow[kt*8]));
                wf[nt][kt][1] = f2tf(__ldg(&wrow[kt*8 + 4]));
            }
        }
    }

    int cb = tid & 31;
    int cu = tid >> 5;
    int mylen = lengths[cb];
    int len_hi = 0;
    #pragma unroll
    for (int i = 16; i < 32; i++) len_hi = max(len_hi, lengths[i]);
    float creg = 0.0f, hreg = 0.0f;

    g_hbuf[cb*NH + u0 + cu] = 0.0f;          // tf32(0) == 0 bits

    int lr    = tid >> 3;
    int lane8 = tid & 7;
    uint32_t sh_base = cvta_s(sH);

    gridbar();

    for (int s = 0; s < NS; s++) {
        const float* hin  = g_hbuf + (s & 1)*(NB*NH);
        float*       hout = g_hbuf + ((s & 1) ^ 1)*(NB*NH);
        bool act_hi = (s < len_hi);

        const float* xp = g_xproj + ((size_t)s*NG + u0 + cu)*32 + cb;
        float xg0 = __ldg(&xp[0]);
        float xg1 = __ldg(&xp[(size_t)NH*32]);
        float xg2 = __ldg(&xp[(size_t)2*NH*32]);
        float xg3 = __ldg(&xp[(size_t)3*NH*32]);

        // ---- pure copy: g_hbuf already holds tf32 bits ----
        if (lr < 16 || act_hi) {
            const uint4* hr = (const uint4*)(hin + lr*NH);
            #pragma unroll 8
            for (int kk = 0; kk < 32; kk++) {
                uint4 v = __ldcg(&hr[lane8 + 8*kk]);
                *(uint4*)&sH[lr*HPITCH + (lane8 + 8*kk)*4] = v;
            }
        }
        __syncthreads();

        float acc[2][4][4] = {};
        int kbase = warp*128;
        #pragma unroll
        for (int kt = 0; kt < 16; kt++) {
            int kof = kbase + kt*8 + ((lane >> 4) << 2);
            {
                uint32_t a0, a1, a2, a3;
                uint32_t addr = sh_base + (uint32_t)(((lane & 15))*HPITCH + kof)*4;
                ldsm_x4(a0, a1, a2, a3, addr);
                #pragma unroll
                for (int nt = 0; nt < 4; nt++)
                    mma_tf32(acc[0][nt], a0, a1, a2, a3,
                             wf[nt][kt][0], wf[nt][kt][1]);
            }
            if (act_hi) {
                uint32_t a0, a1, a2, a3;
                uint32_t addr = sh_base + (uint32_t)((16 + (lane & 15))*HPITCH + kof)*4;
                ldsm_x4(a0, a1, a2, a3, addr);
                #pragma unroll
                for (int nt = 0; nt < 4; nt++)
                    mma_tf32(acc[1][nt], a0, a1, a2, a3,
                             wf[nt][kt][0], wf[nt][kt][1]);
            }
        }

        {
            float* zw = sZ + warp*(32*33);
            int rr = lane >> 2;
            int cc = (lane & 3)*2;
            #pragma unroll
            for (int mi = 0; mi < 2; mi++) {
                if (mi == 1 && !act_hi) break;
                #pragma unroll
                for (int nt = 0; nt < 4; nt++) {
                    int col = nt*8 + cc;
                    int row = mi*16 + rr;
                    zw[col*33 + row]       = acc[mi][nt][0];
                    zw[(col+1)*33 + row]   = acc[mi][nt][1];
                    zw[col*33 + row + 8]   = acc[mi][nt][2];
                    zw[(col+1)*33 + row+8] = acc[mi][nt][3];
                }
            }
        }
        __syncthreads();

        float zg4[4] = {xg0, xg1, xg2, xg3};
        #pragma unroll
        for (int g = 0; g < 4; g++) {
            int col = g*8 + cu;
            #pragma unroll
            for (int w = 0; w < 8; w++)
                zg4[g] += sZ[w*(32*33) + col*33 + cb];
        }
        float cn = sigmf_(zg4[1])*creg + sigmf_(zg4[0])*tanhf(zg4[2]);
        float hn = sigmf_(zg4[3])*tanhf(cn);
        bool msk = (s < mylen);
        creg = msk ? cn : creg;
        hreg = msk ? hn : hreg;
        ((uint32_t*)hout)[cb*NH + u0 + cu] = f2tf(hreg);   // producer-side cvt
        g_enc_out[((size_t)(s*NB + cb))*NH + u0 + cu] = msk ? hreg : 0.0f;

        gridbar();
    }

    g_h[cb*NH + u0 + cu] = hreg;
    g_c[cb*NH + u0 + cu] = creg;
}

// ------------------------- persistent decoder helpers -----------------------
__device__ __forceinline__ void dec_feat(int tt, const float* __restrict__ hsrc,
    const float* __restrict__ out_W, const float* __restrict__ out_b,
    float* sH, float* sZ, int fn0)
{
    int tid = threadIdx.x;
    int r   = tid >> 6;
    int fks = (tid >> 5) & 1;
    int fb  = tid & 31;
    int lb  = tid >> 3;
    int lq  = tid & 7;
    const float* wrow = out_W + (size_t)(fn0 + r)*(2*NH);
    float fa = 0.f;

    float4 p0, p1, p2, p3;
    {
        const float* hr = hsrc + lb*NH;
        p0 = __ldcg((const float4*)&hr[4*lq]);
        p1 = __ldcg((const float4*)&hr[4*(lq+8)]);
        p2 = __ldcg((const float4*)&hr[4*(lq+16)]);
        p3 = __ldcg((const float4*)&hr[4*(lq+24)]);
        stash4(sH, lq, lb, p0, p1, p2, p3);
    }
    __syncthreads();

    for (int ch = 0; ch < 16; ch++) {
        float* cur = sH + (ch & 1)*(128*36);
        if (ch < 15) {
            int cn_ = ch + 1;
            const float* src = (cn_ < 8) ? hsrc : g_ctx;
            const float* hr = src + lb*NH + (cn_ & 7)*128;
            p0 = __ldcg((const float4*)&hr[4*lq]);
            p1 = __ldcg((const float4*)&hr[4*(lq+8)]);
            p2 = __ldcg((const float4*)&hr[4*(lq+16)]);
            p3 = __ldcg((const float4*)&hr[4*(lq+24)]);
        }
        const float* wc = wrow + ch*128 + fks*64;
        const float* hc = cur + fks*64*36 + fb;
        #pragma unroll 16
        for (int k = 0; k < 64; k++)
            fa += __ldg(&wc[k]) * hc[k*36];
        if (ch < 15)
            stash4(sH + ((ch & 1) ^ 1)*(128*36), lq, lb, p0, p1, p2, p3);
        __syncthreads();
    }
    sZ[(r*2 + fks)*33 + fb] = fa;
    __syncthreads();
    if (tid < 128) {
        int rr = tid >> 5, bb = tid & 31;
        float v = sZ[(rr*2)*33 + bb] + sZ[(rr*2+1)*33 + bb] + __ldg(&out_b[fn0 + rr]);
        g_feat[((size_t)(tt*NB + bb))*ND + fn0 + rr] = v;
    }
    __syncthreads();
}

__device__ __forceinline__ void dec_attn(int b, int mylen,
    const float* __restrict__ hcur,
    const float* __restrict__ ak_W, const float* __restrict__ ak_b,
    float* sW)
{
    int tid = threadIdx.x;
    float* sh_ = sW;
    float* sak = sW + 1024;
    float* se  = sW + 1152;
    float* sr  = sW + 1280;

    for (int i = tid; i < NH; i += 256) sh_[i] = __ldcg(&hcur[b*NH + i]);
    __syncthreads();

    if (tid < NK) {
        const float* wr = ak_W + (size_t)tid*NH;
        float acc0 = 0.f, acc1 = 0.f;
        for (int k = 0; k < NH; k += 8) {
            float4 w0 = *(const float4*)&wr[k];
            float4 w1 = *(const float4*)&wr[k+4];
            float4 h0 = *(const float4*)&sh_[k];
            float4 h1 = *(const float4*)&sh_[k+4];
            acc0 += w0.x*h0.x + w0.y*h0.y + w0.z*h0.z + w0.w*h0.w;
            acc1 += w1.x*h1.x + w1.y*h1.y + w1.z*h1.z + w1.w*h1.w;
        }
        sak[tid] = tanhf(acc0 + acc1 + ak_b[tid]);
    }
    __syncthreads();

    if (tid < NS) {
        const float* qr = g_qkey + ((size_t)(tid*NB + b))*NK;
        float acc = 0.f;
        for (int k = 0; k < NK; k++) acc += qr[k]*sak[k];
        se[tid] = (tid < mylen) ? acc : -INFINITY;
    }
    __syncthreads();

    sr[tid] = (tid < NS) ? se[tid] : -INFINITY;
    __syncthreads();
    for (int off = 128; off >= 1; off >>= 1) {
        if (tid < off) sr[tid] = fmaxf(sr[tid], sr[tid+off]);
        __syncthreads();
    }
    float mx = sr[0];
    __syncthreads();

    float ex = (tid < NS) ? expf(se[tid] - mx) : 0.0f;
    sr[tid] = ex;
    __syncthreads();
    for (int off = 128; off >= 1; off >>= 1) {
        if (tid < off) sr[tid] += sr[tid+off];
        __syncthreads();
    }
    float inv = 1.0f / sr[0];
    __syncthreads();
    if (tid < NS) g_attw[b*NS + tid] = ex * inv;
    __syncthreads();
}

// ------------------------- persistent decoder -------------------------------
__global__ void __launch_bounds__(256, 1)
k_dec_persist(const float* __restrict__ dec_Wih, const float* __restrict__ dec_Whh,
              const float* __restrict__ ak_W,   const float* __restrict__ ak_b,
              const float* __restrict__ out_W,  const float* __restrict__ out_b,
              const int* __restrict__ lengths)
{
    extern __shared__ float sm[];
    float* sW = sm;                     // 2 x [128][36]
    float* sH = sm + 2*128*36;          // 2 x [128][36]
    float* sZ = sm + 4*128*36;          // [4][32][33]

    int tid = threadIdx.x;
    int blk = blockIdx.x;
    int u0  = blk * 8;
    int fn0 = blk * 4;

    int cb = tid & 31, cu = tid >> 5;
    float creg = g_c[cb*NH + u0 + cu];

    int rq = tid & 7;
    int bq = (tid >> 3) & 7;
    int ks = tid >> 6;
    int lb = tid >> 3;
    int lq = tid & 7;
    int wr_ = tid >> 3;
    int wn_ = (wr_ >> 3)*NH + u0 + (wr_ & 7);

    int mylen = (blk < 32) ? lengths[blk] : 0;

    for (int t = 0; t < NT; t++) {
        const float* hcur = (t == 0) ? g_h : (g_hbuf + ((t-1) & 1)*(NB*NH));
        float*       hnew = g_hbuf + (t & 1)*(NB*NH);

        if (t > 0)
            dec_feat(t-1, hcur, out_W, out_b, sH, sZ, fn0);
        if (blk < 32)
            dec_attn(blk, mylen, hcur, ak_W, ak_b, sW);
        gridbar();

        // ---- context ----
        {
            int b  = blk & 31;
            int hq = blk >> 5;
            if (tid < NS) sZ[tid] = __ldcg(&g_attw[b*NS + tid]);
            __syncthreads();
            int hh = hq*256 + tid;
            float a0 = 0.f, a1 = 0.f, a2 = 0.f, a3 = 0.f;
            #pragma unroll 4
            for (int s = 0; s < NS; s += 4) {
                a0 += sZ[s+0]*__ldg(&g_qval[((size_t)((s+0)*NB + b))*NH + hh]);
                a1 += sZ[s+1]*__ldg(&g_qval[((size_t)((s+1)*NB + b))*NH + hh]);
                a2 += sZ[s+2]*__ldg(&g_qval[((size_t)((s+2)*NB + b))*NH + hh]);
                a3 += sZ[s+3]*__ldg(&g_qval[((size_t)((s+3)*NB + b))*NH + hh]);
            }
            g_ctx[b*NH + hh] = (a0 + a1) + (a2 + a3);
            __syncthreads();
        }
        gridbar();

        const float* xp = g_dxe + ((size_t)t*NG + u0 + cu)*32 + cb;
        float xg0 = __ldg(&xp[0]);
        float xg1 = __ldg(&xp[(size_t)NH*32]);
        float xg2 = __ldg(&xp[(size_t)2*NH*32]);
        float xg3 = __ldg(&xp[(size_t)3*NH*32]);

        // ---- z GEMM, double-buffered W and H, f32x2 core ----
        ull_t acc2[4][2] = {};
        float4 pH0, pH1, pH2, pH3, pW0, pW1, pW2, pW3;
        {
            const float* hr = hcur + lb*NH;
            pH0 = __ldcg((const float4*)&hr[4*lq]);
            pH1 = __ldcg((const float4*)&hr[4*(lq+8)]);
            pH2 = __ldcg((const float4*)&hr[4*(lq+16)]);
            pH3 = __ldcg((const float4*)&hr[4*(lq+24)]);
            const float* wrow = dec_Whh + (size_t)wn_*NH;
            pW0 = __ldg((const float4*)&wrow[4*lq]);
            pW1 = __ldg((const float4*)&wrow[4*(lq+8)]);
            pW2 = __ldg((const float4*)&wrow[4*(lq+16)]);
            pW3 = __ldg((const float4*)&wrow[4*(lq+24)]);
            stash4(sH, lq, lb, pH0, pH1, pH2, pH3);
            stash4(sW, lq, wr_, pW0, pW1, pW2, pW3);
        }
        __syncthreads();

        for (int ch = 0; ch < 16; ch++) {
            float* curW = sW + (ch & 1)*(128*36);
            float* curH = sH + (ch & 1)*(128*36);
            if (ch < 15) {
                int cn_ = ch + 1;
                const float* asrc = (cn_ < 8) ? hcur : g_ctx;
                int kc = (cn_ & 7)*128;
                const float* hr = asrc + lb*NH + kc;
                pH0 = __ldcg((const float4*)&hr[4*lq]);
                pH1 = __ldcg((const float4*)&hr[4*(lq+8)]);
                pH2 = __ldcg((const float4*)&hr[4*(lq+16)]);
                pH3 = __ldcg((const float4*)&hr[4*(lq+24)]);
                const float* wrow = (cn_ < 8)
                    ? (dec_Whh + (size_t)wn_*NH + kc)
                    : (dec_Wih + (size_t)wn_*(ND+NH) + ND + kc);
                pW0 = __ldg((const float4*)&wrow[4*lq]);
                pW1 = __ldg((const float4*)&wrow[4*(lq+8)]);
                pW2 = __ldg((const float4*)&wrow[4*(lq+16)]);
                pW3 = __ldg((const float4*)&wrow[4*(lq+24)]);
            }
            for (int kb = 0; kb < 128; kb += 16) {
                int k = kb + 4*ks;
                #pragma unroll
                for (int kk2 = 0; kk2 < 4; kk2++) {
                    float4 wv = *(const float4*)&curW[(k+kk2)*36 + 4*rq];
                    ulonglong2 hq2 = *(const ulonglong2*)&curH[(k+kk2)*36 + 4*bq];
                    ull_t d0 = dup2(wv.x), d1 = dup2(wv.y);
                    ull_t d2 = dup2(wv.z), d3 = dup2(wv.w);
                    ffma2(acc2[0][0], d0, hq2.x); ffma2(acc2[0][1], d0, hq2.y);
                    ffma2(acc2[1][0], d1, hq2.x); ffma2(acc2[1][1], d1, hq2.y);
                    ffma2(acc2[2][0], d2, hq2.x); ffma2(acc2[2][1], d2, hq2.y);
                    ffma2(acc2[3][0], d3, hq2.x); ffma2(acc2[3][1], d3, hq2.y);
                }
            }
            if (ch < 15) {
                stash4(sH + ((ch & 1) ^ 1)*(128*36), lq, lb, pH0, pH1, pH2, pH3);
                stash4(sW + ((ch & 1) ^ 1)*(128*36), lq, wr_, pW0, pW1, pW2, pW3);
            }
            __syncthreads();
        }

        #pragma unroll
        for (int i = 0; i < 4; i++) {
            float2 t0 = unpk(acc2[i][0]);
            float2 t1 = unpk(acc2[i][1]);
            float* zr = &sZ[(ks*32 + 4*rq + i)*33 + 4*bq];
            zr[0] = t0.x; zr[1] = t0.y; zr[2] = t1.x; zr[3] = t1.y;
        }
        __syncthreads();

        {
            float zg4[4] = {xg0, xg1, xg2, xg3};
            #pragma unroll
            for (int g = 0; g < 4; g++)
                #pragma unroll
                for (int q = 0; q < 4; q++) zg4[g] += sZ[(q*32 + g*8 + cu)*33 + cb];
            float cn = sigmf_(zg4[1])*creg + sigmf_(zg4[0])*tanhf(zg4[2]);
            float hn = sigmf_(zg4[3])*tanhf(cn);
            creg = cn;
            hnew[cb*NH + u0 + cu] = hn;
        }
        __syncthreads();
        gridbar();
    }

    {
        const float* hlast = g_hbuf + ((NT-1) & 1)*(NB*NH);
        dec_feat(NT-1, hlast, out_W, out_b, sH, sZ, fn0);
    }
}

// =============================================================================
extern "C" void kernel_launch(void* const* d_in, const int* in_sizes, int n_in,
                              void* d_out, int out_size)
{
    const float* embed    = (const float*)d_in[0];
    const float* enc_Wih  = (const float*)d_in[1];
    const float* enc_Whh  = (const float*)d_in[2];
    const float* enc_bih  = (const float*)d_in[3];
    const float* enc_bhh  = (const float*)d_in[4];
    const float* dec_Wih  = (const float*)d_in[5];
    const float* dec_Whh  = (const float*)d_in[6];
    const float* dec_bih  = (const float*)d_in[7];
    const float* dec_bhh  = (const float*)d_in[8];
    const float* qk_W     = (const float*)d_in[9];
    const float* qk_b     = (const float*)d_in[10];
    const float* qv_W     = (const float*)d_in[11];
    const float* qv_b     = (const float*)d_in[12];
    const float* ak_W     = (const float*)d_in[13];
    const float* ak_b     = (const float*)d_in[14];
    const float* out_W    = (const float*)d_in[15];
    const float* out_b    = (const float*)d_in[16];
    const float* wd_b     = (const float*)d_in[17];
    const float* hfc1_W   = (const float*)d_in[18];
    const float* hfc1_b   = (const float*)d_in[19];
    const float* hfc2_W   = (const float*)d_in[20];
    const float* hfc2_b   = (const float*)d_in[21];
    const float* cfc1_W   = (const float*)d_in[22];
    const float* cfc1_b   = (const float*)d_in[23];
    const float* cfc2_W   = (const float*)d_in[24];
    const float* cfc2_b   = (const float*)d_in[25];
    const int*   src_seqs = (const int*)d_in[26];
    const int*   src_len  = (const int*)d_in[27];
    const int*   trg_seqs = (const int*)d_in[28];
    float* out = (float*)d_out;

    float *d_src_embed, *d_ans_embed, *d_xproj, *d_dxe, *d_h, *d_c;
    float *d_enc_out, *d_qkey, *d_qval, *d_tmp, *d_feat;
    cudaGetSymbolAddress((void**)&d_src_embed, g_src_embed);
    cudaGetSymbolAddress((void**)&d_ans_embed, g_ans_embed);
    cudaGetSymbolAddress((void**)&d_xproj,     g_xproj);
    cudaGetSymbolAddress((void**)&d_dxe,       g_dxe);
    cudaGetSymbolAddress((void**)&d_h,         g_h);
    cudaGetSymbolAddress((void**)&d_c,         g_c);
    cudaGetSymbolAddress((void**)&d_enc_out,   g_enc_out);
    cudaGetSymbolAddress((void**)&d_qkey,      g_qkey);
    cudaGetSymbolAddress((void**)&d_qval,      g_qval);
    cudaGetSymbolAddress((void**)&d_tmp,       g_tmp);
    cudaGetSymbolAddress((void**)&d_feat,      g_feat);

    // ---- precompute ----
    k_gather<<<NS*NB, 128>>>(src_seqs, NS, embed, d_src_embed);
    k_gather<<<NT*NB, 128>>>(trg_seqs, 20, embed, d_ans_embed);

    k_sgemm<<<dim3(NG/64, (NS*NB)/128), 256>>>(NS*NB, NG, ND,
        d_src_embed, ND, enc_Wih, ND, enc_bih, enc_bhh, d_xproj, NG, 0, 2, 0);
    k_sgemm<<<dim3(NG/64, (NT*NB + 127)/128), 256>>>(NT*NB, NG, ND,
        d_ans_embed, ND, dec_Wih, ND + NH, dec_bih, dec_bhh, d_dxe, NG, 0, 2, 0);

    // ---- encoder recurrence: tensor-core persistent kernel ----
    const int enc_smem = (32*HPITCH + 8*32*33) * (int)sizeof(float);
    cudaFuncSetAttribute(k_enc_persist,
                         cudaFuncAttributeMaxDynamicSharedMemorySize, enc_smem);
    k_enc_persist<<<NBLK, 256, enc_smem>>>(enc_Whh, src_len);

    // ---- bridge MLPs ----
    k_sgemm<<<dim3(2048/64, 1), 256>>>(NB, 2048, NH, d_h, NH, hfc1_W, NH,
                                       hfc1_b, nullptr, d_tmp, 2048, 2, 0, 0);
    k_sgemm<<<dim3(NH/64, 1), 256>>>(NB, NH, 2048, d_tmp, 2048, hfc2_W, 2048,
                                     hfc2_b, nullptr, d_h, NH, 0, 0, 0);
    k_sgemm<<<dim3(2048/64, 1), 256>>>(NB, 2048, NH, d_c, NH, cfc1_W, NH,
                                       cfc1_b, nullptr, d_tmp, 2048, 2, 0, 0);
    k_sgemm<<<dim3(NH/64, 1), 256>>>(NB, NH, 2048, d_tmp, 2048, cfc2_W, 2048,
                                     cfc2_b, nullptr, d_c, NH, 0, 0, 0);

    // ---- attention precompute ----
    k_sgemm<<<dim3((NK + 63)/64, (NS*NB)/128), 256>>>(NS*NB, NK, NH,
        d_enc_out, NH, qk_W, NH, qk_b, nullptr, d_qkey, NK, 1, 0, 0);
    k_sgemm<<<dim3(NH/64, (NS*NB)/128), 256>>>(NS*NB, NH, NH,
        d_enc_out, NH, qv_W, NH, qv_b, nullptr, d_qval, NH, 0, 0, 0);

    // ---- decoder recurrence ----
    const int dec_smem = (4*128*36 + 4*32*33) * (int)sizeof(float);
    cudaFuncSetAttribute(k_dec_persist,
                         cudaFuncAttributeMaxDynamicSharedMemorySize, dec_smem);
    k_dec_persist<<<NBLK, 256, dec_smem>>>(dec_Wih, dec_Whh, ak_W, ak_b,
                                           out_W, out_b, src_len);

    // ---- final logits: swap_grid so adjacent blocks share embed n-tiles ----
    k_sgemm<<<dim3((NT*NB + 127)/128, NV/64), 256>>>(NT*NB, NV, ND,
        d_feat, ND, embed, ND, wd_b, nullptr, out, NV, 0, 1, 1);

    (void)in_sizes; (void)n_in; (void)out_size;
}

// round 11
// speedup vs baseline: 1.1005x; 1.1005x over previous
#include <cuda_runtime.h>
#include <math.h>
#include <stdint.h>

// Problem dims (fixed by the dataset)
#define NB 32      // batch
#define NS 128     // src seq len
#define NT 19      // decoder steps (T-1)
#define ND 512     // embed dim
#define NH 1024    // hidden
#define NG 4096    // 4*H
#define NK 100     // attn key dim
#define NV 32000   // vocab
#define NBLK 128

typedef unsigned long long ull_t;

// ------------------------- scratch (device globals; no allocs) ---------------
__device__ float g_src_embed[NS*NB*ND];
__device__ float g_ans_embed[NT*NB*ND];
__device__ float g_xproj[NS*NG*NB];         // [s][n][b]
__device__ float g_dxe[NT*NG*NB];           // [t][n][b]
__device__ float g_h[NB*NH];
__device__ float g_c[NB*NH];
__device__ float g_hbuf[2*NB*NH];           // enc: tf32 bits; dec: fp32
__device__ float g_enc_out[NS*NB*NH];
__device__ float g_qkey[NS*NB*NK];
__device__ float g_qval[NS*NB*NH];
__device__ float g_tmp[NB*2048];
__device__ float g_ctx[NB*NH];
__device__ float g_attw[NB*NS];
__device__ float g_feat[NT*NB*ND];

__device__ unsigned g_barcnt = 0;
__device__ unsigned g_bargen = 0;

__device__ __forceinline__ float sigmf_(float x) { return 1.0f/(1.0f+expf(-x)); }

// ---- packed f32x2 helpers (decoder FFMA2 path) ----
__device__ __forceinline__ void ffma2(ull_t& d, ull_t a, ull_t b)
{
    asm("fma.rn.f32x2 %0, %1, %2, %3;" : "=l"(d) : "l"(a), "l"(b), "l"(d));
}
__device__ __forceinline__ ull_t dup2(float x)
{
    ull_t r;
    asm("mov.b64 %0, {%1, %1};" : "=l"(r) : "f"(x));
    return r;
}
__device__ __forceinline__ float2 unpk(ull_t v)
{
    float2 r;
    asm("mov.b64 {%0, %1}, %2;" : "=f"(r.x), "=f"(r.y) : "l"(v));
    return r;
}

// ---- tf32 tensor-core helpers ----
__device__ __forceinline__ uint32_t f2tf(float x)
{
    uint32_t r;
    asm("cvt.rna.tf32.f32 %0, %1;" : "=r"(r) : "f"(x));
    return r;
}
__device__ __forceinline__ uint32_t cvta_s(const void* p)
{
    uint32_t a;
    asm("{ .reg .u64 t; cvta.to.shared.u64 t, %1; cvt.u32.u64 %0, t; }"
        : "=r"(a) : "l"(p));
    return a;
}
__device__ __forceinline__ void ldsm_x4(uint32_t& r0, uint32_t& r1,
                                        uint32_t& r2, uint32_t& r3, uint32_t addr)
{
    asm volatile("ldmatrix.sync.aligned.m8n8.x4.b16 {%0,%1,%2,%3}, [%4];"
                 : "=r"(r0), "=r"(r1), "=r"(r2), "=r"(r3) : "r"(addr));
}
__device__ __forceinline__ void mma_tf32(float* d, uint32_t a0, uint32_t a1,
                                         uint32_t a2, uint32_t a3,
                                         uint32_t b0, uint32_t b1)
{
    asm volatile(
        "mma.sync.aligned.m16n8k8.row.col.f32.tf32.tf32.f32 "
        "{%0,%1,%2,%3}, {%4,%5,%6,%7}, {%8,%9}, {%0,%1,%2,%3};"
        : "+f"(d[0]), "+f"(d[1]), "+f"(d[2]), "+f"(d[3])
        : "r"(a0), "r"(a1), "r"(a2), "r"(a3), "r"(b0), "r"(b1));
}

// ---- cp.async (16B, zero-fill when vbytes==0) ----
__device__ __forceinline__ void cpasync16(uint32_t dst, const void* src, int vbytes)
{
    asm volatile("cp.async.cg.shared.global [%0], [%1], 16, %2;"
                 :: "r"(dst), "l"(src), "r"(vbytes));
}
__device__ __forceinline__ void cp_commit()
{
    asm volatile("cp.async.commit_group;");
}
__device__ __forceinline__ void cp_wait2()
{
    asm volatile("cp.async.wait_group 2;");
}

// single-counter grid barrier (R9-proven: release = 1 atomic after last arrival)
__device__ __forceinline__ void gridbar()
{
    __syncthreads();
    if (threadIdx.x == 0) {
        __threadfence();
        volatile unsigned* vgen = &g_bargen;
        unsigned gen = *vgen;
        if (atomicAdd(&g_barcnt, 1u) == NBLK - 1) {
            g_barcnt = 0;
            __threadfence();
            atomicAdd(&g_bargen, 1u);
        } else {
            while (*vgen == gen) { __nanosleep(16); }
        }
        __threadfence();
    }
    __syncthreads();
}

// helper: scatter 4 prefetched float4s (rows kk=4*(lq+8p)) into tile[k][row]
__device__ __forceinline__ void stash4(float* buf, int lq, int row,
                                       float4 p0, float4 p1, float4 p2, float4 p3)
{
    buf[(4*lq+0)*36+row]=p0.x; buf[(4*lq+1)*36+row]=p0.y;
    buf[(4*lq+2)*36+row]=p0.z; buf[(4*lq+3)*36+row]=p0.w;
    buf[(4*(lq+8)+0)*36+row]=p1.x; buf[(4*(lq+8)+1)*36+row]=p1.y;
    buf[(4*(lq+8)+2)*36+row]=p1.z; buf[(4*(lq+8)+3)*36+row]=p1.w;
    buf[(4*(lq+16)+0)*36+row]=p2.x; buf[(4*(lq+16)+1)*36+row]=p2.y;
    buf[(4*(lq+16)+2)*36+row]=p2.z; buf[(4*(lq+16)+3)*36+row]=p2.w;
    buf[(4*(lq+24)+0)*36+row]=p3.x; buf[(4*(lq+24)+1)*36+row]=p3.y;
    buf[(4*(lq+24)+2)*36+row]=p3.z; buf[(4*(lq+24)+3)*36+row]=p3.w;
}

// ------------------------- embedding gather ---------------------------------
__global__ void k_gather(const int* __restrict__ seq, int seq_stride,
                         const float* __restrict__ embed, float* __restrict__ out)
{
    int row = blockIdx.x;
    int st  = row / NB;
    int b   = row % NB;
    int tok = seq[b*seq_stride + st];
    const float4* src = (const float4*)(embed + (size_t)tok*ND);
    float4*       dst = (float4*)(out + (size_t)row*ND);
    dst[threadIdx.x] = src[threadIdx.x];
}

// ------------------------- tf32 tensor-core GEMM (cp.async 4-stage) ----------
// Raw fp32 staged via cp.async; tf32 convert at fragment consumption (same
// cvt.rna on the same values -> bit-identical results to the previous version).
#define SGSTG 3840          // stage stride in u32 (As 2560 + Ws 1280)
#define SGSMEM (4*SGSTG*4)  // 61440 bytes
__global__ __launch_bounds__(256)
void k_sgemm(int M, int N, int K,
             const float* __restrict__ A, int lda,
             const float* __restrict__ W, int ldw,
             const float* __restrict__ bias1, const float* __restrict__ bias2,
             float* __restrict__ C, int ldc, int act, int out_map, int swap_grid)
{
    extern __shared__ __align__(16) uint32_t smem_u[];   // 4 stages
    float* Cs = (float*)smem_u;                          // [128][68] reuse at end

    int tid  = threadIdx.x;
    int lane = tid & 31;
    int warp = tid >> 5;
    int wm   = warp & 3;
    int wn   = warp >> 2;
    int m0, n0;
    if (swap_grid) { m0 = blockIdx.x*128; n0 = blockIdx.y*64; }
    else           { m0 = blockIdx.y*128; n0 = blockIdx.x*64; }

    int ra = tid >> 2;
    int kc = (tid & 3) * 4;

    bool a0v = (m0 + ra < M);
    bool a1v = (m0 + ra + 64 < M);
    bool wv_ = (n0 + ra < N) && (ra < 64);
    const float* Arow0 = A + (size_t)(a0v ? (m0+ra)    : 0)*lda + kc;
    const float* Arow1 = A + (size_t)(a1v ? (m0+ra+64) : 0)*lda + kc;
    const float* Wrow  = W + (size_t)(wv_ ? (n0+ra)    : 0)*ldw + kc;
    int az0 = a0v ? 16 : 0, az1 = a1v ? 16 : 0, wz = wv_ ? 16 : 0;

    uint32_t sbase[4];
    #pragma unroll
    for (int s = 0; s < 4; s++) sbase[s] = cvta_s(smem_u + s*SGSTG);
    uint32_t a0off = (uint32_t)(ra*20 + kc)*4;
    uint32_t a1off = (uint32_t)((ra+64)*20 + kc)*4;
    uint32_t woff  = (uint32_t)(2560 + ra*20 + kc)*4;

    uint32_t ws_row = (uint32_t)(wn*32 + (lane >> 2))*20 + (lane & 3);
    float acc[2][4][4] = {};
    int nit = K >> 4;

    // prologue: stages 0..2
    #pragma unroll
    for (int s = 0; s < 3; s++) {
        int k0 = s << 4;
        uint32_t b = sbase[s];
        cpasync16(b + a0off, Arow0 + k0, az0);
        cpasync16(b + a1off, Arow1 + k0, az1);
        if (ra < 64) cpasync16(b + woff, Wrow + k0, wz);
        cp_commit();
    }

    for (int it = 0; it < nit; it++) {
        cp_wait2();
        __syncthreads();

        // issue stage it+3 (buffer free: last read at it-1, fenced by sync above)
        if (it + 3 < nit) {
            int k0 = (it + 3) << 4;
            uint32_t b = sbase[(it + 3) & 3];
            cpasync16(b + a0off, Arow0 + k0, az0);
            cpasync16(b + a1off, Arow1 + k0, az1);
            if (ra < 64) cpasync16(b + woff, Wrow + k0, wz);
        }
        cp_commit();

        uint32_t as_base = sbase[it & 3];
        const float* WsF = (const float*)(smem_u + (it & 3)*SGSTG + 2560);
        #pragma unroll
        for (int ks = 0; ks < 16; ks += 8) {
            uint32_t afr[2][4];
            #pragma unroll
            for (int mi = 0; mi < 2; mi++) {
                uint32_t row = (uint32_t)(wm*32 + mi*16 + (lane & 15));
                uint32_t kof = (uint32_t)(ks + ((lane >> 4) << 2));
                uint32_t addr = as_base + (row*20 + kof)*4;
                ldsm_x4(afr[mi][0], afr[mi][1], afr[mi][2], afr[mi][3], addr);
                #pragma unroll
                for (int q = 0; q < 4; q++)
                    afr[mi][q] = f2tf(__uint_as_float(afr[mi][q]));
            }
            uint32_t bfr[4][2];
            #pragma unroll
            for (int j = 0; j < 4; j++) {
                bfr[j][0] = f2tf(WsF[ws_row + (uint32_t)(j*8)*20 + ks]);
                bfr[j][1] = f2tf(WsF[ws_row + (uint32_t)(j*8)*20 + ks + 4]);
            }
            #pragma unroll
            for (int mi = 0; mi < 2; mi++)
                #pragma unroll
                for (int j = 0; j < 4; j++)
                    mma_tf32(acc[mi][j], afr[mi][0], afr[mi][1], afr[mi][2],
                             afr[mi][3], bfr[j][0], bfr[j][1]);
        }
    }
    __syncthreads();

    // stage C with bias + activation: Cs[m][n], stride 68
    #pragma unroll
    for (int mi = 0; mi < 2; mi++) {
        int ml0 = wm*32 + mi*16 + (lane >> 2);
        #pragma unroll
        for (int j = 0; j < 4; j++) {
            int nl = wn*32 + j*8 + (lane & 3)*2;
            float b0v = 0.f, b1v = 0.f;
            if (n0 + nl < N) {
                b0v = bias1[n0+nl];
                if (bias2) b0v += bias2[n0+nl];
            }
            if (n0 + nl + 1 < N) {
                b1v = bias1[n0+nl+1];
                if (bias2) b1v += bias2[n0+nl+1];
            }
            float v0 = acc[mi][j][0] + b0v;
            float v1 = acc[mi][j][1] + b1v;
            float v2 = acc[mi][j][2] + b0v;
            float v3 = acc[mi][j][3] + b1v;
            if (act == 1) { v0=tanhf(v0); v1=tanhf(v1); v2=tanhf(v2); v3=tanhf(v3); }
            else if (act == 2) { v0=fmaxf(v0,0.f); v1=fmaxf(v1,0.f);
                                 v2=fmaxf(v2,0.f); v3=fmaxf(v3,0.f); }
            Cs[ml0*68 + nl]       = v0;
            Cs[ml0*68 + nl + 1]   = v1;
            Cs[(ml0+8)*68 + nl]   = v2;
            Cs[(ml0+8)*68 + nl+1] = v3;
        }
    }
    __syncthreads();

    if (out_map == 2) {
        for (int c = tid; c < 2048; c += 256) {
            int qb = (c & 7) * 4;
            int nl = (c >> 3) & 63;
            int sh = c >> 9;
            int mgrp = m0 + sh*32;
            if (mgrp >= M) continue;
            float4 v4 = make_float4(Cs[(sh*32+qb+0)*68 + nl],
                                    Cs[(sh*32+qb+1)*68 + nl],
                                    Cs[(sh*32+qb+2)*68 + nl],
                                    Cs[(sh*32+qb+3)*68 + nl]);
            *(float4*)&C[((size_t)(mgrp >> 5)*NG + n0 + nl)*32 + qb] = v4;
        }
        return;
    }

    for (int c = tid; c < 2048; c += 256) {
        int ml = c >> 4;
        int nl = (c & 15) * 4;
        int m = m0 + ml;
        if (m >= M) continue;
        size_t row = (out_map == 1) ? (size_t)((m & 31)*NT + (m >> 5)) : (size_t)m;
        int n = n0 + nl;
        if (n + 3 < N) {
            *(float4*)&C[row*ldc + n] = *(const float4*)&Cs[ml*68 + nl];
        } else {
            for (int j = 0; j < 4; j++)
                if (n + j < N) C[row*ldc + n + j] = Cs[ml*68 + nl + j];
        }
    }
}

// ------------------------- tensor-core persistent encoder -------------------
// g_hbuf carries tf32 BITS (producer-side convert): loader is a pure copy.
#define HPITCH 1028
__global__ void __launch_bounds__(256, 1)
k_enc_persist(const float* __restrict__ Whh, const int* __restrict__ lengths)
{
    extern __shared__ float sm[];
    float* sH = sm;                          // [32][HPITCH] tf32 bits
    float* sZ = sm + 32*HPITCH;              // [8][32][33]

    int tid  = threadIdx.x;
    int lane = tid & 31;
    int warp = tid >> 5;
    int u0   = blockIdx.x * 8;

    uint32_t wf[4][16][2];
    {
        int nr  = lane >> 2;
        int kq  = lane & 3;
        #pragma unroll
        for (int nt = 0; nt < 4; nt++) {
            int n = nt*8 + nr;
            const float* wrow = Whh + (size_t)((n >> 3)*NH + u0 + (n & 7))*NH
                                + warp*128 + kq;
            #pragma unroll
            for (int kt = 0; kt < 16; kt++) {
                wf[nt][kt][0] = f2tf(__ldg(&wrow[kt*8]));
                wf[nt][kt][1] = f2tf(__ldg(&wrow[kt*8 + 4]));
            }
        }
    }

    int cb = tid & 31;
    int cu = tid >> 5;
    int mylen = lengths[cb];
    int len_hi = 0;
    #pragma unroll
    for (int i = 16; i < 32; i++) len_hi = max(len_hi, lengths[i]);
    float creg = 0.0f, hreg = 0.0f;

    g_hbuf[cb*NH + u0 + cu] = 0.0f;          // tf32(0) == 0 bits

    int lr    = tid >> 3;
    int lane8 = tid & 7;
    uint32_t sh_base = cvta_s(sH);

    gridbar();

    for (int s = 0; s < NS; s++) {
        const float* hin  = g_hbuf + (s & 1)*(NB*NH);
        float*       hout = g_hbuf + ((s & 1) ^ 1)*(NB*NH);
        bool act_hi = (s < len_hi);

        const float* xp = g_xproj + ((size_t)s*NG + u0 + cu)*32 + cb;
        float xg0 = __ldg(&xp[0]);
        float xg1 = __ldg(&xp[(size_t)NH*32]);
        float xg2 = __ldg(&xp[(size_t)2*NH*32]);
        float xg3 = __ldg(&xp[(size_t)3*NH*32]);

        if (lr < 16 || act_hi) {
            const uint4* hr = (const uint4*)(hin + lr*NH);
            #pragma unroll 8
            for (int kk = 0; kk < 32; kk++) {
                uint4 v = __ldcg(&hr[lane8 + 8*kk]);
                *(uint4*)&sH[lr*HPITCH + (lane8 + 8*kk)*4] = v;
            }
        }
        __syncthreads();

        float acc[2][4][4] = {};
        int kbase = warp*128;
        #pragma unroll
        for (int kt = 0; kt < 16; kt++) {
            int kof = kbase + kt*8 + ((lane >> 4) << 2);
            {
                uint32_t a0, a1, a2, a3;
                uint32_t addr = sh_base + (uint32_t)(((lane & 15))*HPITCH + kof)*4;
                ldsm_x4(a0, a1, a2, a3, addr);
                #pragma unroll
                for (int nt = 0; nt < 4; nt++)
                    mma_tf32(acc[0][nt], a0, a1, a2, a3,
                             wf[nt][kt][0], wf[nt][kt][1]);
            }
            if (act_hi) {
                uint32_t a0, a1, a2, a3;
                uint32_t addr = sh_base + (uint32_t)((16 + (lane & 15))*HPITCH + kof)*4;
                ldsm_x4(a0, a1, a2, a3, addr);
                #pragma unroll
                for (int nt = 0; nt < 4; nt++)
                    mma_tf32(acc[1][nt], a0, a1, a2, a3,
                             wf[nt][kt][0], wf[nt][kt][1]);
            }
        }

        {
            float* zw = sZ + warp*(32*33);
            int rr = lane >> 2;
            int cc = (lane & 3)*2;
            #pragma unroll
            for (int mi = 0; mi < 2; mi++) {
                if (mi == 1 && !act_hi) break;
                #pragma unroll
                for (int nt = 0; nt < 4; nt++) {
                    int col = nt*8 + cc;
                    int row = mi*16 + rr;
                    zw[col*33 + row]       = acc[mi][nt][0];
                    zw[(col+1)*33 + row]   = acc[mi][nt][1];
                    zw[col*33 + row + 8]   = acc[mi][nt][2];
                    zw[(col+1)*33 + row+8] = acc[mi][nt][3];
                }
            }
        }
        __syncthreads();

        float zg4[4] = {xg0, xg1, xg2, xg3};
        #pragma unroll
        for (int g = 0; g < 4; g++) {
            int col = g*8 + cu;
            #pragma unroll
            for (int w = 0; w < 8; w++)
                zg4[g] += sZ[w*(32*33) + col*33 + cb];
        }
        float cn = sigmf_(zg4[1])*creg + sigmf_(zg4[0])*tanhf(zg4[2]);
        float hn = sigmf_(zg4[3])*tanhf(cn);
        bool msk = (s < mylen);
        creg = msk ? cn : creg;
        hreg = msk ? hn : hreg;
        ((uint32_t*)hout)[cb*NH + u0 + cu] = f2tf(hreg);   // producer-side cvt
        g_enc_out[((size_t)(s*NB + cb))*NH + u0 + cu] = msk ? hreg : 0.0f;

        gridbar();
    }

    g_h[cb*NH + u0 + cu] = hreg;
    g_c[cb*NH + u0 + cu] = creg;
}

// ------------------------- persistent decoder helpers -----------------------
__device__ __forceinline__ void dec_feat(int tt, const float* __restrict__ hsrc,
    const float* __restrict__ out_W, const float* __restrict__ out_b,
    float* sH, float* sZ, int fn0)
{
    int tid = threadIdx.x;
    int r   = tid >> 6;
    int fks = (tid >> 5) & 1;
    int fb  = tid & 31;
    int lb  = tid >> 3;
    int lq  = tid & 7;
    const float* wrow = out_W + (size_t)(fn0 + r)*(2*NH);
    float fa = 0.f;

    float4 p0, p1, p2, p3;
    {
        const float* hr = hsrc + lb*NH;
        p0 = __ldcg((const float4*)&hr[4*lq]);
        p1 = __ldcg((const float4*)&hr[4*(lq+8)]);
        p2 = __ldcg((const float4*)&hr[4*(lq+16)]);
        p3 = __ldcg((const float4*)&hr[4*(lq+24)]);
        stash4(sH, lq, lb, p0, p1, p2, p3);
    }
    __syncthreads();

    for (int ch = 0; ch < 16; ch++) {
        float* cur = sH + (ch & 1)*(128*36);
        if (ch < 15) {
            int cn_ = ch + 1;
            const float* src = (cn_ < 8) ? hsrc : g_ctx;
            const float* hr = src + lb*NH + (cn_ & 7)*128;
            p0 = __ldcg((const float4*)&hr[4*lq]);
            p1 = __ldcg((const float4*)&hr[4*(lq+8)]);
            p2 = __ldcg((const float4*)&hr[4*(lq+16)]);
            p3 = __ldcg((const float4*)&hr[4*(lq+24)]);
        }
        const float* wc = wrow + ch*128 + fks*64;
        const float* hc = cur + fks*64*36 + fb;
        #pragma unroll 16
        for (int k = 0; k < 64; k++)
            fa += __ldg(&wc[k]) * hc[k*36];
        if (ch < 15)
            stash4(sH + ((ch & 1) ^ 1)*(128*36), lq, lb, p0, p1, p2, p3);
        __syncthreads();
    }
    sZ[(r*2 + fks)*33 + fb] = fa;
    __syncthreads();
    if (tid < 128) {
        int rr = tid >> 5, bb = tid & 31;
        float v = sZ[(rr*2)*33 + bb] + sZ[(rr*2+1)*33 + bb] + __ldg(&out_b[fn0 + rr]);
        g_feat[((size_t)(tt*NB + bb))*ND + fn0 + rr] = v;
    }
    __syncthreads();
}

__device__ __forceinline__ void dec_attn(int b, int mylen,
    const float* __restrict__ hcur,
    const float* __restrict__ ak_W, const float* __restrict__ ak_b,
    float* sW)
{
    int tid = threadIdx.x;
    float* sh_ = sW;
    float* sak = sW + 1024;
    float* se  = sW + 1152;
    float* sr  = sW + 1280;

    for (int i = tid; i < NH; i += 256) sh_[i] = __ldcg(&hcur[b*NH + i]);
    __syncthreads();

    if (tid < NK) {
        const float* wr = ak_W + (size_t)tid*NH;
        float acc0 = 0.f, acc1 = 0.f;
        for (int k = 0; k < NH; k += 8) {
            float4 w0 = *(const float4*)&wr[k];
            float4 w1 = *(const float4*)&wr[k+4];
            float4 h0 = *(const float4*)&sh_[k];
            float4 h1 = *(const float4*)&sh_[k+4];
            acc0 += w0.x*h0.x + w0.y*h0.y + w0.z*h0.z + w0.w*h0.w;
            acc1 += w1.x*h1.x + w1.y*h1.y + w1.z*h1.z + w1.w*h1.w;
        }
        sak[tid] = tanhf(acc0 + acc1 + ak_b[tid]);
    }
    __syncthreads();

    if (tid < NS) {
        const float* qr = g_qkey + ((size_t)(tid*NB + b))*NK;
        float acc = 0.f;
        for (int k = 0; k < NK; k++) acc += qr[k]*sak[k];
        se[tid] = (tid < mylen) ? acc : -INFINITY;
    }
    __syncthreads();

    sr[tid] = (tid < NS) ? se[tid] : -INFINITY;
    __syncthreads();
    for (int off = 128; off >= 1; off >>= 1) {
        if (tid < off) sr[tid] = fmaxf(sr[tid], sr[tid+off]);
        __syncthreads();
    }
    float mx = sr[0];
    __syncthreads();

    float ex = (tid < NS) ? expf(se[tid] - mx) : 0.0f;
    sr[tid] = ex;
    __syncthreads();
    for (int off = 128; off >= 1; off >>= 1) {
        if (tid < off) sr[tid] += sr[tid+off];
        __syncthreads();
    }
    float inv = 1.0f / sr[0];
    __syncthreads();
    if (tid < NS) g_attw[b*NS + tid] = ex * inv;
    __syncthreads();
}

// ------------------------- persistent decoder -------------------------------
__global__ void __launch_bounds__(256, 1)
k_dec_persist(const float* __restrict__ dec_Wih, const float* __restrict__ dec_Whh,
              const float* __restrict__ ak_W,   const float* __restrict__ ak_b,
              const float* __restrict__ out_W,  const float* __restrict__ out_b,
              const int* __restrict__ lengths)
{
    extern __shared__ float sm[];
    float* sW = sm;                     // 2 x [128][36]
    float* sH = sm + 2*128*36;          // 2 x [128][36]
    float* sZ = sm + 4*128*36;          // [4][32][33]

    int tid = threadIdx.x;
    int blk = blockIdx.x;
    int u0  = blk * 8;
    int fn0 = blk * 4;

    int cb = tid & 31, cu = tid >> 5;
    float creg = g_c[cb*NH + u0 + cu];

    int rq = tid & 7;
    int bq = (tid >> 3) & 7;
    int ks = tid >> 6;
    int lb = tid >> 3;
    int lq = tid & 7;
    int wr_ = tid >> 3;
    int wn_ = (wr_ >> 3)*NH + u0 + (wr_ & 7);

    int mylen = (blk < 32) ? lengths[blk] : 0;

    for (int t = 0; t < NT; t++) {
        const float* hcur = (t == 0) ? g_h : (g_hbuf + ((t-1) & 1)*(NB*NH));
        float*       hnew = g_hbuf + (t & 1)*(NB*NH);

        if (t > 0)
            dec_feat(t-1, hcur, out_W, out_b, sH, sZ, fn0);
        if (blk < 32)
            dec_attn(blk, mylen, hcur, ak_W, ak_b, sW);
        gridbar();

        // ---- context ----
        {
            int b  = blk & 31;
            int hq = blk >> 5;
            if (tid < NS) sZ[tid] = __ldcg(&g_attw[b*NS + tid]);
            __syncthreads();
            int hh = hq*256 + tid;
            float a0 = 0.f, a1 = 0.f, a2 = 0.f, a3 = 0.f;
            #pragma unroll 4
            for (int s = 0; s < NS; s += 4) {
                a0 += sZ[s+0]*__ldg(&g_qval[((size_t)((s+0)*NB + b))*NH + hh]);
                a1 += sZ[s+1]*__ldg(&g_qval[((size_t)((s+1)*NB + b))*NH + hh]);
                a2 += sZ[s+2]*__ldg(&g_qval[((size_t)((s+2)*NB + b))*NH + hh]);
                a3 += sZ[s+3]*__ldg(&g_qval[((size_t)((s+3)*NB + b))*NH + hh]);
            }
            g_ctx[b*NH + hh] = (a0 + a1) + (a2 + a3);
            __syncthreads();
        }
        gridbar();

        const float* xp = g_dxe + ((size_t)t*NG + u0 + cu)*32 + cb;
        float xg0 = __ldg(&xp[0]);
        float xg1 = __ldg(&xp[(size_t)NH*32]);
        float xg2 = __ldg(&xp[(size_t)2*NH*32]);
        float xg3 = __ldg(&xp[(size_t)3*NH*32]);

        // ---- z GEMM, double-buffered W and H, f32x2 core ----
        ull_t acc2[4][2] = {};
        float4 pH0, pH1, pH2, pH3, pW0, pW1, pW2, pW3;
        {
            const float* hr = hcur + lb*NH;
            pH0 = __ldcg((const float4*)&hr[4*lq]);
            pH1 = __ldcg((const float4*)&hr[4*(lq+8)]);
            pH2 = __ldcg((const float4*)&hr[4*(lq+16)]);
            pH3 = __ldcg((const float4*)&hr[4*(lq+24)]);
            const float* wrow = dec_Whh + (size_t)wn_*NH;
            pW0 = __ldg((const float4*)&wrow[4*lq]);
            pW1 = __ldg((const float4*)&wrow[4*(lq+8)]);
            pW2 = __ldg((const float4*)&wrow[4*(lq+16)]);
            pW3 = __ldg((const float4*)&wrow[4*(lq+24)]);
            stash4(sH, lq, lb, pH0, pH1, pH2, pH3);
            stash4(sW, lq, wr_, pW0, pW1, pW2, pW3);
        }
        __syncthreads();

        for (int ch = 0; ch < 16; ch++) {
            float* curW = sW + (ch & 1)*(128*36);
            float* curH = sH + (ch & 1)*(128*36);
            if (ch < 15) {
                int cn_ = ch + 1;
                const float* asrc = (cn_ < 8) ? hcur : g_ctx;
                int kc = (cn_ & 7)*128;
                const float* hr = asrc + lb*NH + kc;
                pH0 = __ldcg((const float4*)&hr[4*lq]);
                pH1 = __ldcg((const float4*)&hr[4*(lq+8)]);
                pH2 = __ldcg((const float4*)&hr[4*(lq+16)]);
                pH3 = __ldcg((const float4*)&hr[4*(lq+24)]);
                const float* wrow = (cn_ < 8)
                    ? (dec_Whh + (size_t)wn_*NH + kc)
                    : (dec_Wih + (size_t)wn_*(ND+NH) + ND + kc);
                pW0 = __ldg((const float4*)&wrow[4*lq]);
                pW1 = __ldg((const float4*)&wrow[4*(lq+8)]);
                pW2 = __ldg((const float4*)&wrow[4*(lq+16)]);
                pW3 = __ldg((const float4*)&wrow[4*(lq+24)]);
            }
            for (int kb = 0; kb < 128; kb += 16) {
                int k = kb + 4*ks;
                #pragma unroll
                for (int kk2 = 0; kk2 < 4; kk2++) {
                    float4 wv = *(const float4*)&curW[(k+kk2)*36 + 4*rq];
                    ulonglong2 hq2 = *(const ulonglong2*)&curH[(k+kk2)*36 + 4*bq];
                    ull_t d0 = dup2(wv.x), d1 = dup2(wv.y);
                    ull_t d2 = dup2(wv.z), d3 = dup2(wv.w);
                    ffma2(acc2[0][0], d0, hq2.x); ffma2(acc2[0][1], d0, hq2.y);
                    ffma2(acc2[1][0], d1, hq2.x); ffma2(acc2[1][1], d1, hq2.y);
                    ffma2(acc2[2][0], d2, hq2.x); ffma2(acc2[2][1], d2, hq2.y);
                    ffma2(acc2[3][0], d3, hq2.x); ffma2(acc2[3][1], d3, hq2.y);
                }
            }
            if (ch < 15) {
                stash4(sH + ((ch & 1) ^ 1)*(128*36), lq, lb, pH0, pH1, pH2, pH3);
                stash4(sW + ((ch & 1) ^ 1)*(128*36), lq, wr_, pW0, pW1, pW2, pW3);
            }
            __syncthreads();
        }

        #pragma unroll
        for (int i = 0; i < 4; i++) {
            float2 t0 = unpk(acc2[i][0]);
            float2 t1 = unpk(acc2[i][1]);
            float* zr = &sZ[(ks*32 + 4*rq + i)*33 + 4*bq];
            zr[0] = t0.x; zr[1] = t0.y; zr[2] = t1.x; zr[3] = t1.y;
        }
        __syncthreads();

        {
            float zg4[4] = {xg0, xg1, xg2, xg3};
            #pragma unroll
            for (int g = 0; g < 4; g++)
                #pragma unroll
                for (int q = 0; q < 4; q++) zg4[g] += sZ[(q*32 + g*8 + cu)*33 + cb];
            float cn = sigmf_(zg4[1])*creg + sigmf_(zg4[0])*tanhf(zg4[2]);
            float hn = sigmf_(zg4[3])*tanhf(cn);
            creg = cn;
            hnew[cb*NH + u0 + cu] = hn;
        }
        __syncthreads();
        gridbar();
    }

    {
        const float* hlast = g_hbuf + ((NT-1) & 1)*(NB*NH);
        dec_feat(NT-1, hlast, out_W, out_b, sH, sZ, fn0);
    }
}

// =============================================================================
extern "C" void kernel_launch(void* const* d_in, const int* in_sizes, int n_in,
                              void* d_out, int out_size)
{
    const float* embed    = (const float*)d_in[0];
    const float* enc_Wih  = (const float*)d_in[1];
    const float* enc_Whh  = (const float*)d_in[2];
    const float* enc_bih  = (const float*)d_in[3];
    const float* enc_bhh  = (const float*)d_in[4];
    const float* dec_Wih  = (const float*)d_in[5];
    const float* dec_Whh  = (const float*)d_in[6];
    const float* dec_bih  = (const float*)d_in[7];
    const float* dec_bhh  = (const float*)d_in[8];
    const float* qk_W     = (const float*)d_in[9];
    const float* qk_b     = (const float*)d_in[10];
    const float* qv_W     = (const float*)d_in[11];
    const float* qv_b     = (const float*)d_in[12];
    const float* ak_W     = (const float*)d_in[13];
    const float* ak_b     = (const float*)d_in[14];
    const float* out_W    = (const float*)d_in[15];
    const float* out_b    = (const float*)d_in[16];
    const float* wd_b     = (const float*)d_in[17];
    const float* hfc1_W   = (const float*)d_in[18];
    const float* hfc1_b   = (const float*)d_in[19];
    const float* hfc2_W   = (const float*)d_in[20];
    const float* hfc2_b   = (const float*)d_in[21];
    const float* cfc1_W   = (const float*)d_in[22];
    const float* cfc1_b   = (const float*)d_in[23];
    const float* cfc2_W   = (const float*)d_in[24];
    const float* cfc2_b   = (const float*)d_in[25];
    const int*   src_seqs = (const int*)d_in[26];
    const int*   src_len  = (const int*)d_in[27];
    const int*   trg_seqs = (const int*)d_in[28];
    float* out = (float*)d_out;

    float *d_src_embed, *d_ans_embed, *d_xproj, *d_dxe, *d_h, *d_c;
    float *d_enc_out, *d_qkey, *d_qval, *d_tmp, *d_feat;
    cudaGetSymbolAddress((void**)&d_src_embed, g_src_embed);
    cudaGetSymbolAddress((void**)&d_ans_embed, g_ans_embed);
    cudaGetSymbolAddress((void**)&d_xproj,     g_xproj);
    cudaGetSymbolAddress((void**)&d_dxe,       g_dxe);
    cudaGetSymbolAddress((void**)&d_h,         g_h);
    cudaGetSymbolAddress((void**)&d_c,         g_c);
    cudaGetSymbolAddress((void**)&d_enc_out,   g_enc_out);
    cudaGetSymbolAddress((void**)&d_qkey,      g_qkey);
    cudaGetSymbolAddress((void**)&d_qval,      g_qval);
    cudaGetSymbolAddress((void**)&d_tmp,       g_tmp);
    cudaGetSymbolAddress((void**)&d_feat,      g_feat);

    cudaFuncSetAttribute(k_sgemm,
                         cudaFuncAttributeMaxDynamicSharedMemorySize, SGSMEM);

    // ---- precompute ----
    k_gather<<<NS*NB, 128>>>(src_seqs, NS, embed, d_src_embed);
    k_gather<<<NT*NB, 128>>>(trg_seqs, 20, embed, d_ans_embed);

    k_sgemm<<<dim3(NG/64, (NS*NB)/128), 256, SGSMEM>>>(NS*NB, NG, ND,
        d_src_embed, ND, enc_Wih, ND, enc_bih, enc_bhh, d_xproj, NG, 0, 2, 0);
    k_sgemm<<<dim3(NG/64, (NT*NB + 127)/128), 256, SGSMEM>>>(NT*NB, NG, ND,
        d_ans_embed, ND, dec_Wih, ND + NH, dec_bih, dec_bhh, d_dxe, NG, 0, 2, 0);

    // ---- encoder recurrence: tensor-core persistent kernel ----
    const int enc_smem = (32*HPITCH + 8*32*33) * (int)sizeof(float);
    cudaFuncSetAttribute(k_enc_persist,
                         cudaFuncAttributeMaxDynamicSharedMemorySize, enc_smem);
    k_enc_persist<<<NBLK, 256, enc_smem>>>(enc_Whh, src_len);

    // ---- bridge MLPs ----
    k_sgemm<<<dim3(2048/64, 1), 256, SGSMEM>>>(NB, 2048, NH, d_h, NH, hfc1_W, NH,
                                       hfc1_b, nullptr, d_tmp, 2048, 2, 0, 0);
    k_sgemm<<<dim3(NH/64, 1), 256, SGSMEM>>>(NB, NH, 2048, d_tmp, 2048, hfc2_W, 2048,
                                     hfc2_b, nullptr, d_h, NH, 0, 0, 0);
    k_sgemm<<<dim3(2048/64, 1), 256, SGSMEM>>>(NB, 2048, NH, d_c, NH, cfc1_W, NH,
                                       cfc1_b, nullptr, d_tmp, 2048, 2, 0, 0);
    k_sgemm<<<dim3(NH/64, 1), 256, SGSMEM>>>(NB, NH, 2048, d_tmp, 2048, cfc2_W, 2048,
                                     cfc2_b, nullptr, d_c, NH, 0, 0, 0);

    // ---- attention precompute ----
    k_sgemm<<<dim3((NK + 63)/64, (NS*NB)/128), 256, SGSMEM>>>(NS*NB, NK, NH,
        d_enc_out, NH, qk_W, NH, qk_b, nullptr, d_qkey, NK, 1, 0, 0);
    k_sgemm<<<dim3(NH/64, (NS*NB)/128), 256, SGSMEM>>>(NS*NB, NH, NH,
        d_enc_out, NH, qv_W, NH, qv_b, nullptr, d_qval, NH, 0, 0, 0);

    // ---- decoder recurrence ----
    const int dec_smem = (4*128*36 + 4*32*33) * (int)sizeof(float);
    cudaFuncSetAttribute(k_dec_persist,
                         cudaFuncAttributeMaxDynamicSharedMemorySize, dec_smem);
    k_dec_persist<<<NBLK, 256, dec_smem>>>(dec_Wih, dec_Whh, ak_W, ak_b,
                                           out_W, out_b, src_len);

    // ---- final logits: swap_grid so adjacent blocks share embed n-tiles ----
    k_sgemm<<<dim3((NT*NB + 127)/128, NV/64), 256, SGSMEM>>>(NT*NB, NV, ND,
        d_feat, ND, embed, ND, wd_b, nullptr, out, NV, 0, 1, 1);

    (void)in_sizes; (void)n_in; (void)out_size;
}

// round 12
// speedup vs baseline: 1.2074x; 1.0971x over previous
#include <cuda_runtime.h>
#include <math.h>
#include <stdint.h>

// Problem dims (fixed by the dataset)
#define NB 32      // batch
#define NS 128     // src seq len
#define NT 19      // decoder steps (T-1)
#define ND 512     // embed dim
#define NH 1024    // hidden
#define NG 4096    // 4*H
#define NK 100     // attn key dim
#define NV 32000   // vocab
#define NBLK 128

typedef unsigned long long ull_t;

// ------------------------- scratch (device globals; no allocs) ---------------
__device__ float g_src_embed[NS*NB*ND];
__device__ float g_ans_embed[NT*NB*ND];
__device__ float g_xproj[NS*NG*NB];         // [s][n][b]
__device__ float g_dxe[NT*NG*NB];           // [t][n][b]
__device__ float g_h[NB*NH];
__device__ float g_c[NB*NH];
__device__ float g_hbuf[2*NB*NH];           // enc: tf32 bits; dec: fp32
__device__ float g_enc_out[NS*NB*NH];
__device__ float g_qkey[NS*NB*NK];
__device__ float g_qval[NS*NB*NH];
__device__ float g_tmp[NB*2048];
__device__ float g_ctx[NB*NH];
__device__ float g_attw[NB*NS];
__device__ float g_feat[NT*NB*ND];

__device__ unsigned g_barcnt = 0;
__device__ unsigned g_bargen = 0;

__device__ __forceinline__ float sigmf_(float x) { return 1.0f/(1.0f+expf(-x)); }

// ---- tf32 tensor-core helpers ----
__device__ __forceinline__ uint32_t f2tf(float x)
{
    uint32_t r;
    asm("cvt.rna.tf32.f32 %0, %1;" : "=r"(r) : "f"(x));
    return r;
}
__device__ __forceinline__ uint32_t cvta_s(const void* p)
{
    uint32_t a;
    asm("{ .reg .u64 t; cvta.to.shared.u64 t, %1; cvt.u32.u64 %0, t; }"
        : "=r"(a) : "l"(p));
    return a;
}
__device__ __forceinline__ void ldsm_x4(uint32_t& r0, uint32_t& r1,
                                        uint32_t& r2, uint32_t& r3, uint32_t addr)
{
    asm volatile("ldmatrix.sync.aligned.m8n8.x4.b16 {%0,%1,%2,%3}, [%4];"
                 : "=r"(r0), "=r"(r1), "=r"(r2), "=r"(r3) : "r"(addr));
}
__device__ __forceinline__ void mma_tf32(float* d, uint32_t a0, uint32_t a1,
                                         uint32_t a2, uint32_t a3,
                                         uint32_t b0, uint32_t b1)
{
    asm volatile(
        "mma.sync.aligned.m16n8k8.row.col.f32.tf32.tf32.f32 "
        "{%0,%1,%2,%3}, {%4,%5,%6,%7}, {%8,%9}, {%0,%1,%2,%3};"
        : "+f"(d[0]), "+f"(d[1]), "+f"(d[2]), "+f"(d[3])
        : "r"(a0), "r"(a1), "r"(a2), "r"(a3), "r"(b0), "r"(b1));
}

// ---- cp.async (16B, zero-fill when vbytes==0) ----
__device__ __forceinline__ void cpasync16(uint32_t dst, const void* src, int vbytes)
{
    asm volatile("cp.async.cg.shared.global [%0], [%1], 16, %2;"
                 :: "r"(dst), "l"(src), "r"(vbytes));
}
__device__ __forceinline__ void cp_commit()
{
    asm volatile("cp.async.commit_group;");
}
__device__ __forceinline__ void cp_wait2()
{
    asm volatile("cp.async.wait_group 2;");
}

// single-counter grid barrier
__device__ __forceinline__ void gridbar()
{
    __syncthreads();
    if (threadIdx.x == 0) {
        __threadfence();
        volatile unsigned* vgen = &g_bargen;
        unsigned gen = *vgen;
        if (atomicAdd(&g_barcnt, 1u) == NBLK - 1) {
            g_barcnt = 0;
            __threadfence();
            atomicAdd(&g_bargen, 1u);
        } else {
            while (*vgen == gen) { __nanosleep(16); }
        }
        __threadfence();
    }
    __syncthreads();
}

// helper: scatter 4 prefetched float4s (rows kk=4*(lq+8p)) into tile[k][row]
__device__ __forceinline__ void stash4(float* buf, int lq, int row,
                                       float4 p0, float4 p1, float4 p2, float4 p3)
{
    buf[(4*lq+0)*36+row]=p0.x; buf[(4*lq+1)*36+row]=p0.y;
    buf[(4*lq+2)*36+row]=p0.z; buf[(4*lq+3)*36+row]=p0.w;
    buf[(4*(lq+8)+0)*36+row]=p1.x; buf[(4*(lq+8)+1)*36+row]=p1.y;
    buf[(4*(lq+8)+2)*36+row]=p1.z; buf[(4*(lq+8)+3)*36+row]=p1.w;
    buf[(4*(lq+16)+0)*36+row]=p2.x; buf[(4*(lq+16)+1)*36+row]=p2.y;
    buf[(4*(lq+16)+2)*36+row]=p2.z; buf[(4*(lq+16)+3)*36+row]=p2.w;
    buf[(4*(lq+24)+0)*36+row]=p3.x; buf[(4*(lq+24)+1)*36+row]=p3.y;
    buf[(4*(lq+24)+2)*36+row]=p3.z; buf[(4*(lq+24)+3)*36+row]=p3.w;
}

// ------------------------- embedding gather ---------------------------------
__global__ void k_gather(const int* __restrict__ seq, int seq_stride,
                         const float* __restrict__ embed, float* __restrict__ out)
{
    int row = blockIdx.x;
    int st  = row / NB;
    int b   = row % NB;
    int tok = seq[b*seq_stride + st];
    const float4* src = (const float4*)(embed + (size_t)tok*ND);
    float4*       dst = (float4*)(out + (size_t)row*ND);
    dst[threadIdx.x] = src[threadIdx.x];
}

// ------------------------- tf32 tensor-core GEMM (cp.async 4-stage) ----------
#define SGSTG 3840          // stage stride in u32 (As 2560 + Ws 1280)
#define SGSMEM (4*SGSTG*4)  // 61440 bytes
__global__ __launch_bounds__(256)
void k_sgemm(int M, int N, int K,
             const float* __restrict__ A, int lda,
             const float* __restrict__ W, int ldw,
             const float* __restrict__ bias1, const float* __restrict__ bias2,
             float* __restrict__ C, int ldc, int act, int out_map, int swap_grid)
{
    extern __shared__ __align__(16) uint32_t smem_u[];   // 4 stages
    float* Cs = (float*)smem_u;                          // [128][68] reuse at end

    int tid  = threadIdx.x;
    int lane = tid & 31;
    int warp = tid >> 5;
    int wm   = warp & 3;
    int wn   = warp >> 2;
    int m0, n0;
    if (swap_grid) { m0 = blockIdx.x*128; n0 = blockIdx.y*64; }
    else           { m0 = blockIdx.y*128; n0 = blockIdx.x*64; }

    int ra = tid >> 2;
    int kc = (tid & 3) * 4;

    bool a0v = (m0 + ra < M);
    bool a1v = (m0 + ra + 64 < M);
    bool wv_ = (n0 + ra < N) && (ra < 64);
    const float* Arow0 = A + (size_t)(a0v ? (m0+ra)    : 0)*lda + kc;
    const float* Arow1 = A + (size_t)(a1v ? (m0+ra+64) : 0)*lda + kc;
    const float* Wrow  = W + (size_t)(wv_ ? (n0+ra)    : 0)*ldw + kc;
    int az0 = a0v ? 16 : 0, az1 = a1v ? 16 : 0, wz = wv_ ? 16 : 0;

    uint32_t sbase[4];
    #pragma unroll
    for (int s = 0; s < 4; s++) sbase[s] = cvta_s(smem_u + s*SGSTG);
    uint32_t a0off = (uint32_t)(ra*20 + kc)*4;
    uint32_t a1off = (uint32_t)((ra+64)*20 + kc)*4;
    uint32_t woff  = (uint32_t)(2560 + ra*20 + kc)*4;

    uint32_t ws_row = (uint32_t)(wn*32 + (lane >> 2))*20 + (lane & 3);
    float acc[2][4][4] = {};
    int nit = K >> 4;

    #pragma unroll
    for (int s = 0; s < 3; s++) {
        int k0 = s << 4;
        uint32_t b = sbase[s];
        cpasync16(b + a0off, Arow0 + k0, az0);
        cpasync16(b + a1off, Arow1 + k0, az1);
        if (ra < 64) cpasync16(b + woff, Wrow + k0, wz);
        cp_commit();
    }

    for (int it = 0; it < nit; it++) {
        cp_wait2();
        __syncthreads();

        if (it + 3 < nit) {
            int k0 = (it + 3) << 4;
            uint32_t b = sbase[(it + 3) & 3];
            cpasync16(b + a0off, Arow0 + k0, az0);
            cpasync16(b + a1off, Arow1 + k0, az1);
            if (ra < 64) cpasync16(b + woff, Wrow + k0, wz);
        }
        cp_commit();

        uint32_t as_base = sbase[it & 3];
        const float* WsF = (const float*)(smem_u + (it & 3)*SGSTG + 2560);
        #pragma unroll
        for (int ks = 0; ks < 16; ks += 8) {
            uint32_t afr[2][4];
            #pragma unroll
            for (int mi = 0; mi < 2; mi++) {
                uint32_t row = (uint32_t)(wm*32 + mi*16 + (lane & 15));
                uint32_t kof = (uint32_t)(ks + ((lane >> 4) << 2));
                uint32_t addr = as_base + (row*20 + kof)*4;
                ldsm_x4(afr[mi][0], afr[mi][1], afr[mi][2], afr[mi][3], addr);
                #pragma unroll
                for (int q = 0; q < 4; q++)
                    afr[mi][q] = f2tf(__uint_as_float(afr[mi][q]));
            }
            uint32_t bfr[4][2];
            #pragma unroll
            for (int j = 0; j < 4; j++) {
                bfr[j][0] = f2tf(WsF[ws_row + (uint32_t)(j*8)*20 + ks]);
                bfr[j][1] = f2tf(WsF[ws_row + (uint32_t)(j*8)*20 + ks + 4]);
            }
            #pragma unroll
            for (int mi = 0; mi < 2; mi++)
                #pragma unroll
                for (int j = 0; j < 4; j++)
                    mma_tf32(acc[mi][j], afr[mi][0], afr[mi][1], afr[mi][2],
                             afr[mi][3], bfr[j][0], bfr[j][1]);
        }
    }
    __syncthreads();

    #pragma unroll
    for (int mi = 0; mi < 2; mi++) {
        int ml0 = wm*32 + mi*16 + (lane >> 2);
        #pragma unroll
        for (int j = 0; j < 4; j++) {
            int nl = wn*32 + j*8 + (lane & 3)*2;
            float b0v = 0.f, b1v = 0.f;
            if (n0 + nl < N) {
                b0v = bias1[n0+nl];
                if (bias2) b0v += bias2[n0+nl];
            }
            if (n0 + nl + 1 < N) {
                b1v = bias1[n0+nl+1];
                if (bias2) b1v += bias2[n0+nl+1];
            }
            float v0 = acc[mi][j][0] + b0v;
            float v1 = acc[mi][j][1] + b1v;
            float v2 = acc[mi][j][2] + b0v;
            float v3 = acc[mi][j][3] + b1v;
            if (act == 1) { v0=tanhf(v0); v1=tanhf(v1); v2=tanhf(v2); v3=tanhf(v3); }
            else if (act == 2) { v0=fmaxf(v0,0.f); v1=fmaxf(v1,0.f);
                                 v2=fmaxf(v2,0.f); v3=fmaxf(v3,0.f); }
            Cs[ml0*68 + nl]       = v0;
            Cs[ml0*68 + nl + 1]   = v1;
            Cs[(ml0+8)*68 + nl]   = v2;
            Cs[(ml0+8)*68 + nl+1] = v3;
        }
    }
    __syncthreads();

    if (out_map == 2) {
        for (int c = tid; c < 2048; c += 256) {
            int qb = (c & 7) * 4;
            int nl = (c >> 3) & 63;
            int sh = c >> 9;
            int mgrp = m0 + sh*32;
            if (mgrp >= M) continue;
            float4 v4 = make_float4(Cs[(sh*32+qb+0)*68 + nl],
                                    Cs[(sh*32+qb+1)*68 + nl],
                                    Cs[(sh*32+qb+2)*68 + nl],
                                    Cs[(sh*32+qb+3)*68 + nl]);
            *(float4*)&C[((size_t)(mgrp >> 5)*NG + n0 + nl)*32 + qb] = v4;
        }
        return;
    }

    for (int c = tid; c < 2048; c += 256) {
        int ml = c >> 4;
        int nl = (c & 15) * 4;
        int m = m0 + ml;
        if (m >= M) continue;
        size_t row = (out_map == 1) ? (size_t)((m & 31)*NT + (m >> 5)) : (size_t)m;
        int n = n0 + nl;
        if (n + 3 < N) {
            *(float4*)&C[row*ldc + n] = *(const float4*)&Cs[ml*68 + nl];
        } else {
            for (int j = 0; j < 4; j++)
                if (n + j < N) C[row*ldc + n + j] = Cs[ml*68 + nl + j];
        }
    }
}

// ------------------------- tensor-core persistent encoder -------------------
// g_hbuf carries tf32 BITS (producer-side convert). Per-row load skip:
// frozen batch rows keep their (bit-identical) stale sH content.
#define HPITCH 1028
__global__ void __launch_bounds__(256, 1)
k_enc_persist(const float* __restrict__ Whh, const int* __restrict__ lengths)
{
    extern __shared__ float sm[];
    float* sH = sm;                          // [32][HPITCH] tf32 bits
    float* sZ = sm + 32*HPITCH;              // [8][32][33]

    int tid  = threadIdx.x;
    int lane = tid & 31;
    int warp = tid >> 5;
    int u0   = blockIdx.x * 8;

    uint32_t wf[4][16][2];
    {
        int nr  = lane >> 2;
        int kq  = lane & 3;
        #pragma unroll
        for (int nt = 0; nt < 4; nt++) {
            int n = nt*8 + nr;
            const float* wrow = Whh + (size_t)((n >> 3)*NH + u0 + (n & 7))*NH
                                + warp*128 + kq;
            #pragma unroll
            for (int kt = 0; kt < 16; kt++) {
                wf[nt][kt][0] = f2tf(__ldg(&wrow[kt*8]));
                wf[nt][kt][1] = f2tf(__ldg(&wrow[kt*8 + 4]));
            }
        }
    }

    int cb = tid & 31;
    int cu = tid >> 5;
    int mylen = lengths[cb];
    int len_hi = 0;
    #pragma unroll
    for (int i = 16; i < 32; i++) len_hi = max(len_hi, lengths[i]);
    float creg = 0.0f, hreg = 0.0f;

    g_hbuf[cb*NH + u0 + cu] = 0.0f;          // tf32(0) == 0 bits

    int lr      = tid >> 3;
    int lane8   = tid & 7;
    int loadlen = lengths[lr];               // load row lr while s <= loadlen
    uint32_t sh_base = cvta_s(sH);

    gridbar();

    for (int s = 0; s < NS; s++) {
        const float* hin  = g_hbuf + (s & 1)*(NB*NH);
        float*       hout = g_hbuf + ((s & 1) ^ 1)*(NB*NH);
        bool act_hi = (s < len_hi);

        const float* xp = g_xproj + ((size_t)s*NG + u0 + cu)*32 + cb;
        float xg0 = __ldg(&xp[0]);
        float xg1 = __ldg(&xp[(size_t)NH*32]);
        float xg2 = __ldg(&xp[(size_t)2*NH*32]);
        float xg3 = __ldg(&xp[(size_t)3*NH*32]);

        if (s <= loadlen) {
            const uint4* hr = (const uint4*)(hin + lr*NH);
            #pragma unroll 8
            for (int kk = 0; kk < 32; kk++) {
                uint4 v = __ldcg(&hr[lane8 + 8*kk]);
                *(uint4*)&sH[lr*HPITCH + (lane8 + 8*kk)*4] = v;
            }
        }
        __syncthreads();

        float acc[2][4][4] = {};
        int kbase = warp*128;
        #pragma unroll
        for (int kt = 0; kt < 16; kt++) {
            int kof = kbase + kt*8 + ((lane >> 4) << 2);
            {
                uint32_t a0, a1, a2, a3;
                uint32_t addr = sh_base + (uint32_t)(((lane & 15))*HPITCH + kof)*4;
                ldsm_x4(a0, a1, a2, a3, addr);
                #pragma unroll
                for (int nt = 0; nt < 4; nt++)
                    mma_tf32(acc[0][nt], a0, a1, a2, a3,
                             wf[nt][kt][0], wf[nt][kt][1]);
            }
            if (act_hi) {
                uint32_t a0, a1, a2, a3;
                uint32_t addr = sh_base + (uint32_t)((16 + (lane & 15))*HPITCH + kof)*4;
                ldsm_x4(a0, a1, a2, a3, addr);
                #pragma unroll
                for (int nt = 0; nt < 4; nt++)
                    mma_tf32(acc[1][nt], a0, a1, a2, a3,
                             wf[nt][kt][0], wf[nt][kt][1]);
            }
        }

        {
            float* zw = sZ + warp*(32*33);
            int rr = lane >> 2;
            int cc = (lane & 3)*2;
            #pragma unroll
            for (int mi = 0; mi < 2; mi++) {
                if (mi == 1 && !act_hi) break;
                #pragma unroll
                for (int nt = 0; nt < 4; nt++) {
                    int col = nt*8 + cc;
                    int row = mi*16 + rr;
                    zw[col*33 + row]       = acc[mi][nt][0];
                    zw[(col+1)*33 + row]   = acc[mi][nt][1];
                    zw[col*33 + row + 8]   = acc[mi][nt][2];
                    zw[(col+1)*33 + row+8] = acc[mi][nt][3];
                }
            }
        }
        __syncthreads();

        float zg4[4] = {xg0, xg1, xg2, xg3};
        #pragma unroll
        for (int g = 0; g < 4; g++) {
            int col = g*8 + cu;
            #pragma unroll
            for (int w = 0; w < 8; w++)
                zg4[g] += sZ[w*(32*33) + col*33 + cb];
        }
        float cn = sigmf_(zg4[1])*creg + sigmf_(zg4[0])*tanhf(zg4[2]);
        float hn = sigmf_(zg4[3])*tanhf(cn);
        bool msk = (s < mylen);
        creg = msk ? cn : creg;
        hreg = msk ? hn : hreg;
        ((uint32_t*)hout)[cb*NH + u0 + cu] = f2tf(hreg);   // producer-side cvt
        g_enc_out[((size_t)(s*NB + cb))*NH + u0 + cu] = msk ? hreg : 0.0f;

        gridbar();
    }

    g_h[cb*NH + u0 + cu] = hreg;
    g_c[cb*NH + u0 + cu] = creg;
}

// ------------------------- persistent decoder helpers -----------------------
__device__ __forceinline__ void dec_feat(int tt, const float* __restrict__ hsrc,
    const float* __restrict__ out_W, const float* __restrict__ out_b,
    float* sH, float* sZ, int fn0)
{
    int tid = threadIdx.x;
    int r   = tid >> 6;
    int fks = (tid >> 5) & 1;
    int fb  = tid & 31;
    int lb  = tid >> 3;
    int lq  = tid & 7;
    const float* wrow = out_W + (size_t)(fn0 + r)*(2*NH);
    float fa = 0.f;

    float4 p0, p1, p2, p3;
    {
        const float* hr = hsrc + lb*NH;
        p0 = __ldcg((const float4*)&hr[4*lq]);
        p1 = __ldcg((const float4*)&hr[4*(lq+8)]);
        p2 = __ldcg((const float4*)&hr[4*(lq+16)]);
        p3 = __ldcg((const float4*)&hr[4*(lq+24)]);
        stash4(sH, lq, lb, p0, p1, p2, p3);
    }
    __syncthreads();

    for (int ch = 0; ch < 16; ch++) {
        float* cur = sH + (ch & 1)*(128*36);
        if (ch < 15) {
            int cn_ = ch + 1;
            const float* src = (cn_ < 8) ? hsrc : g_ctx;
            const float* hr = src + lb*NH + (cn_ & 7)*128;
            p0 = __ldcg((const float4*)&hr[4*lq]);
            p1 = __ldcg((const float4*)&hr[4*(lq+8)]);
            p2 = __ldcg((const float4*)&hr[4*(lq+16)]);
            p3 = __ldcg((const float4*)&hr[4*(lq+24)]);
        }
        const float* wc = wrow + ch*128 + fks*64;
        const float* hc = cur + fks*64*36 + fb;
        #pragma unroll 16
        for (int k = 0; k < 64; k++)
            fa += __ldg(&wc[k]) * hc[k*36];
        if (ch < 15)
            stash4(sH + ((ch & 1) ^ 1)*(128*36), lq, lb, p0, p1, p2, p3);
        __syncthreads();
    }
    sZ[(r*2 + fks)*33 + fb] = fa;
    __syncthreads();
    if (tid < 128) {
        int rr = tid >> 5, bb = tid & 31;
        float v = sZ[(rr*2)*33 + bb] + sZ[(rr*2+1)*33 + bb] + __ldg(&out_b[fn0 + rr]);
        g_feat[((size_t)(tt*NB + bb))*ND + fn0 + rr] = v;
    }
    __syncthreads();
}

__device__ __forceinline__ void dec_attn(int b, int mylen,
    const float* __restrict__ hcur,
    const float* __restrict__ ak_W, const float* __restrict__ ak_b,
    float* sW)
{
    int tid = threadIdx.x;
    float* sh_ = sW;
    float* sak = sW + 1024;
    float* se  = sW + 1152;
    float* sr  = sW + 1280;

    for (int i = tid; i < NH; i += 256) sh_[i] = __ldcg(&hcur[b*NH + i]);
    __syncthreads();

    if (tid < NK) {
        const float* wr = ak_W + (size_t)tid*NH;
        float acc0 = 0.f, acc1 = 0.f;
        for (int k = 0; k < NH; k += 8) {
            float4 w0 = *(const float4*)&wr[k];
            float4 w1 = *(const float4*)&wr[k+4];
            float4 h0 = *(const float4*)&sh_[k];
            float4 h1 = *(const float4*)&sh_[k+4];
            acc0 += w0.x*h0.x + w0.y*h0.y + w0.z*h0.z + w0.w*h0.w;
            acc1 += w1.x*h1.x + w1.y*h1.y + w1.z*h1.z + w1.w*h1.w;
        }
        sak[tid] = tanhf(acc0 + acc1 + ak_b[tid]);
    }
    __syncthreads();

    if (tid < NS) {
        const float* qr = g_qkey + ((size_t)(tid*NB + b))*NK;
        float acc = 0.f;
        for (int k = 0; k < NK; k++) acc += qr[k]*sak[k];
        se[tid] = (tid < mylen) ? acc : -INFINITY;
    }
    __syncthreads();

    sr[tid] = (tid < NS) ? se[tid] : -INFINITY;
    __syncthreads();
    for (int off = 128; off >= 1; off >>= 1) {
        if (tid < off) sr[tid] = fmaxf(sr[tid], sr[tid+off]);
        __syncthreads();
    }
    float mx = sr[0];
    __syncthreads();

    float ex = (tid < NS) ? expf(se[tid] - mx) : 0.0f;
    sr[tid] = ex;
    __syncthreads();
    for (int off = 128; off >= 1; off >>= 1) {
        if (tid < off) sr[tid] += sr[tid+off];
        __syncthreads();
    }
    float inv = 1.0f / sr[0];
    __syncthreads();
    if (tid < NS) g_attw[b*NS + tid] = ex * inv;
    __syncthreads();
}

// ------------------------- persistent decoder (tf32 mma z-GEMM) -------------
// SMEM: sA 2x[32][132], sW 2x[32][132], sZ [8][32][33]
#define DPITCH 132
#define DBUF (32*DPITCH)
__global__ void __launch_bounds__(256, 1)
k_dec_persist(const float* __restrict__ dec_Wih, const float* __restrict__ dec_Whh,
              const float* __restrict__ ak_W,   const float* __restrict__ ak_b,
              const float* __restrict__ out_W,  const float* __restrict__ out_b,
              const int* __restrict__ lengths)
{
    extern __shared__ float sm[];
    float* sA  = sm;                    // 2 x DBUF
    float* sWt = sm + 2*DBUF;           // 2 x DBUF
    float* sZd = sm + 4*DBUF;           // [8][32][33] = 8448

    int tid  = threadIdx.x;
    int lane = tid & 31;
    int warp = tid >> 5;
    int blk  = blockIdx.x;
    int u0   = blk * 8;
    int fn0  = blk * 4;

    int cb = tid & 31, cu = tid >> 5;
    float creg = g_c[cb*NH + u0 + cu];

    // loader mapping for z chunks: row r=tid>>3, 4 float4 cols
    int lr  = tid >> 3;
    int lq  = tid & 7;
    int wn_ = (lr >> 3)*NH + u0 + (lr & 7);
    const float* WhhRow = dec_Whh + (size_t)wn_*NH;
    const float* WihRow = dec_Wih + (size_t)wn_*(ND+NH) + ND;

    uint32_t saA0 = cvta_s(sA);
    uint32_t saA1 = cvta_s(sA + DBUF);

    int mylen = (blk < 32) ? lengths[blk] : 0;

    for (int t = 0; t < NT; t++) {
        const float* hcur = (t == 0) ? g_h : (g_hbuf + ((t-1) & 1)*(NB*NH));
        float*       hnew = g_hbuf + (t & 1)*(NB*NH);

        if (t > 0)
            dec_feat(t-1, hcur, out_W, out_b, sm, sm + 4*DBUF, fn0);
        if (blk < 32)
            dec_attn(blk, mylen, hcur, ak_W, ak_b, sm);
        gridbar();

        // ---- context ----
        {
            int b  = blk & 31;
            int hq = blk >> 5;
            if (tid < NS) sZd[tid] = __ldcg(&g_attw[b*NS + tid]);
            __syncthreads();
            int hh = hq*256 + tid;
            float a0 = 0.f, a1 = 0.f, a2 = 0.f, a3 = 0.f;
            #pragma unroll 4
            for (int s = 0; s < NS; s += 4) {
                a0 += sZd[s+0]*__ldg(&g_qval[((size_t)((s+0)*NB + b))*NH + hh]);
                a1 += sZd[s+1]*__ldg(&g_qval[((size_t)((s+1)*NB + b))*NH + hh]);
                a2 += sZd[s+2]*__ldg(&g_qval[((size_t)((s+2)*NB + b))*NH + hh]);
                a3 += sZd[s+3]*__ldg(&g_qval[((size_t)((s+3)*NB + b))*NH + hh]);
            }
            g_ctx[b*NH + hh] = (a0 + a1) + (a2 + a3);
            __syncthreads();
        }
        gridbar();

        const float* xp = g_dxe + ((size_t)t*NG + u0 + cu)*32 + cb;
        float xg0 = __ldg(&xp[0]);
        float xg1 = __ldg(&xp[(size_t)NH*32]);
        float xg2 = __ldg(&xp[(size_t)2*NH*32]);
        float xg3 = __ldg(&xp[(size_t)3*NH*32]);

        // ---- z GEMM via tf32 mma, 16 chunks of 128 k, double-buffered ----
        float acc[2][4][4] = {};
        float4 pA[4], pW[4];

        // prologue: chunk 0 (hcur, Whh)
        {
            const float* ar = hcur + lr*NH;
            #pragma unroll
            for (int p = 0; p < 4; p++) {
                pA[p] = __ldcg((const float4*)&ar[4*(lq + 8*p)]);
                pW[p] = __ldg((const float4*)&WhhRow[4*(lq + 8*p)]);
            }
            #pragma unroll
            for (int p = 0; p < 4; p++) {
                *(float4*)&sA [lr*DPITCH + 4*(lq + 8*p)] = pA[p];
                *(float4*)&sWt[lr*DPITCH + 4*(lq + 8*p)] = pW[p];
            }
        }
        __syncthreads();

        for (int ci = 0; ci < 16; ci++) {
            int cur = ci & 1;
            if (ci < 15) {
                int cn_ = ci + 1;
                int kc  = (cn_ & 7) * 128;
                const float* ar = ((cn_ < 8) ? hcur : g_ctx) + lr*NH + kc;
                const float* wr = ((cn_ < 8) ? WhhRow : WihRow) + kc;
                #pragma unroll
                for (int p = 0; p < 4; p++) {
                    pA[p] = __ldcg((const float4*)&ar[4*(lq + 8*p)]);
                    pW[p] = __ldg((const float4*)&wr[4*(lq + 8*p)]);
                }
            }

            uint32_t saA = cur ? saA1 : saA0;
            const float* Wc = sWt + cur*DBUF;
            #pragma unroll
            for (int k8 = 0; k8 < 2; k8++) {
                int kw = warp*16 + k8*8;
                uint32_t afr[2][4];
                #pragma unroll
                for (int mi = 0; mi < 2; mi++) {
                    uint32_t addr = saA +
                        (uint32_t)((mi*16 + (lane & 15))*DPITCH + kw + ((lane >> 4) << 2))*4;
                    ldsm_x4(afr[mi][0], afr[mi][1], afr[mi][2], afr[mi][3], addr);
                    #pragma unroll
                    for (int q = 0; q < 4; q++)
                        afr[mi][q] = f2tf(__uint_as_float(afr[mi][q]));
                }
                uint32_t bfr[4][2];
                #pragma unroll
                for (int nt = 0; nt < 4; nt++) {
                    const float* wp = Wc + (nt*8 + (lane >> 2))*DPITCH + kw + (lane & 3);
                    bfr[nt][0] = f2tf(wp[0]);
                    bfr[nt][1] = f2tf(wp[4]);
                }
                #pragma unroll
                for (int mi = 0; mi < 2; mi++)
                    #pragma unroll
                    for (int nt = 0; nt < 4; nt++)
                        mma_tf32(acc[mi][nt], afr[mi][0], afr[mi][1], afr[mi][2],
                                 afr[mi][3], bfr[nt][0], bfr[nt][1]);
            }

            if (ci < 15) {
                float* dA = sA  + (cur ^ 1)*DBUF;
                float* dW = sWt + (cur ^ 1)*DBUF;
                #pragma unroll
                for (int p = 0; p < 4; p++) {
                    *(float4*)&dA[lr*DPITCH + 4*(lq + 8*p)] = pA[p];
                    *(float4*)&dW[lr*DPITCH + 4*(lq + 8*p)] = pW[p];
                }
            }
            __syncthreads();
        }

        // write partials: sZd[warp][n][b], pitch 33
        {
            float* zw = sZd + warp*(32*33);
            int rr = lane >> 2;
            int cc = (lane & 3)*2;
            #pragma unroll
            for (int mi = 0; mi < 2; mi++)
                #pragma unroll
                for (int nt = 0; nt < 4; nt++) {
                    int col = nt*8 + cc;
                    int row = mi*16 + rr;
                    zw[col*33 + row]       = acc[mi][nt][0];
                    zw[(col+1)*33 + row]   = acc[mi][nt][1];
                    zw[col*33 + row + 8]   = acc[mi][nt][2];
                    zw[(col+1)*33 + row+8] = acc[mi][nt][3];
                }
        }
        __syncthreads();

        {
            float zg4[4] = {xg0, xg1, xg2, xg3};
            #pragma unroll
            for (int g = 0; g < 4; g++) {
                int col = g*8 + cu;
                #pragma unroll
                for (int w = 0; w < 8; w++)
                    zg4[g] += sZd[w*(32*33) + col*33 + cb];
            }
            float cn = sigmf_(zg4[1])*creg + sigmf_(zg4[0])*tanhf(zg4[2]);
            float hn = sigmf_(zg4[3])*tanhf(cn);
            creg = cn;
            hnew[cb*NH + u0 + cu] = hn;
        }
        __syncthreads();
        gridbar();
    }

    {
        const float* hlast = g_hbuf + ((NT-1) & 1)*(NB*NH);
        dec_feat(NT-1, hlast, out_W, out_b, sm, sm + 4*DBUF, fn0);
    }
}

// =============================================================================
extern "C" void kernel_launch(void* const* d_in, const int* in_sizes, int n_in,
                              void* d_out, int out_size)
{
    const float* embed    = (const float*)d_in[0];
    const float* enc_Wih  = (const float*)d_in[1];
    const float* enc_Whh  = (const float*)d_in[2];
    const float* enc_bih  = (const float*)d_in[3];
    const float* enc_bhh  = (const float*)d_in[4];
    const float* dec_Wih  = (const float*)d_in[5];
    const float* dec_Whh  = (const float*)d_in[6];
    const float* dec_bih  = (const float*)d_in[7];
    const float* dec_bhh  = (const float*)d_in[8];
    const float* qk_W     = (const float*)d_in[9];
    const float* qk_b     = (const float*)d_in[10];
    const float* qv_W     = (const float*)d_in[11];
    const float* qv_b     = (const float*)d_in[12];
    const float* ak_W     = (const float*)d_in[13];
    const float* ak_b     = (const float*)d_in[14];
    const float* out_W    = (const float*)d_in[15];
    const float* out_b    = (const float*)d_in[16];
    const float* wd_b     = (const float*)d_in[17];
    const float* hfc1_W   = (const float*)d_in[18];
    const float* hfc1_b   = (const float*)d_in[19];
    const float* hfc2_W   = (const float*)d_in[20];
    const float* hfc2_b   = (const float*)d_in[21];
    const float* cfc1_W   = (const float*)d_in[22];
    const float* cfc1_b   = (const float*)d_in[23];
    const float* cfc2_W   = (const float*)d_in[24];
    const float* cfc2_b   = (const float*)d_in[25];
    const int*   src_seqs = (const int*)d_in[26];
    const int*   src_len  = (const int*)d_in[27];
    const int*   trg_seqs = (const int*)d_in[28];
    float* out = (float*)d_out;

    float *d_src_embed, *d_ans_embed, *d_xproj, *d_dxe, *d_h, *d_c;
    float *d_enc_out, *d_qkey, *d_qval, *d_tmp, *d_feat;
    cudaGetSymbolAddress((void**)&d_src_embed, g_src_embed);
    cudaGetSymbolAddress((void**)&d_ans_embed, g_ans_embed);
    cudaGetSymbolAddress((void**)&d_xproj,     g_xproj);
    cudaGetSymbolAddress((void**)&d_dxe,       g_dxe);
    cudaGetSymbolAddress((void**)&d_h,         g_h);
    cudaGetSymbolAddress((void**)&d_c,         g_c);
    cudaGetSymbolAddress((void**)&d_enc_out,   g_enc_out);
    cudaGetSymbolAddress((void**)&d_qkey,      g_qkey);
    cudaGetSymbolAddress((void**)&d_qval,      g_qval);
    cudaGetSymbolAddress((void**)&d_tmp,       g_tmp);
    cudaGetSymbolAddress((void**)&d_feat,      g_feat);

    cudaFuncSetAttribute(k_sgemm,
                         cudaFuncAttributeMaxDynamicSharedMemorySize, SGSMEM);

    // ---- precompute ----
    k_gather<<<NS*NB, 128>>>(src_seqs, NS, embed, d_src_embed);
    k_gather<<<NT*NB, 128>>>(trg_seqs, 20, embed, d_ans_embed);

    k_sgemm<<<dim3(NG/64, (NS*NB)/128), 256, SGSMEM>>>(NS*NB, NG, ND,
        d_src_embed, ND, enc_Wih, ND, enc_bih, enc_bhh, d_xproj, NG, 0, 2, 0);
    k_sgemm<<<dim3(NG/64, (NT*NB + 127)/128), 256, SGSMEM>>>(NT*NB, NG, ND,
        d_ans_embed, ND, dec_Wih, ND + NH, dec_bih, dec_bhh, d_dxe, NG, 0, 2, 0);

    // ---- encoder recurrence ----
    const int enc_smem = (32*HPITCH + 8*32*33) * (int)sizeof(float);
    cudaFuncSetAttribute(k_enc_persist,
                         cudaFuncAttributeMaxDynamicSharedMemorySize, enc_smem);
    k_enc_persist<<<NBLK, 256, enc_smem>>>(enc_Whh, src_len);

    // ---- bridge MLPs ----
    k_sgemm<<<dim3(2048/64, 1), 256, SGSMEM>>>(NB, 2048, NH, d_h, NH, hfc1_W, NH,
                                       hfc1_b, nullptr, d_tmp, 2048, 2, 0, 0);
    k_sgemm<<<dim3(NH/64, 1), 256, SGSMEM>>>(NB, NH, 2048, d_tmp, 2048, hfc2_W, 2048,
                                     hfc2_b, nullptr, d_h, NH, 0, 0, 0);
    k_sgemm<<<dim3(2048/64, 1), 256, SGSMEM>>>(NB, 2048, NH, d_c, NH, cfc1_W, NH,
                                       cfc1_b, nullptr, d_tmp, 2048, 2, 0, 0);
    k_sgemm<<<dim3(NH/64, 1), 256, SGSMEM>>>(NB, NH, 2048, d_tmp, 2048, cfc2_W, 2048,
                                     cfc2_b, nullptr, d_c, NH, 0, 0, 0);

    // ---- attention precompute ----
    k_sgemm<<<dim3((NK + 63)/64, (NS*NB)/128), 256, SGSMEM>>>(NS*NB, NK, NH,
        d_enc_out, NH, qk_W, NH, qk_b, nullptr, d_qkey, NK, 1, 0, 0);
    k_sgemm<<<dim3(NH/64, (NS*NB)/128), 256, SGSMEM>>>(NS*NB, NH, NH,
        d_enc_out, NH, qv_W, NH, qv_b, nullptr, d_qval, NH, 0, 0, 0);

    // ---- decoder recurrence ----
    const int dec_smem = (4*DBUF + 8*32*33) * (int)sizeof(float);
    cudaFuncSetAttribute(k_dec_persist,
                         cudaFuncAttributeMaxDynamicSharedMemorySize, dec_smem);
    k_dec_persist<<<NBLK, 256, dec_smem>>>(dec_Wih, dec_Whh, ak_W, ak_b,
                                           out_W, out_b, src_len);

    // ---- final logits ----
    k_sgemm<<<dim3((NT*NB + 127)/128, NV/64), 256, SGSMEM>>>(NT*NB, NV, ND,
        d_feat, ND, embed, ND, wd_b, nullptr, out, NV, 0, 1, 1);

    (void)in_sizes; (void)n_in; (void)out_size;
}

// round 13
// speedup vs baseline: 1.2144x; 1.0058x over previous
#include <cuda_runtime.h>
#include <math.h>
#include <stdint.h>

// Problem dims (fixed by the dataset)
#define NB 32      // batch
#define NS 128     // src seq len
#define NT 19      // decoder steps (T-1)
#define ND 512     // embed dim
#define NH 1024    // hidden
#define NG 4096    // 4*H
#define NK 100     // attn key dim
#define NV 32000   // vocab
#define NBLK 128

typedef unsigned long long ull_t;

// ------------------------- scratch (device globals; no allocs) ---------------
__device__ float g_src_embed[NS*NB*ND];
__device__ float g_ans_embed[NT*NB*ND];
__device__ float g_xproj[NS*NG*NB];         // [s][n][b]
__device__ float g_dxe[NT*NG*NB];           // [t][n][b]
__device__ float g_h[NB*NH];
__device__ float g_c[NB*NH];
__device__ float g_hbuf[2*NB*NH];           // enc: tf32 bits; dec: fp32
__device__ float g_enc_out[NS*NB*NH];
__device__ float g_qkey[NS*NB*NK];
__device__ float g_qval[NS*NB*NH];
__device__ float g_tmp[NB*2048];
__device__ float g_ctx[NB*NH];
__device__ float g_attw[NB*NS];
__device__ float g_feat[NT*NB*ND];

__device__ unsigned g_barcnt = 0;
__device__ unsigned g_bargen = 0;

__device__ __forceinline__ float sigmf_(float x) { return 1.0f/(1.0f+expf(-x)); }

// ---- tf32 tensor-core helpers ----
__device__ __forceinline__ uint32_t f2tf(float x)
{
    uint32_t r;
    asm("cvt.rna.tf32.f32 %0, %1;" : "=r"(r) : "f"(x));
    return r;
}
__device__ __forceinline__ uint32_t cvta_s(const void* p)
{
    uint32_t a;
    asm("{ .reg .u64 t; cvta.to.shared.u64 t, %1; cvt.u32.u64 %0, t; }"
        : "=r"(a) : "l"(p));
    return a;
}
__device__ __forceinline__ void ldsm_x4(uint32_t& r0, uint32_t& r1,
                                        uint32_t& r2, uint32_t& r3, uint32_t addr)
{
    asm volatile("ldmatrix.sync.aligned.m8n8.x4.b16 {%0,%1,%2,%3}, [%4];"
                 : "=r"(r0), "=r"(r1), "=r"(r2), "=r"(r3) : "r"(addr));
}
__device__ __forceinline__ void mma_tf32(float* d, uint32_t a0, uint32_t a1,
                                         uint32_t a2, uint32_t a3,
                                         uint32_t b0, uint32_t b1)
{
    asm volatile(
        "mma.sync.aligned.m16n8k8.row.col.f32.tf32.tf32.f32 "
        "{%0,%1,%2,%3}, {%4,%5,%6,%7}, {%8,%9}, {%0,%1,%2,%3};"
        : "+f"(d[0]), "+f"(d[1]), "+f"(d[2]), "+f"(d[3])
        : "r"(a0), "r"(a1), "r"(a2), "r"(a3), "r"(b0), "r"(b1));
}

// ---- cp.async (16B, zero-fill when vbytes==0) ----
__device__ __forceinline__ void cpasync16(uint32_t dst, const void* src, int vbytes)
{
    asm volatile("cp.async.cg.shared.global [%0], [%1], 16, %2;"
                 :: "r"(dst), "l"(src), "r"(vbytes));
}
__device__ __forceinline__ void cp_commit()
{
    asm volatile("cp.async.commit_group;");
}
__device__ __forceinline__ void cp_wait1()
{
    asm volatile("cp.async.wait_group 1;");
}

// single-counter grid barrier
__device__ __forceinline__ void gridbar()
{
    __syncthreads();
    if (threadIdx.x == 0) {
        __threadfence();
        volatile unsigned* vgen = &g_bargen;
        unsigned gen = *vgen;
        if (atomicAdd(&g_barcnt, 1u) == NBLK - 1) {
            g_barcnt = 0;
            __threadfence();
            atomicAdd(&g_bargen, 1u);
        } else {
            while (*vgen == gen) { __nanosleep(16); }
        }
        __threadfence();
    }
    __syncthreads();
}

// helper: scatter 4 prefetched float4s (rows kk=4*(lq+8p)) into tile[k][row]
__device__ __forceinline__ void stash4(float* buf, int lq, int row,
                                       float4 p0, float4 p1, float4 p2, float4 p3)
{
    buf[(4*lq+0)*36+row]=p0.x; buf[(4*lq+1)*36+row]=p0.y;
    buf[(4*lq+2)*36+row]=p0.z; buf[(4*lq+3)*36+row]=p0.w;
    buf[(4*(lq+8)+0)*36+row]=p1.x; buf[(4*(lq+8)+1)*36+row]=p1.y;
    buf[(4*(lq+8)+2)*36+row]=p1.z; buf[(4*(lq+8)+3)*36+row]=p1.w;
    buf[(4*(lq+16)+0)*36+row]=p2.x; buf[(4*(lq+16)+1)*36+row]=p2.y;
    buf[(4*(lq+16)+2)*36+row]=p2.z; buf[(4*(lq+16)+3)*36+row]=p2.w;
    buf[(4*(lq+24)+0)*36+row]=p3.x; buf[(4*(lq+24)+1)*36+row]=p3.y;
    buf[(4*(lq+24)+2)*36+row]=p3.z; buf[(4*(lq+24)+3)*36+row]=p3.w;
}

// ------------------------- embedding gather ---------------------------------
__global__ void k_gather(const int* __restrict__ seq, int seq_stride,
                         const float* __restrict__ embed, float* __restrict__ out)
{
    int row = blockIdx.x;
    int st  = row / NB;
    int b   = row % NB;
    int tok = seq[b*seq_stride + st];
    const float4* src = (const float4*)(embed + (size_t)tok*ND);
    float4*       dst = (float4*)(out + (size_t)row*ND);
    dst[threadIdx.x] = src[threadIdx.x];
}

// ------------------------- tf32 tensor-core GEMM (cp.async 3-stage) ----------
// 3 stages -> 46KB smem -> 4 blocks/SM; latency hidden by block parallelism.
#define SGSTG 3840          // stage stride in u32 (As 2560 + Ws 1280)
#define SGSMEM (3*SGSTG*4)  // 46080 bytes
__global__ __launch_bounds__(256)
void k_sgemm(int M, int N, int K,
             const float* __restrict__ A, int lda,
             const float* __restrict__ W, int ldw,
             const float* __restrict__ bias1, const float* __restrict__ bias2,
             float* __restrict__ C, int ldc, int act, int out_map, int swap_grid)
{
    extern __shared__ __align__(16) uint32_t smem_u[];   // 3 stages
    float* Cs = (float*)smem_u;                          // [128][68] reuse at end

    int tid  = threadIdx.x;
    int lane = tid & 31;
    int warp = tid >> 5;
    int wm   = warp & 3;
    int wn   = warp >> 2;
    int m0, n0;
    if (swap_grid) { m0 = blockIdx.x*128; n0 = blockIdx.y*64; }
    else           { m0 = blockIdx.y*128; n0 = blockIdx.x*64; }

    int ra = tid >> 2;
    int kc = (tid & 3) * 4;

    bool a0v = (m0 + ra < M);
    bool a1v = (m0 + ra + 64 < M);
    bool wv_ = (n0 + ra < N) && (ra < 64);
    const float* Arow0 = A + (size_t)(a0v ? (m0+ra)    : 0)*lda + kc;
    const float* Arow1 = A + (size_t)(a1v ? (m0+ra+64) : 0)*lda + kc;
    const float* Wrow  = W + (size_t)(wv_ ? (n0+ra)    : 0)*ldw + kc;
    int az0 = a0v ? 16 : 0, az1 = a1v ? 16 : 0, wz = wv_ ? 16 : 0;

    uint32_t sbase[3];
    #pragma unroll
    for (int s = 0; s < 3; s++) sbase[s] = cvta_s(smem_u + s*SGSTG);
    uint32_t a0off = (uint32_t)(ra*20 + kc)*4;
    uint32_t a1off = (uint32_t)((ra+64)*20 + kc)*4;
    uint32_t woff  = (uint32_t)(2560 + ra*20 + kc)*4;

    uint32_t ws_row = (uint32_t)(wn*32 + (lane >> 2))*20 + (lane & 3);
    float acc[2][4][4] = {};
    int nit = K >> 4;

    // prologue: stages 0..1
    #pragma unroll
    for (int s = 0; s < 2; s++) {
        int k0 = s << 4;
        uint32_t b = sbase[s];
        cpasync16(b + a0off, Arow0 + k0, az0);
        cpasync16(b + a1off, Arow1 + k0, az1);
        if (ra < 64) cpasync16(b + woff, Wrow + k0, wz);
        cp_commit();
    }

    int sidx = 0;                 // stage index of iteration it (mod 3)
    for (int it = 0; it < nit; it++) {
        cp_wait1();
        __syncthreads();

        int snx = sidx + 2; if (snx >= 3) snx -= 3;   // (it+2)%3
        if (it + 2 < nit) {
            int k0 = (it + 2) << 4;
            uint32_t b = sbase[snx];
            cpasync16(b + a0off, Arow0 + k0, az0);
            cpasync16(b + a1off, Arow1 + k0, az1);
            if (ra < 64) cpasync16(b + woff, Wrow + k0, wz);
        }
        cp_commit();

        uint32_t as_base = sbase[sidx];
        const float* WsF = (const float*)(smem_u + sidx*SGSTG + 2560);
        #pragma unroll
        for (int ks = 0; ks < 16; ks += 8) {
            uint32_t afr[2][4];
            #pragma unroll
            for (int mi = 0; mi < 2; mi++) {
                uint32_t row = (uint32_t)(wm*32 + mi*16 + (lane & 15));
                uint32_t kof = (uint32_t)(ks + ((lane >> 4) << 2));
                uint32_t addr = as_base + (row*20 + kof)*4;
                ldsm_x4(afr[mi][0], afr[mi][1], afr[mi][2], afr[mi][3], addr);
                #pragma unroll
                for (int q = 0; q < 4; q++)
                    afr[mi][q] = f2tf(__uint_as_float(afr[mi][q]));
            }
            uint32_t bfr[4][2];
            #pragma unroll
            for (int j = 0; j < 4; j++) {
                bfr[j][0] = f2tf(WsF[ws_row + (uint32_t)(j*8)*20 + ks]);
                bfr[j][1] = f2tf(WsF[ws_row + (uint32_t)(j*8)*20 + ks + 4]);
            }
            #pragma unroll
            for (int mi = 0; mi < 2; mi++)
                #pragma unroll
                for (int j = 0; j < 4; j++)
                    mma_tf32(acc[mi][j], afr[mi][0], afr[mi][1], afr[mi][2],
                             afr[mi][3], bfr[j][0], bfr[j][1]);
        }
        sidx++; if (sidx >= 3) sidx = 0;
    }
    __syncthreads();

    #pragma unroll
    for (int mi = 0; mi < 2; mi++) {
        int ml0 = wm*32 + mi*16 + (lane >> 2);
        #pragma unroll
        for (int j = 0; j < 4; j++) {
            int nl = wn*32 + j*8 + (lane & 3)*2;
            float b0v = 0.f, b1v = 0.f;
            if (n0 + nl < N) {
                b0v = bias1[n0+nl];
                if (bias2) b0v += bias2[n0+nl];
            }
            if (n0 + nl + 1 < N) {
                b1v = bias1[n0+nl+1];
                if (bias2) b1v += bias2[n0+nl+1];
            }
            float v0 = acc[mi][j][0] + b0v;
            float v1 = acc[mi][j][1] + b1v;
            float v2 = acc[mi][j][2] + b0v;
            float v3 = acc[mi][j][3] + b1v;
            if (act == 1) { v0=tanhf(v0); v1=tanhf(v1); v2=tanhf(v2); v3=tanhf(v3); }
            else if (act == 2) { v0=fmaxf(v0,0.f); v1=fmaxf(v1,0.f);
                                 v2=fmaxf(v2,0.f); v3=fmaxf(v3,0.f); }
            Cs[ml0*68 + nl]       = v0;
            Cs[ml0*68 + nl + 1]   = v1;
            Cs[(ml0+8)*68 + nl]   = v2;
            Cs[(ml0+8)*68 + nl+1] = v3;
        }
    }
    __syncthreads();

    if (out_map == 2) {
        for (int c = tid; c < 2048; c += 256) {
            int qb = (c & 7) * 4;
            int nl = (c >> 3) & 63;
            int sh = c >> 9;
            int mgrp = m0 + sh*32;
            if (mgrp >= M) continue;
            float4 v4 = make_float4(Cs[(sh*32+qb+0)*68 + nl],
                                    Cs[(sh*32+qb+1)*68 + nl],
                                    Cs[(sh*32+qb+2)*68 + nl],
                                    Cs[(sh*32+qb+3)*68 + nl]);
            *(float4*)&C[((size_t)(mgrp >> 5)*NG + n0 + nl)*32 + qb] = v4;
        }
        return;
    }

    for (int c = tid; c < 2048; c += 256) {
        int ml = c >> 4;
        int nl = (c & 15) * 4;
        int m = m0 + ml;
        if (m >= M) continue;
        size_t row = (out_map == 1) ? (size_t)((m & 31)*NT + (m >> 5)) : (size_t)m;
        int n = n0 + nl;
        if (n + 3 < N) {
            *(float4*)&C[row*ldc + n] = *(const float4*)&Cs[ml*68 + nl];
        } else {
            for (int j = 0; j < 4; j++)
                if (n + j < N) C[row*ldc + n + j] = Cs[ml*68 + nl + j];
        }
    }
}

// ------------------------- tensor-core persistent encoder -------------------
#define HPITCH 1028
__global__ void __launch_bounds__(256, 1)
k_enc_persist(const float* __restrict__ Whh, const int* __restrict__ lengths)
{
    extern __shared__ float sm[];
    float* sH = sm;                          // [32][HPITCH] tf32 bits
    float* sZ = sm + 32*HPITCH;              // [8][32][33]

    int tid  = threadIdx.x;
    int lane = tid & 31;
    int warp = tid >> 5;
    int u0   = blockIdx.x * 8;

    uint32_t wf[4][16][2];
    {
        int nr  = lane >> 2;
        int kq  = lane & 3;
        #pragma unroll
        for (int nt = 0; nt < 4; nt++) {
            int n = nt*8 + nr;
            const float* wrow = Whh + (size_t)((n >> 3)*NH + u0 + (n & 7))*NH
                                + warp*128 + kq;
            #pragma unroll
            for (int kt = 0; kt < 16; kt++) {
                wf[nt][kt][0] = f2tf(__ldg(&wrow[kt*8]));
                wf[nt][kt][1] = f2tf(__ldg(&wrow[kt*8 + 4]));
            }
        }
    }

    int cb = tid & 31;
    int cu = tid >> 5;
    int mylen = lengths[cb];
    int len_hi = 0;
    #pragma unroll
    for (int i = 16; i < 32; i++) len_hi = max(len_hi, lengths[i]);
    float creg = 0.0f, hreg = 0.0f;

    g_hbuf[cb*NH + u0 + cu] = 0.0f;          // tf32(0) == 0 bits

    int lr      = tid >> 3;
    int lane8   = tid & 7;
    int loadlen = lengths[lr];               // load row lr while s <= loadlen
    uint32_t sh_base = cvta_s(sH);

    gridbar();

    for (int s = 0; s < NS; s++) {
        const float* hin  = g_hbuf + (s & 1)*(NB*NH);
        float*       hout = g_hbuf + ((s & 1) ^ 1)*(NB*NH);
        bool act_hi = (s < len_hi);

        const float* xp = g_xproj + ((size_t)s*NG + u0 + cu)*32 + cb;
        float xg0 = __ldg(&xp[0]);
        float xg1 = __ldg(&xp[(size_t)NH*32]);
        float xg2 = __ldg(&xp[(size_t)2*NH*32]);
        float xg3 = __ldg(&xp[(size_t)3*NH*32]);

        if (s <= loadlen) {
            const uint4* hr = (const uint4*)(hin + lr*NH);
            #pragma unroll 8
            for (int kk = 0; kk < 32; kk++) {
                uint4 v = __ldcg(&hr[lane8 + 8*kk]);
                *(uint4*)&sH[lr*HPITCH + (lane8 + 8*kk)*4] = v;
            }
        }
        __syncthreads();

        float acc[2][4][4] = {};
        int kbase = warp*128;
        #pragma unroll
        for (int kt = 0; kt < 16; kt++) {
            int kof = kbase + kt*8 + ((lane >> 4) << 2);
            {
                uint32_t a0, a1, a2, a3;
                uint32_t addr = sh_base + (uint32_t)(((lane & 15))*HPITCH + kof)*4;
                ldsm_x4(a0, a1, a2, a3, addr);
                #pragma unroll
                for (int nt = 0; nt < 4; nt++)
                    mma_tf32(acc[0][nt], a0, a1, a2, a3,
                             wf[nt][kt][0], wf[nt][kt][1]);
            }
            if (act_hi) {
                uint32_t a0, a1, a2, a3;
                uint32_t addr = sh_base + (uint32_t)((16 + (lane & 15))*HPITCH + kof)*4;
                ldsm_x4(a0, a1, a2, a3, addr);
                #pragma unroll
                for (int nt = 0; nt < 4; nt++)
                    mma_tf32(acc[1][nt], a0, a1, a2, a3,
                             wf[nt][kt][0], wf[nt][kt][1]);
            }
        }

        {
            float* zw = sZ + warp*(32*33);
            int rr = lane >> 2;
            int cc = (lane & 3)*2;
            #pragma unroll
            for (int mi = 0; mi < 2; mi++) {
                if (mi == 1 && !act_hi) break;
                #pragma unroll
                for (int nt = 0; nt < 4; nt++) {
                    int col = nt*8 + cc;
                    int row = mi*16 + rr;
                    zw[col*33 + row]       = acc[mi][nt][0];
                    zw[(col+1)*33 + row]   = acc[mi][nt][1];
                    zw[col*33 + row + 8]   = acc[mi][nt][2];
                    zw[(col+1)*33 + row+8] = acc[mi][nt][3];
                }
            }
        }
        __syncthreads();

        float zg4[4] = {xg0, xg1, xg2, xg3};
        #pragma unroll
        for (int g = 0; g < 4; g++) {
            int col = g*8 + cu;
            #pragma unroll
            for (int w = 0; w < 8; w++)
                zg4[g] += sZ[w*(32*33) + col*33 + cb];
        }
        float cn = sigmf_(zg4[1])*creg + sigmf_(zg4[0])*tanhf(zg4[2]);
        float hn = sigmf_(zg4[3])*tanhf(cn);
        bool msk = (s < mylen);
        creg = msk ? cn : creg;
        hreg = msk ? hn : hreg;
        ((uint32_t*)hout)[cb*NH + u0 + cu] = f2tf(hreg);   // producer-side cvt
        g_enc_out[((size_t)(s*NB + cb))*NH + u0 + cu] = msk ? hreg : 0.0f;

        gridbar();
    }

    g_h[cb*NH + u0 + cu] = hreg;
    g_c[cb*NH + u0 + cu] = creg;
}

// ------------------------- persistent decoder helpers -----------------------
__device__ __forceinline__ void dec_feat(int tt, const float* __restrict__ hsrc,
    const float* __restrict__ out_W, const float* __restrict__ out_b,
    float* sH, float* sZ, int fn0)
{
    int tid = threadIdx.x;
    int r   = tid >> 6;
    int fks = (tid >> 5) & 1;
    int fb  = tid & 31;
    int lb  = tid >> 3;
    int lq  = tid & 7;
    const float* wrow = out_W + (size_t)(fn0 + r)*(2*NH);
    float fa = 0.f;

    float4 p0, p1, p2, p3;
    {
        const float* hr = hsrc + lb*NH;
        p0 = __ldcg((const float4*)&hr[4*lq]);
        p1 = __ldcg((const float4*)&hr[4*(lq+8)]);
        p2 = __ldcg((const float4*)&hr[4*(lq+16)]);
        p3 = __ldcg((const float4*)&hr[4*(lq+24)]);
        stash4(sH, lq, lb, p0, p1, p2, p3);
    }
    __syncthreads();

    for (int ch = 0; ch < 16; ch++) {
        float* cur = sH + (ch & 1)*(128*36);
        if (ch < 15) {
            int cn_ = ch + 1;
            const float* src = (cn_ < 8) ? hsrc : g_ctx;
            const float* hr = src + lb*NH + (cn_ & 7)*128;
            p0 = __ldcg((const float4*)&hr[4*lq]);
            p1 = __ldcg((const float4*)&hr[4*(lq+8)]);
            p2 = __ldcg((const float4*)&hr[4*(lq+16)]);
            p3 = __ldcg((const float4*)&hr[4*(lq+24)]);
        }
        const float* wc = wrow + ch*128 + fks*64;
        const float* hc = cur + fks*64*36 + fb;
        #pragma unroll 16
        for (int k = 0; k < 64; k++)
            fa += __ldg(&wc[k]) * hc[k*36];
        if (ch < 15)
            stash4(sH + ((ch & 1) ^ 1)*(128*36), lq, lb, p0, p1, p2, p3);
        __syncthreads();
    }
    sZ[(r*2 + fks)*33 + fb] = fa;
    __syncthreads();
    if (tid < 128) {
        int rr = tid >> 5, bb = tid & 31;
        float v = sZ[(rr*2)*33 + bb] + sZ[(rr*2+1)*33 + bb] + __ldg(&out_b[fn0 + rr]);
        g_feat[((size_t)(tt*NB + bb))*ND + fn0 + rr] = v;
    }
    __syncthreads();
}

__device__ __forceinline__ void dec_attn(int b, int mylen,
    const float* __restrict__ hcur,
    const float* __restrict__ ak_W, const float* __restrict__ ak_b,
    float* sW)
{
    int tid = threadIdx.x;
    float* sh_ = sW;
    float* sak = sW + 1024;
    float* se  = sW + 1152;
    float* sr  = sW + 1280;

    for (int i = tid; i < NH; i += 256) sh_[i] = __ldcg(&hcur[b*NH + i]);
    __syncthreads();

    if (tid < NK) {
        const float* wr = ak_W + (size_t)tid*NH;
        float acc0 = 0.f, acc1 = 0.f;
        for (int k = 0; k < NH; k += 8) {
            float4 w0 = *(const float4*)&wr[k];
            float4 w1 = *(const float4*)&wr[k+4];
            float4 h0 = *(const float4*)&sh_[k];
            float4 h1 = *(const float4*)&sh_[k+4];
            acc0 += w0.x*h0.x + w0.y*h0.y + w0.z*h0.z + w0.w*h0.w;
            acc1 += w1.x*h1.x + w1.y*h1.y + w1.z*h1.z + w1.w*h1.w;
        }
        sak[tid] = tanhf(acc0 + acc1 + ak_b[tid]);
    }
    __syncthreads();

    if (tid < NS) {
        const float* qr = g_qkey + ((size_t)(tid*NB + b))*NK;
        float acc = 0.f;
        for (int k = 0; k < NK; k++) acc += qr[k]*sak[k];
        se[tid] = (tid < mylen) ? acc : -INFINITY;
    }
    __syncthreads();

    sr[tid] = (tid < NS) ? se[tid] : -INFINITY;
    __syncthreads();
    for (int off = 128; off >= 1; off >>= 1) {
        if (tid < off) sr[tid] = fmaxf(sr[tid], sr[tid+off]);
        __syncthreads();
    }
    float mx = sr[0];
    __syncthreads();

    float ex = (tid < NS) ? expf(se[tid] - mx) : 0.0f;
    sr[tid] = ex;
    __syncthreads();
    for (int off = 128; off >= 1; off >>= 1) {
        if (tid < off) sr[tid] += sr[tid+off];
        __syncthreads();
    }
    float inv = 1.0f / sr[0];
    __syncthreads();
    if (tid < NS) g_attw[b*NS + tid] = ex * inv;
    __syncthreads();
}

// ------------------------- persistent decoder (tf32 mma z-GEMM) -------------
#define DPITCH 132
#define DBUF (32*DPITCH)
__global__ void __launch_bounds__(256, 1)
k_dec_persist(const float* __restrict__ dec_Wih, const float* __restrict__ dec_Whh,
              const float* __restrict__ ak_W,   const float* __restrict__ ak_b,
              const float* __restrict__ out_W,  const float* __restrict__ out_b,
              const int* __restrict__ lengths)
{
    extern __shared__ float sm[];
    float* sA  = sm;                    // 2 x DBUF
    float* sWt = sm + 2*DBUF;           // 2 x DBUF
    float* sZd = sm + 4*DBUF;           // [8][32][33] = 8448

    int tid  = threadIdx.x;
    int lane = tid & 31;
    int warp = tid >> 5;
    int blk  = blockIdx.x;
    int u0   = blk * 8;
    int fn0  = blk * 4;

    int cb = tid & 31, cu = tid >> 5;
    float creg = g_c[cb*NH + u0 + cu];

    int lr  = tid >> 3;
    int lq  = tid & 7;
    int wn_ = (lr >> 3)*NH + u0 + (lr & 7);
    const float* WhhRow = dec_Whh + (size_t)wn_*NH;
    const float* WihRow = dec_Wih + (size_t)wn_*(ND+NH) + ND;

    uint32_t saA0 = cvta_s(sA);
    uint32_t saA1 = cvta_s(sA + DBUF);

    int mylen = (blk < 32) ? lengths[blk] : 0;

    for (int t = 0; t < NT; t++) {
        const float* hcur = (t == 0) ? g_h : (g_hbuf + ((t-1) & 1)*(NB*NH));
        float*       hnew = g_hbuf + (t & 1)*(NB*NH);

        if (t > 0)
            dec_feat(t-1, hcur, out_W, out_b, sm, sm + 4*DBUF, fn0);
        if (blk < 32)
            dec_attn(blk, mylen, hcur, ak_W, ak_b, sm);
        gridbar();

        // ---- context ----
        {
            int b  = blk & 31;
            int hq = blk >> 5;
            if (tid < NS) sZd[tid] = __ldcg(&g_attw[b*NS + tid]);
            __syncthreads();
            int hh = hq*256 + tid;
            float a0 = 0.f, a1 = 0.f, a2 = 0.f, a3 = 0.f;
            #pragma unroll 4
            for (int s = 0; s < NS; s += 4) {
                a0 += sZd[s+0]*__ldg(&g_qval[((size_t)((s+0)*NB + b))*NH + hh]);
                a1 += sZd[s+1]*__ldg(&g_qval[((size_t)((s+1)*NB + b))*NH + hh]);
                a2 += sZd[s+2]*__ldg(&g_qval[((size_t)((s+2)*NB + b))*NH + hh]);
                a3 += sZd[s+3]*__ldg(&g_qval[((size_t)((s+3)*NB + b))*NH + hh]);
            }
            g_ctx[b*NH + hh] = (a0 + a1) + (a2 + a3);
            __syncthreads();
        }
        gridbar();

        const float* xp = g_dxe + ((size_t)t*NG + u0 + cu)*32 + cb;
        float xg0 = __ldg(&xp[0]);
        float xg1 = __ldg(&xp[(size_t)NH*32]);
        float xg2 = __ldg(&xp[(size_t)2*NH*32]);
        float xg3 = __ldg(&xp[(size_t)3*NH*32]);

        // ---- z GEMM via tf32 mma, 16 chunks of 128 k, double-buffered ----
        float acc[2][4][4] = {};
        float4 pA[4], pW[4];
        {
            const float* ar = hcur + lr*NH;
            #pragma unroll
            for (int p = 0; p < 4; p++) {
                pA[p] = __ldcg((const float4*)&ar[4*(lq + 8*p)]);
                pW[p] = __ldg((const float4*)&WhhRow[4*(lq + 8*p)]);
            }
            #pragma unroll
            for (int p = 0; p < 4; p++) {
                *(float4*)&sA [lr*DPITCH + 4*(lq + 8*p)] = pA[p];
                *(float4*)&sWt[lr*DPITCH + 4*(lq + 8*p)] = pW[p];
            }
        }
        __syncthreads();

        for (int ci = 0; ci < 16; ci++) {
            int cur = ci & 1;
            if (ci < 15) {
                int cn_ = ci + 1;
                int kc  = (cn_ & 7) * 128;
                const float* ar = ((cn_ < 8) ? hcur : g_ctx) + lr*NH + kc;
                const float* wr = ((cn_ < 8) ? WhhRow : WihRow) + kc;
                #pragma unroll
                for (int p = 0; p < 4; p++) {
                    pA[p] = __ldcg((const float4*)&ar[4*(lq + 8*p)]);
                    pW[p] = __ldg((const float4*)&wr[4*(lq + 8*p)]);
                }
            }

            uint32_t saA = cur ? saA1 : saA0;
            const float* Wc = sWt + cur*DBUF;
            #pragma unroll
            for (int k8 = 0; k8 < 2; k8++) {
                int kw = warp*16 + k8*8;
                uint32_t afr[2][4];
                #pragma unroll
                for (int mi = 0; mi < 2; mi++) {
                    uint32_t addr = saA +
                        (uint32_t)((mi*16 + (lane & 15))*DPITCH + kw + ((lane >> 4) << 2))*4;
                    ldsm_x4(afr[mi][0], afr[mi][1], afr[mi][2], afr[mi][3], addr);
                    #pragma unroll
                    for (int q = 0; q < 4; q++)
                        afr[mi][q] = f2tf(__uint_as_float(afr[mi][q]));
                }
                uint32_t bfr[4][2];
                #pragma unroll
                for (int nt = 0; nt < 4; nt++) {
                    const float* wp = Wc + (nt*8 + (lane >> 2))*DPITCH + kw + (lane & 3);
                    bfr[nt][0] = f2tf(wp[0]);
                    bfr[nt][1] = f2tf(wp[4]);
                }
                #pragma unroll
                for (int mi = 0; mi < 2; mi++)
                    #pragma unroll
                    for (int nt = 0; nt < 4; nt++)
                        mma_tf32(acc[mi][nt], afr[mi][0], afr[mi][1], afr[mi][2],
                                 afr[mi][3], bfr[nt][0], bfr[nt][1]);
            }

            if (ci < 15) {
                float* dA = sA  + (cur ^ 1)*DBUF;
                float* dW = sWt + (cur ^ 1)*DBUF;
                #pragma unroll
                for (int p = 0; p < 4; p++) {
                    *(float4*)&dA[lr*DPITCH + 4*(lq + 8*p)] = pA[p];
                    *(float4*)&dW[lr*DPITCH + 4*(lq + 8*p)] = pW[p];
                }
            }
            __syncthreads();
        }

        {
            float* zw = sZd + warp*(32*33);
            int rr = lane >> 2;
            int cc = (lane & 3)*2;
            #pragma unroll
            for (int mi = 0; mi < 2; mi++)
                #pragma unroll
                for (int nt = 0; nt < 4; nt++) {
                    int col = nt*8 + cc;
                    int row = mi*16 + rr;
                    zw[col*33 + row]       = acc[mi][nt][0];
                    zw[(col+1)*33 + row]   = acc[mi][nt][1];
                    zw[col*33 + row + 8]   = acc[mi][nt][2];
                    zw[(col+1)*33 + row+8] = acc[mi][nt][3];
                }
        }
        __syncthreads();

        {
            float zg4[4] = {xg0, xg1, xg2, xg3};
            #pragma unroll
            for (int g = 0; g < 4; g++) {
                int col = g*8 + cu;
                #pragma unroll
                for (int w = 0; w < 8; w++)
                    zg4[g] += sZd[w*(32*33) + col*33 + cb];
            }
            float cn = sigmf_(zg4[1])*creg + sigmf_(zg4[0])*tanhf(zg4[2]);
            float hn = sigmf_(zg4[3])*tanhf(cn);
            creg = cn;
            hnew[cb*NH + u0 + cu] = hn;
        }
        __syncthreads();
        gridbar();
    }

    {
        const float* hlast = g_hbuf + ((NT-1) & 1)*(NB*NH);
        dec_feat(NT-1, hlast, out_W, out_b, sm, sm + 4*DBUF, fn0);
    }
}

// =============================================================================
extern "C" void kernel_launch(void* const* d_in, const int* in_sizes, int n_in,
                              void* d_out, int out_size)
{
    const float* embed    = (const float*)d_in[0];
    const float* enc_Wih  = (const float*)d_in[1];
    const float* enc_Whh  = (const float*)d_in[2];
    const float* enc_bih  = (const float*)d_in[3];
    const float* enc_bhh  = (const float*)d_in[4];
    const float* dec_Wih  = (const float*)d_in[5];
    const float* dec_Whh  = (const float*)d_in[6];
    const float* dec_bih  = (const float*)d_in[7];
    const float* dec_bhh  = (const float*)d_in[8];
    const float* qk_W     = (const float*)d_in[9];
    const float* qk_b     = (const float*)d_in[10];
    const float* qv_W     = (const float*)d_in[11];
    const float* qv_b     = (const float*)d_in[12];
    const float* ak_W     = (const float*)d_in[13];
    const float* ak_b     = (const float*)d_in[14];
    const float* out_W    = (const float*)d_in[15];
    const float* out_b    = (const float*)d_in[16];
    const float* wd_b     = (const float*)d_in[17];
    const float* hfc1_W   = (const float*)d_in[18];
    const float* hfc1_b   = (const float*)d_in[19];
    const float* hfc2_W   = (const float*)d_in[20];
    const float* hfc2_b   = (const float*)d_in[21];
    const float* cfc1_W   = (const float*)d_in[22];
    const float* cfc1_b   = (const float*)d_in[23];
    const float* cfc2_W   = (const float*)d_in[24];
    const float* cfc2_b   = (const float*)d_in[25];
    const int*   src_seqs = (const int*)d_in[26];
    const int*   src_len  = (const int*)d_in[27];
    const int*   trg_seqs = (const int*)d_in[28];
    float* out = (float*)d_out;

    float *d_src_embed, *d_ans_embed, *d_xproj, *d_dxe, *d_h, *d_c;
    float *d_enc_out, *d_qkey, *d_qval, *d_tmp, *d_feat;
    cudaGetSymbolAddress((void**)&d_src_embed, g_src_embed);
    cudaGetSymbolAddress((void**)&d_ans_embed, g_ans_embed);
    cudaGetSymbolAddress((void**)&d_xproj,     g_xproj);
    cudaGetSymbolAddress((void**)&d_dxe,       g_dxe);
    cudaGetSymbolAddress((void**)&d_h,         g_h);
    cudaGetSymbolAddress((void**)&d_c,         g_c);
    cudaGetSymbolAddress((void**)&d_enc_out,   g_enc_out);
    cudaGetSymbolAddress((void**)&d_qkey,      g_qkey);
    cudaGetSymbolAddress((void**)&d_qval,      g_qval);
    cudaGetSymbolAddress((void**)&d_tmp,       g_tmp);
    cudaGetSymbolAddress((void**)&d_feat,      g_feat);

    cudaFuncSetAttribute(k_sgemm,
                         cudaFuncAttributeMaxDynamicSharedMemorySize, SGSMEM);

    // ---- precompute ----
    k_gather<<<NS*NB, 128>>>(src_seqs, NS, embed, d_src_embed);
    k_gather<<<NT*NB, 128>>>(trg_seqs, 20, embed, d_ans_embed);

    k_sgemm<<<dim3(NG/64, (NS*NB)/128), 256, SGSMEM>>>(NS*NB, NG, ND,
        d_src_embed, ND, enc_Wih, ND, enc_bih, enc_bhh, d_xproj, NG, 0, 2, 0);
    k_sgemm<<<dim3(NG/64, (NT*NB + 127)/128), 256, SGSMEM>>>(NT*NB, NG, ND,
        d_ans_embed, ND, dec_Wih, ND + NH, dec_bih, dec_bhh, d_dxe, NG, 0, 2, 0);

    // ---- encoder recurrence ----
    const int enc_smem = (32*HPITCH + 8*32*33) * (int)sizeof(float);
    cudaFuncSetAttribute(k_enc_persist,
                         cudaFuncAttributeMaxDynamicSharedMemorySize, enc_smem);
    k_enc_persist<<<NBLK, 256, enc_smem>>>(enc_Whh, src_len);

    // ---- bridge MLPs ----
    k_sgemm<<<dim3(2048/64, 1), 256, SGSMEM>>>(NB, 2048, NH, d_h, NH, hfc1_W, NH,
                                       hfc1_b, nullptr, d_tmp, 2048, 2, 0, 0);
    k_sgemm<<<dim3(NH/64, 1), 256, SGSMEM>>>(NB, NH, 2048, d_tmp, 2048, hfc2_W, 2048,
                                     hfc2_b, nullptr, d_h, NH, 0, 0, 0);
    k_sgemm<<<dim3(2048/64, 1), 256, SGSMEM>>>(NB, 2048, NH, d_c, NH, cfc1_W, NH,
                                       cfc1_b, nullptr, d_tmp, 2048, 2, 0, 0);
    k_sgemm<<<dim3(NH/64, 1), 256, SGSMEM>>>(NB, NH, 2048, d_tmp, 2048, cfc2_W, 2048,
                                     cfc2_b, nullptr, d_c, NH, 0, 0, 0);

    // ---- attention precompute ----
    k_sgemm<<<dim3((NK + 63)/64, (NS*NB)/128), 256, SGSMEM>>>(NS*NB, NK, NH,
        d_enc_out, NH, qk_W, NH, qk_b, nullptr, d_qkey, NK, 1, 0, 0);
    k_sgemm<<<dim3(NH/64, (NS*NB)/128), 256, SGSMEM>>>(NS*NB, NH, NH,
        d_enc_out, NH, qv_W, NH, qv_b, nullptr, d_qval, NH, 0, 0, 0);

    // ---- decoder recurrence ----
    const int dec_smem = (4*DBUF + 8*32*33) * (int)sizeof(float);
    cudaFuncSetAttribute(k_dec_persist,
                         cudaFuncAttributeMaxDynamicSharedMemorySize, dec_smem);
    k_dec_persist<<<NBLK, 256, dec_smem>>>(dec_Wih, dec_Whh, ak_W, ak_b,
                                           out_W, out_b, src_len);

    // ---- final logits ----
    k_sgemm<<<dim3((NT*NB + 127)/128, NV/64), 256, SGSMEM>>>(NT*NB, NV, ND,
        d_feat, ND, embed, ND, wd_b, nullptr, out, NV, 0, 1, 1);

    (void)in_sizes; (void)n_in; (void)out_size;
}

// round 14
// speedup vs baseline: 1.2441x; 1.0245x over previous
#include <cuda_runtime.h>
#include <math.h>
#include <stdint.h>

// Problem dims (fixed by the dataset)
#define NB 32      // batch
#define NS 128     // src seq len
#define NT 19      // decoder steps (T-1)
#define ND 512     // embed dim
#define NH 1024    // hidden
#define NG 4096    // 4*H
#define NK 100     // attn key dim
#define NV 32000   // vocab
#define NBLK 128

typedef unsigned long long ull_t;

// ------------------------- scratch (device globals; no allocs) ---------------
__device__ float g_src_embed[NS*NB*ND];
__device__ float g_ans_embed[NT*NB*ND];
__device__ float g_xproj[NS*NG*NB];         // [s][n][b]
__device__ float g_dxe[NT*NG*NB];           // [t][n][b]
__device__ float g_h[NB*NH];
__device__ float g_c[NB*NH];
__device__ float g_hbuf[2*NB*NH];           // enc: tf32 bits; dec: fp32
__device__ float g_enc_out[NS*NB*NH];
__device__ float g_qkey[NS*NB*NK];
__device__ float g_qval[NS*NB*NH];
__device__ float g_tmp[NB*2048];
__device__ float g_ctx[NB*NH];
__device__ float g_attw[NB*NS];
__device__ float g_feat[NT*NB*ND];

__device__ unsigned g_barcnt = 0;
__device__ unsigned g_bargen = 0;

__device__ __forceinline__ float sigmf_(float x) { return 1.0f/(1.0f+expf(-x)); }

// ---- tf32 tensor-core helpers ----
__device__ __forceinline__ uint32_t f2tf(float x)
{
    uint32_t r;
    asm("cvt.rna.tf32.f32 %0, %1;" : "=r"(r) : "f"(x));
    return r;
}
__device__ __forceinline__ uint32_t cvta_s(const void* p)
{
    uint32_t a;
    asm("{ .reg .u64 t; cvta.to.shared.u64 t, %1; cvt.u32.u64 %0, t; }"
        : "=r"(a) : "l"(p));
    return a;
}
__device__ __forceinline__ void ldsm_x4(uint32_t& r0, uint32_t& r1,
                                        uint32_t& r2, uint32_t& r3, uint32_t addr)
{
    asm volatile("ldmatrix.sync.aligned.m8n8.x4.b16 {%0,%1,%2,%3}, [%4];"
                 : "=r"(r0), "=r"(r1), "=r"(r2), "=r"(r3) : "r"(addr));
}
__device__ __forceinline__ void mma_tf32(float* d, uint32_t a0, uint32_t a1,
                                         uint32_t a2, uint32_t a3,
                                         uint32_t b0, uint32_t b1)
{
    asm volatile(
        "mma.sync.aligned.m16n8k8.row.col.f32.tf32.tf32.f32 "
        "{%0,%1,%2,%3}, {%4,%5,%6,%7}, {%8,%9}, {%0,%1,%2,%3};"
        : "+f"(d[0]), "+f"(d[1]), "+f"(d[2]), "+f"(d[3])
        : "r"(a0), "r"(a1), "r"(a2), "r"(a3), "r"(b0), "r"(b1));
}

// ---- cp.async (16B, zero-fill when vbytes==0) ----
__device__ __forceinline__ void cpasync16(uint32_t dst, const void* src, int vbytes)
{
    asm volatile("cp.async.cg.shared.global [%0], [%1], 16, %2;"
                 :: "r"(dst), "l"(src), "r"(vbytes));
}
__device__ __forceinline__ void cp_commit()
{
    asm volatile("cp.async.commit_group;");
}
__device__ __forceinline__ void cp_wait1()
{
    asm volatile("cp.async.wait_group 1;");
}
__device__ __forceinline__ void cp_wait0()
{
    asm volatile("cp.async.wait_group 0;");
}

// single-counter grid barrier
__device__ __forceinline__ void gridbar()
{
    __syncthreads();
    if (threadIdx.x == 0) {
        __threadfence();
        volatile unsigned* vgen = &g_bargen;
        unsigned gen = *vgen;
        if (atomicAdd(&g_barcnt, 1u) == NBLK - 1) {
            g_barcnt = 0;
            __threadfence();
            atomicAdd(&g_bargen, 1u);
        } else {
            while (*vgen == gen) { __nanosleep(16); }
        }
        __threadfence();
    }
    __syncthreads();
}

// helper: scatter 4 prefetched float4s (rows kk=4*(lq+8p)) into tile[k][row]
__device__ __forceinline__ void stash4(float* buf, int lq, int row,
                                       float4 p0, float4 p1, float4 p2, float4 p3)
{
    buf[(4*lq+0)*36+row]=p0.x; buf[(4*lq+1)*36+row]=p0.y;
    buf[(4*lq+2)*36+row]=p0.z; buf[(4*lq+3)*36+row]=p0.w;
    buf[(4*(lq+8)+0)*36+row]=p1.x; buf[(4*(lq+8)+1)*36+row]=p1.y;
    buf[(4*(lq+8)+2)*36+row]=p1.z; buf[(4*(lq+8)+3)*36+row]=p1.w;
    buf[(4*(lq+16)+0)*36+row]=p2.x; buf[(4*(lq+16)+1)*36+row]=p2.y;
    buf[(4*(lq+16)+2)*36+row]=p2.z; buf[(4*(lq+16)+3)*36+row]=p2.w;
    buf[(4*(lq+24)+0)*36+row]=p3.x; buf[(4*(lq+24)+1)*36+row]=p3.y;
    buf[(4*(lq+24)+2)*36+row]=p3.z; buf[(4*(lq+24)+3)*36+row]=p3.w;
}

// ------------------------- embedding gather ---------------------------------
__global__ void k_gather(const int* __restrict__ seq, int seq_stride,
                         const float* __restrict__ embed, float* __restrict__ out)
{
    int row = blockIdx.x;
    int st  = row / NB;
    int b   = row % NB;
    int tok = seq[b*seq_stride + st];
    const float4* src = (const float4*)(embed + (size_t)tok*ND);
    float4*       dst = (float4*)(out + (size_t)row*ND);
    dst[threadIdx.x] = src[threadIdx.x];
}

// ------------------------- tf32 tensor-core GEMM (cp.async 3-stage) ----------
#define SGSTG 3840          // stage stride in u32 (As 2560 + Ws 1280)
#define SGSMEM (3*SGSTG*4)  // 46080 bytes
__global__ __launch_bounds__(256)
void k_sgemm(int M, int N, int K,
             const float* __restrict__ A, int lda,
             const float* __restrict__ W, int ldw,
             const float* __restrict__ bias1, const float* __restrict__ bias2,
             float* __restrict__ C, int ldc, int act, int out_map, int swap_grid)
{
    extern __shared__ __align__(16) uint32_t smem_u[];   // 3 stages
    float* Cs = (float*)smem_u;                          // [128][68] reuse at end

    int tid  = threadIdx.x;
    int lane = tid & 31;
    int warp = tid >> 5;
    int wm   = warp & 3;
    int wn   = warp >> 2;
    int m0, n0;
    if (swap_grid) { m0 = blockIdx.x*128; n0 = blockIdx.y*64; }
    else           { m0 = blockIdx.y*128; n0 = blockIdx.x*64; }

    int ra = tid >> 2;
    int kc = (tid & 3) * 4;

    bool a0v = (m0 + ra < M);
    bool a1v = (m0 + ra + 64 < M);
    bool wv_ = (n0 + ra < N) && (ra < 64);
    const float* Arow0 = A + (size_t)(a0v ? (m0+ra)    : 0)*lda + kc;
    const float* Arow1 = A + (size_t)(a1v ? (m0+ra+64) : 0)*lda + kc;
    const float* Wrow  = W + (size_t)(wv_ ? (n0+ra)    : 0)*ldw + kc;
    int az0 = a0v ? 16 : 0, az1 = a1v ? 16 : 0, wz = wv_ ? 16 : 0;

    uint32_t sbase[3];
    #pragma unroll
    for (int s = 0; s < 3; s++) sbase[s] = cvta_s(smem_u + s*SGSTG);
    uint32_t a0off = (uint32_t)(ra*20 + kc)*4;
    uint32_t a1off = (uint32_t)((ra+64)*20 + kc)*4;
    uint32_t woff  = (uint32_t)(2560 + ra*20 + kc)*4;

    uint32_t ws_row = (uint32_t)(wn*32 + (lane >> 2))*20 + (lane & 3);
    float acc[2][4][4] = {};
    int nit = K >> 4;

    #pragma unroll
    for (int s = 0; s < 2; s++) {
        int k0 = s << 4;
        uint32_t b = sbase[s];
        cpasync16(b + a0off, Arow0 + k0, az0);
        cpasync16(b + a1off, Arow1 + k0, az1);
        if (ra < 64) cpasync16(b + woff, Wrow + k0, wz);
        cp_commit();
    }

    int sidx = 0;
    for (int it = 0; it < nit; it++) {
        cp_wait1();
        __syncthreads();

        int snx = sidx + 2; if (snx >= 3) snx -= 3;
        if (it + 2 < nit) {
            int k0 = (it + 2) << 4;
            uint32_t b = sbase[snx];
            cpasync16(b + a0off, Arow0 + k0, az0);
            cpasync16(b + a1off, Arow1 + k0, az1);
            if (ra < 64) cpasync16(b + woff, Wrow + k0, wz);
        }
        cp_commit();

        uint32_t as_base = sbase[sidx];
        const float* WsF = (const float*)(smem_u + sidx*SGSTG + 2560);
        #pragma unroll
        for (int ks = 0; ks < 16; ks += 8) {
            uint32_t afr[2][4];
            #pragma unroll
            for (int mi = 0; mi < 2; mi++) {
                uint32_t row = (uint32_t)(wm*32 + mi*16 + (lane & 15));
                uint32_t kof = (uint32_t)(ks + ((lane >> 4) << 2));
                uint32_t addr = as_base + (row*20 + kof)*4;
                ldsm_x4(afr[mi][0], afr[mi][1], afr[mi][2], afr[mi][3], addr);
                #pragma unroll
                for (int q = 0; q < 4; q++)
                    afr[mi][q] = f2tf(__uint_as_float(afr[mi][q]));
            }
            uint32_t bfr[4][2];
            #pragma unroll
            for (int j = 0; j < 4; j++) {
                bfr[j][0] = f2tf(WsF[ws_row + (uint32_t)(j*8)*20 + ks]);
                bfr[j][1] = f2tf(WsF[ws_row + (uint32_t)(j*8)*20 + ks + 4]);
            }
            #pragma unroll
            for (int mi = 0; mi < 2; mi++)
                #pragma unroll
                for (int j = 0; j < 4; j++)
                    mma_tf32(acc[mi][j], afr[mi][0], afr[mi][1], afr[mi][2],
                             afr[mi][3], bfr[j][0], bfr[j][1]);
        }
        sidx++; if (sidx >= 3) sidx = 0;
    }
    __syncthreads();

    #pragma unroll
    for (int mi = 0; mi < 2; mi++) {
        int ml0 = wm*32 + mi*16 + (lane >> 2);
        #pragma unroll
        for (int j = 0; j < 4; j++) {
            int nl = wn*32 + j*8 + (lane & 3)*2;
            float b0v = 0.f, b1v = 0.f;
            if (n0 + nl < N) {
                b0v = bias1[n0+nl];
                if (bias2) b0v += bias2[n0+nl];
            }
            if (n0 + nl + 1 < N) {
                b1v = bias1[n0+nl+1];
                if (bias2) b1v += bias2[n0+nl+1];
            }
            float v0 = acc[mi][j][0] + b0v;
            float v1 = acc[mi][j][1] + b1v;
            float v2 = acc[mi][j][2] + b0v;
            float v3 = acc[mi][j][3] + b1v;
            if (act == 1) { v0=tanhf(v0); v1=tanhf(v1); v2=tanhf(v2); v3=tanhf(v3); }
            else if (act == 2) { v0=fmaxf(v0,0.f); v1=fmaxf(v1,0.f);
                                 v2=fmaxf(v2,0.f); v3=fmaxf(v3,0.f); }
            Cs[ml0*68 + nl]       = v0;
            Cs[ml0*68 + nl + 1]   = v1;
            Cs[(ml0+8)*68 + nl]   = v2;
            Cs[(ml0+8)*68 + nl+1] = v3;
        }
    }
    __syncthreads();

    if (out_map == 2) {
        for (int c = tid; c < 2048; c += 256) {
            int qb = (c & 7) * 4;
            int nl = (c >> 3) & 63;
            int sh = c >> 9;
            int mgrp = m0 + sh*32;
            if (mgrp >= M) continue;
            float4 v4 = make_float4(Cs[(sh*32+qb+0)*68 + nl],
                                    Cs[(sh*32+qb+1)*68 + nl],
                                    Cs[(sh*32+qb+2)*68 + nl],
                                    Cs[(sh*32+qb+3)*68 + nl]);
            *(float4*)&C[((size_t)(mgrp >> 5)*NG + n0 + nl)*32 + qb] = v4;
        }
        return;
    }

    for (int c = tid; c < 2048; c += 256) {
        int ml = c >> 4;
        int nl = (c & 15) * 4;
        int m = m0 + ml;
        if (m >= M) continue;
        size_t row = (out_map == 1) ? (size_t)((m & 31)*NT + (m >> 5)) : (size_t)m;
        int n = n0 + nl;
        if (n + 3 < N) {
            *(float4*)&C[row*ldc + n] = *(const float4*)&Cs[ml*68 + nl];
        } else {
            for (int j = 0; j < 4; j++)
                if (n + j < N) C[row*ldc + n + j] = Cs[ml*68 + nl + j];
        }
    }
}

// ------------------------- tensor-core persistent encoder -------------------
// 2-phase step pipeline: warp w covers k in [w*64,w*64+64) (phase0, k<512)
// and [512+w*64, +64) (phase1). h halves loaded via cp.async; phase1 load
// overlaps phase0 mma. g_hbuf carries tf32 bits (producer-side cvt).
#define HPITCH 1028
__global__ void __launch_bounds__(256, 1)
k_enc_persist(const float* __restrict__ Whh, const int* __restrict__ lengths)
{
    extern __shared__ float sm[];
    float* sH = sm;                          // [32][HPITCH] tf32 bits
    float* sZ = sm + 32*HPITCH;              // [8][32][33]

    int tid  = threadIdx.x;
    int lane = tid & 31;
    int warp = tid >> 5;
    int u0   = blockIdx.x * 8;

    // ---- load Whh slice as B fragments, new k mapping ----
    uint32_t wf[4][16][2];
    {
        int nr  = lane >> 2;
        int kq  = lane & 3;
        #pragma unroll
        for (int nt = 0; nt < 4; nt++) {
            int n = nt*8 + nr;
            const float* wrow = Whh + (size_t)((n >> 3)*NH + u0 + (n & 7))*NH + kq;
            #pragma unroll
            for (int kt = 0; kt < 16; kt++) {
                int koff = (kt < 8) ? (warp*64 + kt*8)
                                    : (512 + warp*64 + (kt-8)*8);
                wf[nt][kt][0] = f2tf(__ldg(&wrow[koff]));
                wf[nt][kt][1] = f2tf(__ldg(&wrow[koff + 4]));
            }
        }
    }

    int cb = tid & 31;
    int cu = tid >> 5;
    int mylen = lengths[cb];
    int len_hi = 0;
    #pragma unroll
    for (int i = 16; i < 32; i++) len_hi = max(len_hi, lengths[i]);
    float creg = 0.0f, hreg = 0.0f;

    g_hbuf[cb*NH + u0 + cu] = 0.0f;          // tf32(0) == 0 bits

    int lr      = tid >> 3;
    int lane8   = tid & 7;
    int loadlen = lengths[lr];               // load row lr while s <= loadlen
    uint32_t sh_base = cvta_s(sH);
    uint32_t sh_row  = sh_base + (uint32_t)(lr*HPITCH)*4;

    gridbar();

    for (int s = 0; s < NS; s++) {
        const float* hin  = g_hbuf + (s & 1)*(NB*NH);
        float*       hout = g_hbuf + ((s & 1) ^ 1)*(NB*NH);
        bool act_hi = (s < len_hi);
        bool doload = (s <= loadlen);

        // issue half0 (k<512) and half1 (k>=512) as two cp.async groups
        {
            const float* hr = hin + lr*NH;
            if (doload) {
                #pragma unroll
                for (int kk = 0; kk < 16; kk++) {
                    int u4 = lane8 + 8*kk;               // uint4 idx 0..127
                    cpasync16(sh_row + u4*16, hr + u4*4, 16);
                }
            }
            cp_commit();
            if (doload) {
                #pragma unroll
                for (int kk = 16; kk < 32; kk++) {
                    int u4 = lane8 + 8*kk;               // 128..255
                    cpasync16(sh_row + u4*16, hr + u4*4, 16);
                }
            }
            cp_commit();
        }

        const float* xp = g_xproj + ((size_t)s*NG + u0 + cu)*32 + cb;
        float xg0 = __ldg(&xp[0]);
        float xg1 = __ldg(&xp[(size_t)NH*32]);
        float xg2 = __ldg(&xp[(size_t)2*NH*32]);
        float xg3 = __ldg(&xp[(size_t)3*NH*32]);

        cp_wait1();          // half0 landed
        __syncthreads();

        float acc[2][4][4] = {};
        // ---- phase 0: k in [warp*64, warp*64+64) ----
        #pragma unroll
        for (int kt = 0; kt < 8; kt++) {
            int kof = warp*64 + kt*8 + ((lane >> 4) << 2);
            {
                uint32_t a0, a1, a2, a3;
                uint32_t addr = sh_base + (uint32_t)(((lane & 15))*HPITCH + kof)*4;
                ldsm_x4(a0, a1, a2, a3, addr);
                #pragma unroll
                for (int nt = 0; nt < 4; nt++)
                    mma_tf32(acc[0][nt], a0, a1, a2, a3,
                             wf[nt][kt][0], wf[nt][kt][1]);
            }
            if (act_hi) {
                uint32_t a0, a1, a2, a3;
                uint32_t addr = sh_base + (uint32_t)((16 + (lane & 15))*HPITCH + kof)*4;
                ldsm_x4(a0, a1, a2, a3, addr);
                #pragma unroll
                for (int nt = 0; nt < 4; nt++)
                    mma_tf32(acc[1][nt], a0, a1, a2, a3,
                             wf[nt][kt][0], wf[nt][kt][1]);
            }
        }

        cp_wait0();          // half1 landed
        __syncthreads();

        // ---- phase 1: k in [512+warp*64, +64) ----
        #pragma unroll
        for (int kt = 8; kt < 16; kt++) {
            int kof = 512 + warp*64 + (kt-8)*8 + ((lane >> 4) << 2);
            {
                uint32_t a0, a1, a2, a3;
                uint32_t addr = sh_base + (uint32_t)(((lane & 15))*HPITCH + kof)*4;
                ldsm_x4(a0, a1, a2, a3, addr);
                #pragma unroll
                for (int nt = 0; nt < 4; nt++)
                    mma_tf32(acc[0][nt], a0, a1, a2, a3,
                             wf[nt][kt][0], wf[nt][kt][1]);
            }
            if (act_hi) {
                uint32_t a0, a1, a2, a3;
                uint32_t addr = sh_base + (uint32_t)((16 + (lane & 15))*HPITCH + kof)*4;
                ldsm_x4(a0, a1, a2, a3, addr);
                #pragma unroll
                for (int nt = 0; nt < 4; nt++)
                    mma_tf32(acc[1][nt], a0, a1, a2, a3,
                             wf[nt][kt][0], wf[nt][kt][1]);
            }
        }

        {
            float* zw = sZ + warp*(32*33);
            int rr = lane >> 2;
            int cc = (lane & 3)*2;
            #pragma unroll
            for (int mi = 0; mi < 2; mi++) {
                if (mi == 1 && !act_hi) break;
                #pragma unroll
                for (int nt = 0; nt < 4; nt++) {
                    int col = nt*8 + cc;
                    int row = mi*16 + rr;
                    zw[col*33 + row]       = acc[mi][nt][0];
                    zw[(col+1)*33 + row]   = acc[mi][nt][1];
                    zw[col*33 + row + 8]   = acc[mi][nt][2];
                    zw[(col+1)*33 + row+8] = acc[mi][nt][3];
                }
            }
        }
        __syncthreads();

        float zg4[4] = {xg0, xg1, xg2, xg3};
        #pragma unroll
        for (int g = 0; g < 4; g++) {
            int col = g*8 + cu;
            #pragma unroll
            for (int w = 0; w < 8; w++)
                zg4[g] += sZ[w*(32*33) + col*33 + cb];
        }
        float cn = sigmf_(zg4[1])*creg + sigmf_(zg4[0])*tanhf(zg4[2]);
        float hn = sigmf_(zg4[3])*tanhf(cn);
        bool msk = (s < mylen);
        creg = msk ? cn : creg;
        hreg = msk ? hn : hreg;
        ((uint32_t*)hout)[cb*NH + u0 + cu] = f2tf(hreg);   // producer-side cvt
        g_enc_out[((size_t)(s*NB + cb))*NH + u0 + cu] = msk ? hreg : 0.0f;

        gridbar();
    }

    g_h[cb*NH + u0 + cu] = hreg;
    g_c[cb*NH + u0 + cu] = creg;
}

// ------------------------- persistent decoder helpers -----------------------
__device__ __forceinline__ void dec_feat(int tt, const float* __restrict__ hsrc,
    const float* __restrict__ out_W, const float* __restrict__ out_b,
    float* sH, float* sZ, int fn0)
{
    int tid = threadIdx.x;
    int r   = tid >> 6;
    int fks = (tid >> 5) & 1;
    int fb  = tid & 31;
    int lb  = tid >> 3;
    int lq  = tid & 7;
    const float* wrow = out_W + (size_t)(fn0 + r)*(2*NH);
    float fa = 0.f;

    float4 p0, p1, p2, p3;
    {
        const float* hr = hsrc + lb*NH;
        p0 = __ldcg((const float4*)&hr[4*lq]);
        p1 = __ldcg((const float4*)&hr[4*(lq+8)]);
        p2 = __ldcg((const float4*)&hr[4*(lq+16)]);
        p3 = __ldcg((const float4*)&hr[4*(lq+24)]);
        stash4(sH, lq, lb, p0, p1, p2, p3);
    }
    __syncthreads();

    for (int ch = 0; ch < 16; ch++) {
        float* cur = sH + (ch & 1)*(128*36);
        if (ch < 15) {
            int cn_ = ch + 1;
            const float* src = (cn_ < 8) ? hsrc : g_ctx;
            const float* hr = src + lb*NH + (cn_ & 7)*128;
            p0 = __ldcg((const float4*)&hr[4*lq]);
            p1 = __ldcg((const float4*)&hr[4*(lq+8)]);
            p2 = __ldcg((const float4*)&hr[4*(lq+16)]);
            p3 = __ldcg((const float4*)&hr[4*(lq+24)]);
        }
        const float* wc = wrow + ch*128 + fks*64;
        const float* hc = cur + fks*64*36 + fb;
        #pragma unroll 16
        for (int k = 0; k < 64; k++)
            fa += __ldg(&wc[k]) * hc[k*36];
        if (ch < 15)
            stash4(sH + ((ch & 1) ^ 1)*(128*36), lq, lb, p0, p1, p2, p3);
        __syncthreads();
    }
    sZ[(r*2 + fks)*33 + fb] = fa;
    __syncthreads();
    if (tid < 128) {
        int rr = tid >> 5, bb = tid & 31;
        float v = sZ[(rr*2)*33 + bb] + sZ[(rr*2+1)*33 + bb] + __ldg(&out_b[fn0 + rr]);
        g_feat[((size_t)(tt*NB + bb))*ND + fn0 + rr] = v;
    }
    __syncthreads();
}

__device__ __forceinline__ void dec_attn(int b, int mylen,
    const float* __restrict__ hcur,
    const float* __restrict__ ak_W, const float* __restrict__ ak_b,
    float* sW)
{
    int tid = threadIdx.x;
    float* sh_ = sW;
    float* sak = sW + 1024;
    float* se  = sW + 1152;
    float* sr  = sW + 1280;

    for (int i = tid; i < NH; i += 256) sh_[i] = __ldcg(&hcur[b*NH + i]);
    __syncthreads();

    if (tid < NK) {
        const float* wr = ak_W + (size_t)tid*NH;
        float acc0 = 0.f, acc1 = 0.f;
        for (int k = 0; k < NH; k += 8) {
            float4 w0 = *(const float4*)&wr[k];
            float4 w1 = *(const float4*)&wr[k+4];
            float4 h0 = *(const float4*)&sh_[k];
            float4 h1 = *(const float4*)&sh_[k+4];
            acc0 += w0.x*h0.x + w0.y*h0.y + w0.z*h0.z + w0.w*h0.w;
            acc1 += w1.x*h1.x + w1.y*h1.y + w1.z*h1.z + w1.w*h1.w;
        }
        sak[tid] = tanhf(acc0 + acc1 + ak_b[tid]);
    }
    __syncthreads();

    if (tid < NS) {
        const float* qr = g_qkey + ((size_t)(tid*NB + b))*NK;
        float acc = 0.f;
        for (int k = 0; k < NK; k++) acc += qr[k]*sak[k];
        se[tid] = (tid < mylen) ? acc : -INFINITY;
    }
    __syncthreads();

    sr[tid] = (tid < NS) ? se[tid] : -INFINITY;
    __syncthreads();
    for (int off = 128; off >= 1; off >>= 1) {
        if (tid < off) sr[tid] = fmaxf(sr[tid], sr[tid+off]);
        __syncthreads();
    }
    float mx = sr[0];
    __syncthreads();

    float ex = (tid < NS) ? expf(se[tid] - mx) : 0.0f;
    sr[tid] = ex;
    __syncthreads();
    for (int off = 128; off >= 1; off >>= 1) {
        if (tid < off) sr[tid] += sr[tid+off];
        __syncthreads();
    }
    float inv = 1.0f / sr[0];
    __syncthreads();
    if (tid < NS) g_attw[b*NS + tid] = ex * inv;
    __syncthreads();
}

// ------------------------- persistent decoder (tf32 mma z-GEMM) -------------
#define DPITCH 132
#define DBUF (32*DPITCH)
__global__ void __launch_bounds__(256, 1)
k_dec_persist(const float* __restrict__ dec_Wih, const float* __restrict__ dec_Whh,
              const float* __restrict__ ak_W,   const float* __restrict__ ak_b,
              const float* __restrict__ out_W,  const float* __restrict__ out_b,
              const int* __restrict__ lengths)
{
    extern __shared__ float sm[];
    float* sA  = sm;                    // 2 x DBUF
    float* sWt = sm + 2*DBUF;           // 2 x DBUF
    float* sZd = sm + 4*DBUF;           // [8][32][33] = 8448

    int tid  = threadIdx.x;
    int lane = tid & 31;
    int warp = tid >> 5;
    int blk  = blockIdx.x;
    int u0   = blk * 8;
    int fn0  = blk * 4;

    int cb = tid & 31, cu = tid >> 5;
    float creg = g_c[cb*NH + u0 + cu];

    int lr  = tid >> 3;
    int lq  = tid & 7;
    int wn_ = (lr >> 3)*NH + u0 + (lr & 7);
    const float* WhhRow = dec_Whh + (size_t)wn_*NH;
    const float* WihRow = dec_Wih + (size_t)wn_*(ND+NH) + ND;

    uint32_t saA0 = cvta_s(sA);
    uint32_t saA1 = cvta_s(sA + DBUF);

    int mylen = (blk < 32) ? lengths[blk] : 0;

    for (int t = 0; t < NT; t++) {
        const float* hcur = (t == 0) ? g_h : (g_hbuf + ((t-1) & 1)*(NB*NH));
        float*       hnew = g_hbuf + (t & 1)*(NB*NH);

        if (t > 0)
            dec_feat(t-1, hcur, out_W, out_b, sm, sm + 4*DBUF, fn0);
        if (blk < 32)
            dec_attn(blk, mylen, hcur, ak_W, ak_b, sm);
        gridbar();

        // ---- context ----
        {
            int b  = blk & 31;
            int hq = blk >> 5;
            if (tid < NS) sZd[tid] = __ldcg(&g_attw[b*NS + tid]);
            __syncthreads();
            int hh = hq*256 + tid;
            float a0 = 0.f, a1 = 0.f, a2 = 0.f, a3 = 0.f;
            #pragma unroll 4
            for (int s = 0; s < NS; s += 4) {
                a0 += sZd[s+0]*__ldg(&g_qval[((size_t)((s+0)*NB + b))*NH + hh]);
                a1 += sZd[s+1]*__ldg(&g_qval[((size_t)((s+1)*NB + b))*NH + hh]);
                a2 += sZd[s+2]*__ldg(&g_qval[((size_t)((s+2)*NB + b))*NH + hh]);
                a3 += sZd[s+3]*__ldg(&g_qval[((size_t)((s+3)*NB + b))*NH + hh]);
            }
            g_ctx[b*NH + hh] = (a0 + a1) + (a2 + a3);
            __syncthreads();
        }
        gridbar();

        const float* xp = g_dxe + ((size_t)t*NG + u0 + cu)*32 + cb;
        float xg0 = __ldg(&xp[0]);
        float xg1 = __ldg(&xp[(size_t)NH*32]);
        float xg2 = __ldg(&xp[(size_t)2*NH*32]);
        float xg3 = __ldg(&xp[(size_t)3*NH*32]);

        // ---- z GEMM via tf32 mma, 16 chunks of 128 k, double-buffered ----
        float acc[2][4][4] = {};
        float4 pA[4], pW[4];
        {
            const float* ar = hcur + lr*NH;
            #pragma unroll
            for (int p = 0; p < 4; p++) {
                pA[p] = __ldcg((const float4*)&ar[4*(lq + 8*p)]);
                pW[p] = __ldg((const float4*)&WhhRow[4*(lq + 8*p)]);
            }
            #pragma unroll
            for (int p = 0; p < 4; p++) {
                *(float4*)&sA [lr*DPITCH + 4*(lq + 8*p)] = pA[p];
                *(float4*)&sWt[lr*DPITCH + 4*(lq + 8*p)] = pW[p];
            }
        }
        __syncthreads();

        for (int ci = 0; ci < 16; ci++) {
            int cur = ci & 1;
            if (ci < 15) {
                int cn_ = ci + 1;
                int kc  = (cn_ & 7) * 128;
                const float* ar = ((cn_ < 8) ? hcur : g_ctx) + lr*NH + kc;
                const float* wr = ((cn_ < 8) ? WhhRow : WihRow) + kc;
                #pragma unroll
                for (int p = 0; p < 4; p++) {
                    pA[p] = __ldcg((const float4*)&ar[4*(lq + 8*p)]);
                    pW[p] = __ldg((const float4*)&wr[4*(lq + 8*p)]);
                }
            }

            uint32_t saA = cur ? saA1 : saA0;
            const float* Wc = sWt + cur*DBUF;
            #pragma unroll
            for (int k8 = 0; k8 < 2; k8++) {
                int kw = warp*16 + k8*8;
                uint32_t afr[2][4];
                #pragma unroll
                for (int mi = 0; mi < 2; mi++) {
                    uint32_t addr = saA +
                        (uint32_t)((mi*16 + (lane & 15))*DPITCH + kw + ((lane >> 4) << 2))*4;
                    ldsm_x4(afr[mi][0], afr[mi][1], afr[mi][2], afr[mi][3], addr);
                    #pragma unroll
                    for (int q = 0; q < 4; q++)
                        afr[mi][q] = f2tf(__uint_as_float(afr[mi][q]));
                }
                uint32_t bfr[4][2];
                #pragma unroll
                for (int nt = 0; nt < 4; nt++) {
                    const float* wp = Wc + (nt*8 + (lane >> 2))*DPITCH + kw + (lane & 3);
                    bfr[nt][0] = f2tf(wp[0]);
                    bfr[nt][1] = f2tf(wp[4]);
                }
                #pragma unroll
                for (int mi = 0; mi < 2; mi++)
                    #pragma unroll
                    for (int nt = 0; nt < 4; nt++)
                        mma_tf32(acc[mi][nt], afr[mi][0], afr[mi][1], afr[mi][2],
                                 afr[mi][3], bfr[nt][0], bfr[nt][1]);
            }

            if (ci < 15) {
                float* dA = sA  + (cur ^ 1)*DBUF;
                float* dW = sWt + (cur ^ 1)*DBUF;
                #pragma unroll
                for (int p = 0; p < 4; p++) {
                    *(float4*)&dA[lr*DPITCH + 4*(lq + 8*p)] = pA[p];
                    *(float4*)&dW[lr*DPITCH + 4*(lq + 8*p)] = pW[p];
                }
            }
            __syncthreads();
        }

        {
            float* zw = sZd + warp*(32*33);
            int rr = lane >> 2;
            int cc = (lane & 3)*2;
            #pragma unroll
            for (int mi = 0; mi < 2; mi++)
                #pragma unroll
                for (int nt = 0; nt < 4; nt++) {
                    int col = nt*8 + cc;
                    int row = mi*16 + rr;
                    zw[col*33 + row]       = acc[mi][nt][0];
                    zw[(col+1)*33 + row]   = acc[mi][nt][1];
                    zw[col*33 + row + 8]   = acc[mi][nt][2];
                    zw[(col+1)*33 + row+8] = acc[mi][nt][3];
                }
        }
        __syncthreads();

        {
            float zg4[4] = {xg0, xg1, xg2, xg3};
            #pragma unroll
            for (int g = 0; g < 4; g++) {
                int col = g*8 + cu;
                #pragma unroll
                for (int w = 0; w < 8; w++)
                    zg4[g] += sZd[w*(32*33) + col*33 + cb];
            }
            float cn = sigmf_(zg4[1])*creg + sigmf_(zg4[0])*tanhf(zg4[2]);
            float hn = sigmf_(zg4[3])*tanhf(cn);
            creg = cn;
            hnew[cb*NH + u0 + cu] = hn;
        }
        __syncthreads();
        gridbar();
    }

    {
        const float* hlast = g_hbuf + ((NT-1) & 1)*(NB*NH);
        dec_feat(NT-1, hlast, out_W, out_b, sm, sm + 4*DBUF, fn0);
    }
}

// =============================================================================
extern "C" void kernel_launch(void* const* d_in, const int* in_sizes, int n_in,
                              void* d_out, int out_size)
{
    const float* embed    = (const float*)d_in[0];
    const float* enc_Wih  = (const float*)d_in[1];
    const float* enc_Whh  = (const float*)d_in[2];
    const float* enc_bih  = (const float*)d_in[3];
    const float* enc_bhh  = (const float*)d_in[4];
    const float* dec_Wih  = (const float*)d_in[5];
    const float* dec_Whh  = (const float*)d_in[6];
    const float* dec_bih  = (const float*)d_in[7];
    const float* dec_bhh  = (const float*)d_in[8];
    const float* qk_W     = (const float*)d_in[9];
    const float* qk_b     = (const float*)d_in[10];
    const float* qv_W     = (const float*)d_in[11];
    const float* qv_b     = (const float*)d_in[12];
    const float* ak_W     = (const float*)d_in[13];
    const float* ak_b     = (const float*)d_in[14];
    const float* out_W    = (const float*)d_in[15];
    const float* out_b    = (const float*)d_in[16];
    const float* wd_b     = (const float*)d_in[17];
    const float* hfc1_W   = (const float*)d_in[18];
    const float* hfc1_b   = (const float*)d_in[19];
    const float* hfc2_W   = (const float*)d_in[20];
    const float* hfc2_b   = (const float*)d_in[21];
    const float* cfc1_W   = (const float*)d_in[22];
    const float* cfc1_b   = (const float*)d_in[23];
    const float* cfc2_W   = (const float*)d_in[24];
    const float* cfc2_b   = (const float*)d_in[25];
    const int*   src_seqs = (const int*)d_in[26];
    const int*   src_len  = (const int*)d_in[27];
    const int*   trg_seqs = (const int*)d_in[28];
    float* out = (float*)d_out;

    float *d_src_embed, *d_ans_embed, *d_xproj, *d_dxe, *d_h, *d_c;
    float *d_enc_out, *d_qkey, *d_qval, *d_tmp, *d_feat;
    cudaGetSymbolAddress((void**)&d_src_embed, g_src_embed);
    cudaGetSymbolAddress((void**)&d_ans_embed, g_ans_embed);
    cudaGetSymbolAddress((void**)&d_xproj,     g_xproj);
    cudaGetSymbolAddress((void**)&d_dxe,       g_dxe);
    cudaGetSymbolAddress((void**)&d_h,         g_h);
    cudaGetSymbolAddress((void**)&d_c,         g_c);
    cudaGetSymbolAddress((void**)&d_enc_out,   g_enc_out);
    cudaGetSymbolAddress((void**)&d_qkey,      g_qkey);
    cudaGetSymbolAddress((void**)&d_qval,      g_qval);
    cudaGetSymbolAddress((void**)&d_tmp,       g_tmp);
    cudaGetSymbolAddress((void**)&d_feat,      g_feat);

    cudaFuncSetAttribute(k_sgemm,
                         cudaFuncAttributeMaxDynamicSharedMemorySize, SGSMEM);
    cudaFuncSetAttribute(k_sgemm,
                         cudaFuncAttributePreferredSharedMemoryCarveout, 100);

    // ---- precompute ----
    k_gather<<<NS*NB, 128>>>(src_seqs, NS, embed, d_src_embed);
    k_gather<<<NT*NB, 128>>>(trg_seqs, 20, embed, d_ans_embed);

    k_sgemm<<<dim3(NG/64, (NS*NB)/128), 256, SGSMEM>>>(NS*NB, NG, ND,
        d_src_embed, ND, enc_Wih, ND, enc_bih, enc_bhh, d_xproj, NG, 0, 2, 0);
    k_sgemm<<<dim3(NG/64, (NT*NB + 127)/128), 256, SGSMEM>>>(NT*NB, NG, ND,
        d_ans_embed, ND, dec_Wih, ND + NH, dec_bih, dec_bhh, d_dxe, NG, 0, 2, 0);

    // ---- encoder recurrence ----
    const int enc_smem = (32*HPITCH + 8*32*33) * (int)sizeof(float);
    cudaFuncSetAttribute(k_enc_persist,
                         cudaFuncAttributeMaxDynamicSharedMemorySize, enc_smem);
    k_enc_persist<<<NBLK, 256, enc_smem>>>(enc_Whh, src_len);

    // ---- bridge MLPs ----
    k_sgemm<<<dim3(2048/64, 1), 256, SGSMEM>>>(NB, 2048, NH, d_h, NH, hfc1_W, NH,
                                       hfc1_b, nullptr, d_tmp, 2048, 2, 0, 0);
    k_sgemm<<<dim3(NH/64, 1), 256, SGSMEM>>>(NB, NH, 2048, d_tmp, 2048, hfc2_W, 2048,
                                     hfc2_b, nullptr, d_h, NH, 0, 0, 0);
    k_sgemm<<<dim3(2048/64, 1), 256, SGSMEM>>>(NB, 2048, NH, d_c, NH, cfc1_W, NH,
                                       cfc1_b, nullptr, d_tmp, 2048, 2, 0, 0);
    k_sgemm<<<dim3(NH/64, 1), 256, SGSMEM>>>(NB, NH, 2048, d_tmp, 2048, cfc2_W, 2048,
                                     cfc2_b, nullptr, d_c, NH, 0, 0, 0);

    // ---- attention precompute ----
    k_sgemm<<<dim3((NK + 63)/64, (NS*NB)/128), 256, SGSMEM>>>(NS*NB, NK, NH,
        d_enc_out, NH, qk_W, NH, qk_b, nullptr, d_qkey, NK, 1, 0, 0);
    k_sgemm<<<dim3(NH/64, (NS*NB)/128), 256, SGSMEM>>>(NS*NB, NH, NH,
        d_enc_out, NH, qv_W, NH, qv_b, nullptr, d_qval, NH, 0, 0, 0);

    // ---- decoder recurrence ----
    const int dec_smem = (4*DBUF + 8*32*33) * (int)sizeof(float);
    cudaFuncSetAttribute(k_dec_persist,
                         cudaFuncAttributeMaxDynamicSharedMemorySize, dec_smem);
    k_dec_persist<<<NBLK, 256, dec_smem>>>(dec_Wih, dec_Whh, ak_W, ak_b,
                                           out_W, out_b, src_len);

    // ---- final logits ----
    k_sgemm<<<dim3((NT*NB + 127)/128, NV/64), 256, SGSMEM>>>(NT*NB, NV, ND,
        d_feat, ND, embed, ND, wd_b, nullptr, out, NV, 0, 1, 1);

    (void)in_sizes; (void)n_in; (void)out_size;
}

// round 15
// speedup vs baseline: 1.2583x; 1.0114x over previous
#include <cuda_runtime.h>
#include <math.h>
#include <stdint.h>

// Problem dims (fixed by the dataset)
#define NB 32      // batch
#define NS 128     // src seq len
#define NT 19      // decoder steps (T-1)
#define ND 512     // embed dim
#define NH 1024    // hidden
#define NG 4096    // 4*H
#define NK 100     // attn key dim
#define NV 32000   // vocab
#define NBLK 128

typedef unsigned long long ull_t;

// ------------------------- scratch (device globals; no allocs) ---------------
__device__ float g_src_embed[NS*NB*ND];
__device__ float g_ans_embed[NT*NB*ND];
__device__ float g_xproj[NS*NG*NB];         // [s][n][b]
__device__ float g_dxe[NT*NG*NB];           // [t][n][b]
__device__ float g_h[NB*NH];
__device__ float g_c[NB*NH];
__device__ float g_hbuf[2*NB*NH];           // enc: tf32 bits; dec: fp32
__device__ float g_enc_out[NS*NB*NH];
__device__ float g_qkey[NS*NB*NK];
__device__ float g_qval[NS*NB*NH];
__device__ float g_tmp[NB*2048];
__device__ float g_ctx[NB*NH];
__device__ float g_attw[NB*NS];
__device__ float g_feat[NT*NB*ND];

__device__ unsigned g_barcnt = 0;
__device__ unsigned g_bargen = 0;

__device__ __forceinline__ float sigmf_(float x) { return 1.0f/(1.0f+expf(-x)); }

// ---- tf32 tensor-core helpers ----
__device__ __forceinline__ uint32_t f2tf(float x)
{
    uint32_t r;
    asm("cvt.rna.tf32.f32 %0, %1;" : "=r"(r) : "f"(x));
    return r;
}
__device__ __forceinline__ uint32_t cvta_s(const void* p)
{
    uint32_t a;
    asm("{ .reg .u64 t; cvta.to.shared.u64 t, %1; cvt.u32.u64 %0, t; }"
        : "=r"(a) : "l"(p));
    return a;
}
__device__ __forceinline__ void ldsm_x4(uint32_t& r0, uint32_t& r1,
                                        uint32_t& r2, uint32_t& r3, uint32_t addr)
{
    asm volatile("ldmatrix.sync.aligned.m8n8.x4.b16 {%0,%1,%2,%3}, [%4];"
                 : "=r"(r0), "=r"(r1), "=r"(r2), "=r"(r3) : "r"(addr));
}
__device__ __forceinline__ void mma_tf32(float* d, uint32_t a0, uint32_t a1,
                                         uint32_t a2, uint32_t a3,
                                         uint32_t b0, uint32_t b1)
{
    asm volatile(
        "mma.sync.aligned.m16n8k8.row.col.f32.tf32.tf32.f32 "
        "{%0,%1,%2,%3}, {%4,%5,%6,%7}, {%8,%9}, {%0,%1,%2,%3};"
        : "+f"(d[0]), "+f"(d[1]), "+f"(d[2]), "+f"(d[3])
        : "r"(a0), "r"(a1), "r"(a2), "r"(a3), "r"(b0), "r"(b1));
}

// ---- cp.async (16B, zero-fill when vbytes==0) ----
__device__ __forceinline__ void cpasync16(uint32_t dst, const void* src, int vbytes)
{
    asm volatile("cp.async.cg.shared.global [%0], [%1], 16, %2;"
                 :: "r"(dst), "l"(src), "r"(vbytes));
}
__device__ __forceinline__ void cp_commit()
{
    asm volatile("cp.async.commit_group;");
}
__device__ __forceinline__ void cp_wait1()
{
    asm volatile("cp.async.wait_group 1;");
}
__device__ __forceinline__ void cp_wait0()
{
    asm volatile("cp.async.wait_group 0;");
}

// single-counter grid barrier
__device__ __forceinline__ void gridbar()
{
    __syncthreads();
    if (threadIdx.x == 0) {
        __threadfence();
        volatile unsigned* vgen = &g_bargen;
        unsigned gen = *vgen;
        if (atomicAdd(&g_barcnt, 1u) == NBLK - 1) {
            g_barcnt = 0;
            __threadfence();
            atomicAdd(&g_bargen, 1u);
        } else {
            while (*vgen == gen) { __nanosleep(16); }
        }
        __threadfence();
    }
    __syncthreads();
}

// helper: scatter 4 prefetched float4s (rows kk=4*(lq+8p)) into tile[k][row]
__device__ __forceinline__ void stash4(float* buf, int lq, int row,
                                       float4 p0, float4 p1, float4 p2, float4 p3)
{
    buf[(4*lq+0)*36+row]=p0.x; buf[(4*lq+1)*36+row]=p0.y;
    buf[(4*lq+2)*36+row]=p0.z; buf[(4*lq+3)*36+row]=p0.w;
    buf[(4*(lq+8)+0)*36+row]=p1.x; buf[(4*(lq+8)+1)*36+row]=p1.y;
    buf[(4*(lq+8)+2)*36+row]=p1.z; buf[(4*(lq+8)+3)*36+row]=p1.w;
    buf[(4*(lq+16)+0)*36+row]=p2.x; buf[(4*(lq+16)+1)*36+row]=p2.y;
    buf[(4*(lq+16)+2)*36+row]=p2.z; buf[(4*(lq+16)+3)*36+row]=p2.w;
    buf[(4*(lq+24)+0)*36+row]=p3.x; buf[(4*(lq+24)+1)*36+row]=p3.y;
    buf[(4*(lq+24)+2)*36+row]=p3.z; buf[(4*(lq+24)+3)*36+row]=p3.w;
}

// ------------------------- embedding gather ---------------------------------
__global__ void k_gather(const int* __restrict__ seq, int seq_stride,
                         const float* __restrict__ embed, float* __restrict__ out)
{
    int row = blockIdx.x;
    int st  = row / NB;
    int b   = row % NB;
    int tok = seq[b*seq_stride + st];
    const float4* src = (const float4*)(embed + (size_t)tok*ND);
    float4*       dst = (float4*)(out + (size_t)row*ND);
    dst[threadIdx.x] = src[threadIdx.x];
}

// ------------------------- tf32 tensor-core GEMM (cp.async 3-stage) ----------
#define SGSTG 3840          // stage stride in u32 (As 2560 + Ws 1280)
#define SGSMEM (3*SGSTG*4)  // 46080 bytes
__global__ __launch_bounds__(256)
void k_sgemm(int M, int N, int K,
             const float* __restrict__ A, int lda,
             const float* __restrict__ W, int ldw,
             const float* __restrict__ bias1, const float* __restrict__ bias2,
             float* __restrict__ C, int ldc, int act, int out_map, int swap_grid)
{
    extern __shared__ __align__(16) uint32_t smem_u[];   // 3 stages
    float* Cs = (float*)smem_u;                          // [128][68] reuse at end

    int tid  = threadIdx.x;
    int lane = tid & 31;
    int warp = tid >> 5;
    int wm   = warp & 3;
    int wn   = warp >> 2;
    int m0, n0;
    if (swap_grid) { m0 = blockIdx.x*128; n0 = blockIdx.y*64; }
    else           { m0 = blockIdx.y*128; n0 = blockIdx.x*64; }

    int ra = tid >> 2;
    int kc = (tid & 3) * 4;

    bool a0v = (m0 + ra < M);
    bool a1v = (m0 + ra + 64 < M);
    bool wv_ = (n0 + ra < N) && (ra < 64);
    const float* Arow0 = A + (size_t)(a0v ? (m0+ra)    : 0)*lda + kc;
    const float* Arow1 = A + (size_t)(a1v ? (m0+ra+64) : 0)*lda + kc;
    const float* Wrow  = W + (size_t)(wv_ ? (n0+ra)    : 0)*ldw + kc;
    int az0 = a0v ? 16 : 0, az1 = a1v ? 16 : 0, wz = wv_ ? 16 : 0;

    uint32_t sbase[3];
    #pragma unroll
    for (int s = 0; s < 3; s++) sbase[s] = cvta_s(smem_u + s*SGSTG);
    uint32_t a0off = (uint32_t)(ra*20 + kc)*4;
    uint32_t a1off = (uint32_t)((ra+64)*20 + kc)*4;
    uint32_t woff  = (uint32_t)(2560 + ra*20 + kc)*4;

    uint32_t ws_row = (uint32_t)(wn*32 + (lane >> 2))*20 + (lane & 3);
    float acc[2][4][4] = {};
    int nit = K >> 4;

    #pragma unroll
    for (int s = 0; s < 2; s++) {
        int k0 = s << 4;
        uint32_t b = sbase[s];
        cpasync16(b + a0off, Arow0 + k0, az0);
        cpasync16(b + a1off, Arow1 + k0, az1);
        if (ra < 64) cpasync16(b + woff, Wrow + k0, wz);
        cp_commit();
    }

    int sidx = 0;
    for (int it = 0; it < nit; it++) {
        cp_wait1();
        __syncthreads();

        int snx = sidx + 2; if (snx >= 3) snx -= 3;
        if (it + 2 < nit) {
            int k0 = (it + 2) << 4;
            uint32_t b = sbase[snx];
            cpasync16(b + a0off, Arow0 + k0, az0);
            cpasync16(b + a1off, Arow1 + k0, az1);
            if (ra < 64) cpasync16(b + woff, Wrow + k0, wz);
        }
        cp_commit();

        uint32_t as_base = sbase[sidx];
        const float* WsF = (const float*)(smem_u + sidx*SGSTG + 2560);
        #pragma unroll
        for (int ks = 0; ks < 16; ks += 8) {
            uint32_t afr[2][4];
            #pragma unroll
            for (int mi = 0; mi < 2; mi++) {
                uint32_t row = (uint32_t)(wm*32 + mi*16 + (lane & 15));
                uint32_t kof = (uint32_t)(ks + ((lane >> 4) << 2));
                uint32_t addr = as_base + (row*20 + kof)*4;
                ldsm_x4(afr[mi][0], afr[mi][1], afr[mi][2], afr[mi][3], addr);
                #pragma unroll
                for (int q = 0; q < 4; q++)
                    afr[mi][q] = f2tf(__uint_as_float(afr[mi][q]));
            }
            uint32_t bfr[4][2];
            #pragma unroll
            for (int j = 0; j < 4; j++) {
                bfr[j][0] = f2tf(WsF[ws_row + (uint32_t)(j*8)*20 + ks]);
                bfr[j][1] = f2tf(WsF[ws_row + (uint32_t)(j*8)*20 + ks + 4]);
            }
            #pragma unroll
            for (int mi = 0; mi < 2; mi++)
                #pragma unroll
                for (int j = 0; j < 4; j++)
                    mma_tf32(acc[mi][j], afr[mi][0], afr[mi][1], afr[mi][2],
                             afr[mi][3], bfr[j][0], bfr[j][1]);
        }
        sidx++; if (sidx >= 3) sidx = 0;
    }
    __syncthreads();

    #pragma unroll
    for (int mi = 0; mi < 2; mi++) {
        int ml0 = wm*32 + mi*16 + (lane >> 2);
        #pragma unroll
        for (int j = 0; j < 4; j++) {
            int nl = wn*32 + j*8 + (lane & 3)*2;
            float b0v = 0.f, b1v = 0.f;
            if (n0 + nl < N) {
                b0v = bias1[n0+nl];
                if (bias2) b0v += bias2[n0+nl];
            }
            if (n0 + nl + 1 < N) {
                b1v = bias1[n0+nl+1];
                if (bias2) b1v += bias2[n0+nl+1];
            }
            float v0 = acc[mi][j][0] + b0v;
            float v1 = acc[mi][j][1] + b1v;
            float v2 = acc[mi][j][2] + b0v;
            float v3 = acc[mi][j][3] + b1v;
            if (act == 1) { v0=tanhf(v0); v1=tanhf(v1); v2=tanhf(v2); v3=tanhf(v3); }
            else if (act == 2) { v0=fmaxf(v0,0.f); v1=fmaxf(v1,0.f);
                                 v2=fmaxf(v2,0.f); v3=fmaxf(v3,0.f); }
            Cs[ml0*68 + nl]       = v0;
            Cs[ml0*68 + nl + 1]   = v1;
            Cs[(ml0+8)*68 + nl]   = v2;
            Cs[(ml0+8)*68 + nl+1] = v3;
        }
    }
    __syncthreads();

    if (out_map == 2) {
        for (int c = tid; c < 2048; c += 256) {
            int qb = (c & 7) * 4;
            int nl = (c >> 3) & 63;
            int sh = c >> 9;
            int mgrp = m0 + sh*32;
            if (mgrp >= M) continue;
            float4 v4 = make_float4(Cs[(sh*32+qb+0)*68 + nl],
                                    Cs[(sh*32+qb+1)*68 + nl],
                                    Cs[(sh*32+qb+2)*68 + nl],
                                    Cs[(sh*32+qb+3)*68 + nl]);
            *(float4*)&C[((size_t)(mgrp >> 5)*NG + n0 + nl)*32 + qb] = v4;
        }
        return;
    }

    for (int c = tid; c < 2048; c += 256) {
        int ml = c >> 4;
        int nl = (c & 15) * 4;
        int m = m0 + ml;
        if (m >= M) continue;
        size_t row = (out_map == 1) ? (size_t)((m & 31)*NT + (m >> 5)) : (size_t)m;
        int n = n0 + nl;
        if (n + 3 < N) {
            *(float4*)&C[row*ldc + n] = *(const float4*)&Cs[ml*68 + nl];
        } else {
            for (int j = 0; j < 4; j++)
                if (n + j < N) C[row*ldc + n + j] = Cs[ml*68 + nl + j];
        }
    }
}

// ------------------------- tensor-core persistent encoder -------------------
// 2-phase step pipeline + staged coalesced stores for enc_out/hout.
#define HPITCH 1028
__global__ void __launch_bounds__(256, 1)
k_enc_persist(const float* __restrict__ Whh, const int* __restrict__ lengths)
{
    extern __shared__ float sm[];
    float* sH = sm;                          // [32][HPITCH] tf32 bits
    float* sZ = sm + 32*HPITCH;              // [8][32][33]

    int tid  = threadIdx.x;
    int lane = tid & 31;
    int warp = tid >> 5;
    int u0   = blockIdx.x * 8;

    // ---- load Whh slice as B fragments, 2-phase k mapping ----
    uint32_t wf[4][16][2];
    {
        int nr  = lane >> 2;
        int kq  = lane & 3;
        #pragma unroll
        for (int nt = 0; nt < 4; nt++) {
            int n = nt*8 + nr;
            const float* wrow = Whh + (size_t)((n >> 3)*NH + u0 + (n & 7))*NH + kq;
            #pragma unroll
            for (int kt = 0; kt < 16; kt++) {
                int koff = (kt < 8) ? (warp*64 + kt*8)
                                    : (512 + warp*64 + (kt-8)*8);
                wf[nt][kt][0] = f2tf(__ldg(&wrow[koff]));
                wf[nt][kt][1] = f2tf(__ldg(&wrow[koff + 4]));
            }
        }
    }

    int cb = tid & 31;
    int cu = tid >> 5;
    int mylen = lengths[cb];
    int len_hi = 0;
    #pragma unroll
    for (int i = 16; i < 32; i++) len_hi = max(len_hi, lengths[i]);
    float creg = 0.0f, hreg = 0.0f;

    g_hbuf[cb*NH + u0 + cu] = 0.0f;          // tf32(0) == 0 bits

    int lr      = tid >> 3;
    int lane8   = tid & 7;
    int loadlen = lengths[lr];               // load row lr while s <= loadlen
    uint32_t sh_base = cvta_s(sH);
    uint32_t sh_row  = sh_base + (uint32_t)(lr*HPITCH)*4;

    // staging areas (carved from sZ; used after cell has consumed sZ)
    float* sE = sZ;            // [32][9] enc_out values
    float* sO = sZ + 32*9;     // [32][9] hout tf32 bits

    gridbar();

    for (int s = 0; s < NS; s++) {
        const float* hin  = g_hbuf + (s & 1)*(NB*NH);
        float*       hout = g_hbuf + ((s & 1) ^ 1)*(NB*NH);
        bool act_hi = (s < len_hi);
        bool doload = (s <= loadlen);

        // issue half0 (k<512) and half1 (k>=512) as two cp.async groups
        {
            const float* hr = hin + lr*NH;
            if (doload) {
                #pragma unroll
                for (int kk = 0; kk < 16; kk++) {
                    int u4 = lane8 + 8*kk;
                    cpasync16(sh_row + u4*16, hr + u4*4, 16);
                }
            }
            cp_commit();
            if (doload) {
                #pragma unroll
                for (int kk = 16; kk < 32; kk++) {
                    int u4 = lane8 + 8*kk;
                    cpasync16(sh_row + u4*16, hr + u4*4, 16);
                }
            }
            cp_commit();
        }

        const float* xp = g_xproj + ((size_t)s*NG + u0 + cu)*32 + cb;
        float xg0 = __ldg(&xp[0]);
        float xg1 = __ldg(&xp[(size_t)NH*32]);
        float xg2 = __ldg(&xp[(size_t)2*NH*32]);
        float xg3 = __ldg(&xp[(size_t)3*NH*32]);

        cp_wait1();          // half0 landed
        __syncthreads();

        float acc[2][4][4] = {};
        // ---- phase 0: k in [warp*64, warp*64+64) ----
        #pragma unroll
        for (int kt = 0; kt < 8; kt++) {
            int kof = warp*64 + kt*8 + ((lane >> 4) << 2);
            {
                uint32_t a0, a1, a2, a3;
                uint32_t addr = sh_base + (uint32_t)(((lane & 15))*HPITCH + kof)*4;
                ldsm_x4(a0, a1, a2, a3, addr);
                #pragma unroll
                for (int nt = 0; nt < 4; nt++)
                    mma_tf32(acc[0][nt], a0, a1, a2, a3,
                             wf[nt][kt][0], wf[nt][kt][1]);
            }
            if (act_hi) {
                uint32_t a0, a1, a2, a3;
                uint32_t addr = sh_base + (uint32_t)((16 + (lane & 15))*HPITCH + kof)*4;
                ldsm_x4(a0, a1, a2, a3, addr);
                #pragma unroll
                for (int nt = 0; nt < 4; nt++)
                    mma_tf32(acc[1][nt], a0, a1, a2, a3,
                             wf[nt][kt][0], wf[nt][kt][1]);
            }
        }

        cp_wait0();          // half1 landed
        __syncthreads();

        // ---- phase 1: k in [512+warp*64, +64) ----
        #pragma unroll
        for (int kt = 8; kt < 16; kt++) {
            int kof = 512 + warp*64 + (kt-8)*8 + ((lane >> 4) << 2);
            {
                uint32_t a0, a1, a2, a3;
                uint32_t addr = sh_base + (uint32_t)(((lane & 15))*HPITCH + kof)*4;
                ldsm_x4(a0, a1, a2, a3, addr);
                #pragma unroll
                for (int nt = 0; nt < 4; nt++)
                    mma_tf32(acc[0][nt], a0, a1, a2, a3,
                             wf[nt][kt][0], wf[nt][kt][1]);
            }
            if (act_hi) {
                uint32_t a0, a1, a2, a3;
                uint32_t addr = sh_base + (uint32_t)((16 + (lane & 15))*HPITCH + kof)*4;
                ldsm_x4(a0, a1, a2, a3, addr);
                #pragma unroll
                for (int nt = 0; nt < 4; nt++)
                    mma_tf32(acc[1][nt], a0, a1, a2, a3,
                             wf[nt][kt][0], wf[nt][kt][1]);
            }
        }

        {
            float* zw = sZ + warp*(32*33);
            int rr = lane >> 2;
            int cc = (lane & 3)*2;
            #pragma unroll
            for (int mi = 0; mi < 2; mi++) {
                if (mi == 1 && !act_hi) break;
                #pragma unroll
                for (int nt = 0; nt < 4; nt++) {
                    int col = nt*8 + cc;
                    int row = mi*16 + rr;
                    zw[col*33 + row]       = acc[mi][nt][0];
                    zw[(col+1)*33 + row]   = acc[mi][nt][1];
                    zw[col*33 + row + 8]   = acc[mi][nt][2];
                    zw[(col+1)*33 + row+8] = acc[mi][nt][3];
                }
            }
        }
        __syncthreads();

        float zg4[4] = {xg0, xg1, xg2, xg3};
        #pragma unroll
        for (int g = 0; g < 4; g++) {
            int col = g*8 + cu;
            #pragma unroll
            for (int w = 0; w < 8; w++)
                zg4[g] += sZ[w*(32*33) + col*33 + cb];
        }
        float cn = sigmf_(zg4[1])*creg + sigmf_(zg4[0])*tanhf(zg4[2]);
        float hn = sigmf_(zg4[3])*tanhf(cn);
        bool msk = (s < mylen);
        creg = msk ? cn : creg;
        hreg = msk ? hn : hreg;

        // ---- staged coalesced stores ----
        __syncthreads();     // everyone done reading sZ
        sE[cb*9 + cu] = msk ? hreg : 0.0f;
        sO[cb*9 + cu] = __uint_as_float(f2tf(hreg));
        __syncthreads();
        if (tid < 128) {
            int b = tid >> 2, e = (tid & 3)*2;
            float2 v = make_float2(sE[b*9 + e], sE[b*9 + e + 1]);
            *(float2*)&g_enc_out[((size_t)(s*NB + b))*NH + u0 + e] = v;
        } else {
            int j = tid - 128;
            int b = j >> 2, e = (j & 3)*2;
            float2 v = make_float2(sO[b*9 + e], sO[b*9 + e + 1]);
            *(float2*)&hout[b*NH + u0 + e] = v;
        }

        gridbar();
    }

    g_h[cb*NH + u0 + cu] = hreg;
    g_c[cb*NH + u0 + cu] = creg;
}

// ------------------------- persistent decoder helpers -----------------------
__device__ __forceinline__ void dec_feat(int tt, const float* __restrict__ hsrc,
    const float* __restrict__ out_W, const float* __restrict__ out_b,
    float* sH, float* sZ, int fn0)
{
    int tid = threadIdx.x;
    int r   = tid >> 6;
    int fks = (tid >> 5) & 1;
    int fb  = tid & 31;
    int lb  = tid >> 3;
    int lq  = tid & 7;
    const float* wrow = out_W + (size_t)(fn0 + r)*(2*NH);
    float fa = 0.f;

    float4 p0, p1, p2, p3;
    {
        const float* hr = hsrc + lb*NH;
        p0 = __ldcg((const float4*)&hr[4*lq]);
        p1 = __ldcg((const float4*)&hr[4*(lq+8)]);
        p2 = __ldcg((const float4*)&hr[4*(lq+16)]);
        p3 = __ldcg((const float4*)&hr[4*(lq+24)]);
        stash4(sH, lq, lb, p0, p1, p2, p3);
    }
    __syncthreads();

    for (int ch = 0; ch < 16; ch++) {
        float* cur = sH + (ch & 1)*(128*36);
        if (ch < 15) {
            int cn_ = ch + 1;
            const float* src = (cn_ < 8) ? hsrc : g_ctx;
            const float* hr = src + lb*NH + (cn_ & 7)*128;
            p0 = __ldcg((const float4*)&hr[4*lq]);
            p1 = __ldcg((const float4*)&hr[4*(lq+8)]);
            p2 = __ldcg((const float4*)&hr[4*(lq+16)]);
            p3 = __ldcg((const float4*)&hr[4*(lq+24)]);
        }
        const float* wc = wrow + ch*128 + fks*64;
        const float* hc = cur + fks*64*36 + fb;
        #pragma unroll 16
        for (int k = 0; k < 64; k++)
            fa += __ldg(&wc[k]) * hc[k*36];
        if (ch < 15)
            stash4(sH + ((ch & 1) ^ 1)*(128*36), lq, lb, p0, p1, p2, p3);
        __syncthreads();
    }
    sZ[(r*2 + fks)*33 + fb] = fa;
    __syncthreads();
    if (tid < 128) {
        int rr = tid >> 5, bb = tid & 31;
        float v = sZ[(rr*2)*33 + bb] + sZ[(rr*2+1)*33 + bb] + __ldg(&out_b[fn0 + rr]);
        g_feat[((size_t)(tt*NB + bb))*ND + fn0 + rr] = v;
    }
    __syncthreads();
}

__device__ __forceinline__ void dec_attn(int b, int mylen,
    const float* __restrict__ hcur,
    const float* __restrict__ ak_W, const float* __restrict__ ak_b,
    float* sW)
{
    int tid = threadIdx.x;
    float* sh_ = sW;
    float* sak = sW + 1024;
    float* se  = sW + 1152;
    float* sr  = sW + 1280;

    for (int i = tid; i < NH; i += 256) sh_[i] = __ldcg(&hcur[b*NH + i]);
    __syncthreads();

    if (tid < NK) {
        const float* wr = ak_W + (size_t)tid*NH;
        float acc0 = 0.f, acc1 = 0.f;
        for (int k = 0; k < NH; k += 8) {
            float4 w0 = *(const float4*)&wr[k];
            float4 w1 = *(const float4*)&wr[k+4];
            float4 h0 = *(const float4*)&sh_[k];
            float4 h1 = *(const float4*)&sh_[k+4];
            acc0 += w0.x*h0.x + w0.y*h0.y + w0.z*h0.z + w0.w*h0.w;
            acc1 += w1.x*h1.x + w1.y*h1.y + w1.z*h1.z + w1.w*h1.w;
        }
        sak[tid] = tanhf(acc0 + acc1 + ak_b[tid]);
    }
    __syncthreads();

    if (tid < NS) {
        const float* qr = g_qkey + ((size_t)(tid*NB + b))*NK;
        float acc = 0.f;
        for (int k = 0; k < NK; k++) acc += qr[k]*sak[k];
        se[tid] = (tid < mylen) ? acc : -INFINITY;
    }
    __syncthreads();

    sr[tid] = (tid < NS) ? se[tid] : -INFINITY;
    __syncthreads();
    for (int off = 128; off >= 1; off >>= 1) {
        if (tid < off) sr[tid] = fmaxf(sr[tid], sr[tid+off]);
        __syncthreads();
    }
    float mx = sr[0];
    __syncthreads();

    float ex = (tid < NS) ? expf(se[tid] - mx) : 0.0f;
    sr[tid] = ex;
    __syncthreads();
    for (int off = 128; off >= 1; off >>= 1) {
        if (tid < off) sr[tid] += sr[tid+off];
        __syncthreads();
    }
    float inv = 1.0f / sr[0];
    __syncthreads();
    if (tid < NS) g_attw[b*NS + tid] = ex * inv;
    __syncthreads();
}

// ------------------------- persistent decoder (tf32 mma z-GEMM) -------------
#define DPITCH 132
#define DBUF (32*DPITCH)
__global__ void __launch_bounds__(256, 1)
k_dec_persist(const float* __restrict__ dec_Wih, const float* __restrict__ dec_Whh,
              const float* __restrict__ ak_W,   const float* __restrict__ ak_b,
              const float* __restrict__ out_W,  const float* __restrict__ out_b,
              const int* __restrict__ lengths)
{
    extern __shared__ float sm[];
    float* sA  = sm;                    // 2 x DBUF
    float* sWt = sm + 2*DBUF;           // 2 x DBUF
    float* sZd = sm + 4*DBUF;           // [8][32][33] = 8448

    int tid  = threadIdx.x;
    int lane = tid & 31;
    int warp = tid >> 5;
    int blk  = blockIdx.x;
    int u0   = blk * 8;
    int fn0  = blk * 4;

    int cb = tid & 31, cu = tid >> 5;
    float creg = g_c[cb*NH + u0 + cu];

    int lr  = tid >> 3;
    int lq  = tid & 7;
    int wn_ = (lr >> 3)*NH + u0 + (lr & 7);
    const float* WhhRow = dec_Whh + (size_t)wn_*NH;
    const float* WihRow = dec_Wih + (size_t)wn_*(ND+NH) + ND;

    uint32_t saA0 = cvta_s(sA);
    uint32_t saA1 = cvta_s(sA + DBUF);

    int mylen = (blk < 32) ? lengths[blk] : 0;

    for (int t = 0; t < NT; t++) {
        const float* hcur = (t == 0) ? g_h : (g_hbuf + ((t-1) & 1)*(NB*NH));
        float*       hnew = g_hbuf + (t & 1)*(NB*NH);

        if (t > 0)
            dec_feat(t-1, hcur, out_W, out_b, sm, sm + 4*DBUF, fn0);
        if (blk < 32)
            dec_attn(blk, mylen, hcur, ak_W, ak_b, sm);
        gridbar();

        // ---- context ----
        {
            int b  = blk & 31;
            int hq = blk >> 5;
            if (tid < NS) sZd[tid] = __ldcg(&g_attw[b*NS + tid]);
            __syncthreads();
            int hh = hq*256 + tid;
            float a0 = 0.f, a1 = 0.f, a2 = 0.f, a3 = 0.f;
            #pragma unroll 4
            for (int s = 0; s < NS; s += 4) {
                a0 += sZd[s+0]*__ldg(&g_qval[((size_t)((s+0)*NB + b))*NH + hh]);
                a1 += sZd[s+1]*__ldg(&g_qval[((size_t)((s+1)*NB + b))*NH + hh]);
                a2 += sZd[s+2]*__ldg(&g_qval[((size_t)((s+2)*NB + b))*NH + hh]);
                a3 += sZd[s+3]*__ldg(&g_qval[((size_t)((s+3)*NB + b))*NH + hh]);
            }
            g_ctx[b*NH + hh] = (a0 + a1) + (a2 + a3);
            __syncthreads();
        }
        gridbar();

        const float* xp = g_dxe + ((size_t)t*NG + u0 + cu)*32 + cb;
        float xg0 = __ldg(&xp[0]);
        float xg1 = __ldg(&xp[(size_t)NH*32]);
        float xg2 = __ldg(&xp[(size_t)2*NH*32]);
        float xg3 = __ldg(&xp[(size_t)3*NH*32]);

        // ---- z GEMM via tf32 mma, 16 chunks of 128 k, double-buffered ----
        float acc[2][4][4] = {};
        float4 pA[4], pW[4];
        {
            const float* ar = hcur + lr*NH;
            #pragma unroll
            for (int p = 0; p < 4; p++) {
                pA[p] = __ldcg((const float4*)&ar[4*(lq + 8*p)]);
                pW[p] = __ldg((const float4*)&WhhRow[4*(lq + 8*p)]);
            }
            #pragma unroll
            for (int p = 0; p < 4; p++) {
                *(float4*)&sA [lr*DPITCH + 4*(lq + 8*p)] = pA[p];
                *(float4*)&sWt[lr*DPITCH + 4*(lq + 8*p)] = pW[p];
            }
        }
        __syncthreads();

        for (int ci = 0; ci < 16; ci++) {
            int cur = ci & 1;
            if (ci < 15) {
                int cn_ = ci + 1;
                int kc  = (cn_ & 7) * 128;
                const float* ar = ((cn_ < 8) ? hcur : g_ctx) + lr*NH + kc;
                const float* wr = ((cn_ < 8) ? WhhRow : WihRow) + kc;
                #pragma unroll
                for (int p = 0; p < 4; p++) {
                    pA[p] = __ldcg((const float4*)&ar[4*(lq + 8*p)]);
                    pW[p] = __ldg((const float4*)&wr[4*(lq + 8*p)]);
                }
            }

            uint32_t saA = cur ? saA1 : saA0;
            const float* Wc = sWt + cur*DBUF;
            #pragma unroll
            for (int k8 = 0; k8 < 2; k8++) {
                int kw = warp*16 + k8*8;
                uint32_t afr[2][4];
                #pragma unroll
                for (int mi = 0; mi < 2; mi++) {
                    uint32_t addr = saA +
                        (uint32_t)((mi*16 + (lane & 15))*DPITCH + kw + ((lane >> 4) << 2))*4;
                    ldsm_x4(afr[mi][0], afr[mi][1], afr[mi][2], afr[mi][3], addr);
                    #pragma unroll
                    for (int q = 0; q < 4; q++)
                        afr[mi][q] = f2tf(__uint_as_float(afr[mi][q]));
                }
                uint32_t bfr[4][2];
                #pragma unroll
                for (int nt = 0; nt < 4; nt++) {
                    const float* wp = Wc + (nt*8 + (lane >> 2))*DPITCH + kw + (lane & 3);
                    bfr[nt][0] = f2tf(wp[0]);
                    bfr[nt][1] = f2tf(wp[4]);
                }
                #pragma unroll
                for (int mi = 0; mi < 2; mi++)
                    #pragma unroll
                    for (int nt = 0; nt < 4; nt++)
                        mma_tf32(acc[mi][nt], afr[mi][0], afr[mi][1], afr[mi][2],
                                 afr[mi][3], bfr[nt][0], bfr[nt][1]);
            }

            if (ci < 15) {
                float* dA = sA  + (cur ^ 1)*DBUF;
                float* dW = sWt + (cur ^ 1)*DBUF;
                #pragma unroll
                for (int p = 0; p < 4; p++) {
                    *(float4*)&dA[lr*DPITCH + 4*(lq + 8*p)] = pA[p];
                    *(float4*)&dW[lr*DPITCH + 4*(lq + 8*p)] = pW[p];
                }
            }
            __syncthreads();
        }

        {
            float* zw = sZd + warp*(32*33);
            int rr = lane >> 2;
            int cc = (lane & 3)*2;
            #pragma unroll
            for (int mi = 0; mi < 2; mi++)
                #pragma unroll
                for (int nt = 0; nt < 4; nt++) {
                    int col = nt*8 + cc;
                    int row = mi*16 + rr;
                    zw[col*33 + row]       = acc[mi][nt][0];
                    zw[(col+1)*33 + row]   = acc[mi][nt][1];
                    zw[col*33 + row + 8]   = acc[mi][nt][2];
                    zw[(col+1)*33 + row+8] = acc[mi][nt][3];
                }
        }
        __syncthreads();

        {
            float zg4[4] = {xg0, xg1, xg2, xg3};
            #pragma unroll
            for (int g = 0; g < 4; g++) {
                int col = g*8 + cu;
                #pragma unroll
                for (int w = 0; w < 8; w++)
                    zg4[g] += sZd[w*(32*33) + col*33 + cb];
            }
            float cn = sigmf_(zg4[1])*creg + sigmf_(zg4[0])*tanhf(zg4[2]);
            float hn = sigmf_(zg4[3])*tanhf(cn);
            creg = cn;
            hnew[cb*NH + u0 + cu] = hn;
        }
        __syncthreads();
        gridbar();
    }

    {
        const float* hlast = g_hbuf + ((NT-1) & 1)*(NB*NH);
        dec_feat(NT-1, hlast, out_W, out_b, sm, sm + 4*DBUF, fn0);
    }
}

// =============================================================================
extern "C" void kernel_launch(void* const* d_in, const int* in_sizes, int n_in,
                              void* d_out, int out_size)
{
    const float* embed    = (const float*)d_in[0];
    const float* enc_Wih  = (const float*)d_in[1];
    const float* enc_Whh  = (const float*)d_in[2];
    const float* enc_bih  = (const float*)d_in[3];
    const float* enc_bhh  = (const float*)d_in[4];
    const float* dec_Wih  = (const float*)d_in[5];
    const float* dec_Whh  = (const float*)d_in[6];
    const float* dec_bih  = (const float*)d_in[7];
    const float* dec_bhh  = (const float*)d_in[8];
    const float* qk_W     = (const float*)d_in[9];
    const float* qk_b     = (const float*)d_in[10];
    const float* qv_W     = (const float*)d_in[11];
    const float* qv_b     = (const float*)d_in[12];
    const float* ak_W     = (const float*)d_in[13];
    const float* ak_b     = (const float*)d_in[14];
    const float* out_W    = (const float*)d_in[15];
    const float* out_b    = (const float*)d_in[16];
    const float* wd_b     = (const float*)d_in[17];
    const float* hfc1_W   = (const float*)d_in[18];
    const float* hfc1_b   = (const float*)d_in[19];
    const float* hfc2_W   = (const float*)d_in[20];
    const float* hfc2_b   = (const float*)d_in[21];
    const float* cfc1_W   = (const float*)d_in[22];
    const float* cfc1_b   = (const float*)d_in[23];
    const float* cfc2_W   = (const float*)d_in[24];
    const float* cfc2_b   = (const float*)d_in[25];
    const int*   src_seqs = (const int*)d_in[26];
    const int*   src_len  = (const int*)d_in[27];
    const int*   trg_seqs = (const int*)d_in[28];
    float* out = (float*)d_out;

    float *d_src_embed, *d_ans_embed, *d_xproj, *d_dxe, *d_h, *d_c;
    float *d_enc_out, *d_qkey, *d_qval, *d_tmp, *d_feat;
    cudaGetSymbolAddress((void**)&d_src_embed, g_src_embed);
    cudaGetSymbolAddress((void**)&d_ans_embed, g_ans_embed);
    cudaGetSymbolAddress((void**)&d_xproj,     g_xproj);
    cudaGetSymbolAddress((void**)&d_dxe,       g_dxe);
    cudaGetSymbolAddress((void**)&d_h,         g_h);
    cudaGetSymbolAddress((void**)&d_c,         g_c);
    cudaGetSymbolAddress((void**)&d_enc_out,   g_enc_out);
    cudaGetSymbolAddress((void**)&d_qkey,      g_qkey);
    cudaGetSymbolAddress((void**)&d_qval,      g_qval);
    cudaGetSymbolAddress((void**)&d_tmp,       g_tmp);
    cudaGetSymbolAddress((void**)&d_feat,      g_feat);

    cudaFuncSetAttribute(k_sgemm,
                         cudaFuncAttributeMaxDynamicSharedMemorySize, SGSMEM);
    cudaFuncSetAttribute(k_sgemm,
                         cudaFuncAttributePreferredSharedMemoryCarveout, 100);

    // ---- precompute ----
    k_gather<<<NS*NB, 128>>>(src_seqs, NS, embed, d_src_embed);
    k_gather<<<NT*NB, 128>>>(trg_seqs, 20, embed, d_ans_embed);

    k_sgemm<<<dim3(NG/64, (NS*NB)/128), 256, SGSMEM>>>(NS*NB, NG, ND,
        d_src_embed, ND, enc_Wih, ND, enc_bih, enc_bhh, d_xproj, NG, 0, 2, 0);
    k_sgemm<<<dim3(NG/64, (NT*NB + 127)/128), 256, SGSMEM>>>(NT*NB, NG, ND,
        d_ans_embed, ND, dec_Wih, ND + NH, dec_bih, dec_bhh, d_dxe, NG, 0, 2, 0);

    // ---- encoder recurrence ----
    const int enc_smem = (32*HPITCH + 8*32*33) * (int)sizeof(float);
    cudaFuncSetAttribute(k_enc_persist,
                         cudaFuncAttributeMaxDynamicSharedMemorySize, enc_smem);
    k_enc_persist<<<NBLK, 256, enc_smem>>>(enc_Whh, src_len);

    // ---- bridge MLPs ----
    k_sgemm<<<dim3(2048/64, 1), 256, SGSMEM>>>(NB, 2048, NH, d_h, NH, hfc1_W, NH,
                                       hfc1_b, nullptr, d_tmp, 2048, 2, 0, 0);
    k_sgemm<<<dim3(NH/64, 1), 256, SGSMEM>>>(NB, NH, 2048, d_tmp, 2048, hfc2_W, 2048,
                                     hfc2_b, nullptr, d_h, NH, 0, 0, 0);
    k_sgemm<<<dim3(2048/64, 1), 256, SGSMEM>>>(NB, 2048, NH, d_c, NH, cfc1_W, NH,
                                       cfc1_b, nullptr, d_tmp, 2048, 2, 0, 0);
    k_sgemm<<<dim3(NH/64, 1), 256, SGSMEM>>>(NB, NH, 2048, d_tmp, 2048, cfc2_W, 2048,
                                     cfc2_b, nullptr, d_c, NH, 0, 0, 0);

    // ---- attention precompute ----
    k_sgemm<<<dim3((NK + 63)/64, (NS*NB)/128), 256, SGSMEM>>>(NS*NB, NK, NH,
        d_enc_out, NH, qk_W, NH, qk_b, nullptr, d_qkey, NK, 1, 0, 0);
    k_sgemm<<<dim3(NH/64, (NS*NB)/128), 256, SGSMEM>>>(NS*NB, NH, NH,
        d_enc_out, NH, qv_W, NH, qv_b, nullptr, d_qval, NH, 0, 0, 0);

    // ---- decoder recurrence ----
    const int dec_smem = (4*DBUF + 8*32*33) * (int)sizeof(float);
    cudaFuncSetAttribute(k_dec_persist,
                         cudaFuncAttributeMaxDynamicSharedMemorySize, dec_smem);
    k_dec_persist<<<NBLK, 256, dec_smem>>>(dec_Wih, dec_Whh, ak_W, ak_b,
                                           out_W, out_b, src_len);

    // ---- final logits ----
    k_sgemm<<<dim3((NT*NB + 127)/128, NV/64), 256, SGSMEM>>>(NT*NB, NV, ND,
        d_feat, ND, embed, ND, wd_b, nullptr, out, NV, 0, 1, 1);

    (void)in_sizes; (void)n_in; (void)out_size;
}